// round 1
// baseline (speedup 1.0000x reference)
#include <cuda_runtime.h>
#include <cstdint>

#define BATCH 4
#define CH 256
#define HH 128
#define WW 128
#define POOLW 4
#define HP 32
#define WP 32
#define LL 1024
#define NHEAD 8
#define DH 32
#define C2 512
#define NPIX (BATCH*HH*WW)      /* 65536 */
#define NROWS (2*NPIX)          /* 131072 */
#define EPSF 1e-5f
#define TSCALE 0.17677669529663687f
#define NEGINF (-3.402823466e38f)

// ---------------- scratch (device globals; no allocation) ----------------
__device__ float g_p[2][BATCH*CH*LL];          // pooled + LN'd features, [n][c][sp]
__device__ float g_q[2][(size_t)BATCH*LL*CH];  // qk-branch heads: [0]=query(x1), [1]=key(x2)
__device__ float g_v[2][(size_t)BATCH*LL*CH];  // v-branch heads:  [0]=v1h,       [1]=v2h
__device__ float g_qk[(size_t)BATCH*NHEAD*LL*LL];  // t*QK, later overwritten by S2
__device__ float g_rmax[BATCH*NHEAD*LL];
__device__ float g_rinv[BATCH*NHEAD*LL];
__device__ float g_m[2][(size_t)BATCH*LL*CH];   // m1, m2  [n][l][c]
__device__ float g_mm[2][(size_t)BATCH*LL*CH];  // after merge linear
__device__ float g_u[(size_t)NROWS*C2];         // concat MLP input
__device__ float g_z1[(size_t)NROWS*C2];        // after relu(W1)
__device__ float g_z2[(size_t)NROWS*CH];        // after W2
__device__ float g_mu[NROWS];
__device__ float g_rstd[NROWS];

// ---------------- 1. maxpool 4x4 ----------------
__global__ void pool_kernel(const float* __restrict__ x, int o) {
    int nc = blockIdx.x;                // n*CH + c
    int t = threadIdx.x;                // 0..1023 = i*32+j
    int i = t >> 5, j = t & 31;
    const float* xp = x + (size_t)nc*HH*WW + (size_t)(i*POOLW)*WW + j*POOLW;
    float m = NEGINF;
    #pragma unroll
    for (int a = 0; a < POOLW; a++)
        #pragma unroll
        for (int b = 0; b < POOLW; b++)
            m = fmaxf(m, xp[a*WW + b]);
    g_p[o][(size_t)nc*LL + t] = m;
}

// ---------------- 2. LayerNorm over channels (in-place) ----------------
__global__ void lnc_kernel(int o, const float* __restrict__ g, const float* __restrict__ b) {
    int sp = blockIdx.x % LL;
    int n  = blockIdx.x / LL;
    int c  = threadIdx.x;               // 0..255
    size_t idx = ((size_t)(n*CH + c))*LL + sp;
    float v = g_p[o][idx];
    __shared__ float ssum[256], ssq[256];
    ssum[c] = v; ssq[c] = v*v;
    __syncthreads();
    for (int off = 128; off; off >>= 1) {
        if (c < off) { ssum[c] += ssum[c+off]; ssq[c] += ssq[c+off]; }
        __syncthreads();
    }
    float mu  = ssum[0] * (1.0f/CH);
    float var = ssq[0] * (1.0f/CH) - mu*mu;
    float r   = rsqrtf(var + EPSF);
    g_p[o][idx] = g[c]*(v-mu)*r + b[c];
}

// ---------------- 3. depthwise conv3x3 + BN -> heads layout [n][l][c] ----------------
__global__ void dwbn_kernel(int o, int branch,
                            const float* __restrict__ w, const float* __restrict__ g,
                            const float* __restrict__ b, const float* __restrict__ rm,
                            const float* __restrict__ rv) {
    int nc = blockIdx.x;
    int c = nc % CH, n = nc / CH;
    int t = threadIdx.x;
    int i = t >> 5, j = t & 31;
    __shared__ float sp[LL];
    __shared__ float wsh[9];
    sp[t] = g_p[o][(size_t)nc*LL + t];
    if (t < 9) wsh[t] = w[c*9 + t];
    __syncthreads();
    float acc = 0.f;
    #pragma unroll
    for (int di = 0; di < 3; di++) {
        int ii = i + di - 1;
        if (ii < 0 || ii >= HP) continue;
        #pragma unroll
        for (int dj = 0; dj < 3; dj++) {
            int jj = j + dj - 1;
            if (jj < 0 || jj >= WP) continue;
            acc += wsh[di*3+dj] * sp[ii*WP + jj];
        }
    }
    float sc = g[c] * rsqrtf(rv[c] + EPSF);
    float val = sc*(acc - rm[c]) + b[c];
    float* out = branch ? g_v[o] : g_q[o];
    out[((size_t)(n*LL) + t)*CH + c] = val;
}

// ---------------- 4. QK gemm: qk[n][h][l][s] = t * <q[l],k[s]> ----------------
__global__ void qk_gemm_kernel() {
    int h = blockIdx.z % NHEAD, n = blockIdx.z / NHEAD;
    int tx = threadIdx.x, ty = threadIdx.y;
    __shared__ float Qs[32][33], Ks[32][33];
    Qs[ty][tx] = g_q[0][((size_t)(n*LL + blockIdx.y*32 + ty))*CH + h*DH + tx];
    Ks[ty][tx] = g_q[1][((size_t)(n*LL + blockIdx.x*32 + ty))*CH + h*DH + tx];
    __syncthreads();
    float acc = 0.f;
    #pragma unroll
    for (int kk = 0; kk < DH; kk++) acc += Qs[ty][kk]*Ks[tx][kk];
    int l = blockIdx.y*32 + ty, s = blockIdx.x*32 + tx;
    g_qk[(((size_t)(n*NHEAD + h))*LL + l)*LL + s] = TSCALE * acc;
}

// ---------------- 5. per-row softmax stats (over s) ----------------
__global__ void rowstat_kernel() {
    int warp = threadIdx.x >> 5, lane = threadIdx.x & 31;
    int r = blockIdx.x*8 + warp;        // row over B*NH*L
    const float* row = g_qk + (size_t)r*LL;
    float mx = NEGINF;
    for (int s = lane; s < LL; s += 32) mx = fmaxf(mx, row[s]);
    #pragma unroll
    for (int o = 16; o; o >>= 1) mx = fmaxf(mx, __shfl_xor_sync(0xffffffffu, mx, o));
    float sm = 0.f;
    for (int s = lane; s < LL; s += 32) sm += __expf(row[s] - mx);
    #pragma unroll
    for (int o = 16; o; o >>= 1) sm += __shfl_xor_sync(0xffffffffu, sm, o);
    if (lane == 0) { g_rmax[r] = mx; g_rinv[r] = 1.f/sm; }
}

// ---------------- 6. m1 = S1 @ v2h  (softmax computed on the fly) ----------------
__global__ void m1_gemm_kernel() {
    int h = blockIdx.y % NHEAD, n = blockIdx.y / NHEAD;
    int tx = threadIdx.x, ty = threadIdx.y;
    int l0 = blockIdx.x*32;
    int r = (n*NHEAD + h)*LL + l0 + ty;
    float mx = g_rmax[r], ri = g_rinv[r];
    __shared__ float Ps[32][33], Vs[32][33];
    float acc = 0.f;
    for (int st = 0; st < LL; st += 32) {
        Ps[ty][tx] = __expf(g_qk[(size_t)r*LL + st + tx] - mx) * ri;
        Vs[ty][tx] = g_v[1][((size_t)(n*LL + st + ty))*CH + h*DH + tx];
        __syncthreads();
        #pragma unroll
        for (int kk = 0; kk < 32; kk++) acc += Ps[ty][kk]*Vs[kk][tx];
        __syncthreads();
    }
    g_m[0][((size_t)(n*LL + l0 + ty))*CH + h*DH + tx] = acc;
}

// ---------------- 7. S2 = softmax over heads, in place ----------------
__global__ void s2_kernel() {
    size_t idx = (size_t)blockIdx.x*blockDim.x + threadIdx.x; // over B*L*L
    int s = (int)(idx % LL);
    int l = (int)((idx / LL) % LL);
    int n = (int)(idx / ((size_t)LL*LL));
    float v[NHEAD];
    float mx = NEGINF;
    #pragma unroll
    for (int h = 0; h < NHEAD; h++) {
        v[h] = g_qk[(((size_t)(n*NHEAD + h))*LL + l)*LL + s];
        mx = fmaxf(mx, v[h]);
    }
    float sm = 0.f;
    #pragma unroll
    for (int h = 0; h < NHEAD; h++) { v[h] = __expf(v[h]-mx); sm += v[h]; }
    float ri = 1.f/sm;
    #pragma unroll
    for (int h = 0; h < NHEAD; h++)
        g_qk[(((size_t)(n*NHEAD + h))*LL + l)*LL + s] = v[h]*ri;
}

// ---------------- 8. m2[n][s][h][d] = sum_l S2[l][s] * v1[l][d] ----------------
__global__ void m2_gemm_kernel() {
    int h = blockIdx.y % NHEAD, n = blockIdx.y / NHEAD;
    int tx = threadIdx.x, ty = threadIdx.y;
    int s0 = blockIdx.x*32;
    __shared__ float As[32][33], Vs[32][33];
    float acc = 0.f;
    for (int lt = 0; lt < LL; lt += 32) {
        As[ty][tx] = g_qk[(((size_t)(n*NHEAD + h))*LL + lt + ty)*LL + s0 + tx];
        Vs[ty][tx] = g_v[0][((size_t)(n*LL + lt + ty))*CH + h*DH + tx];
        __syncthreads();
        #pragma unroll
        for (int kk = 0; kk < 32; kk++) acc += As[kk][ty]*Vs[kk][tx];
        __syncthreads();
    }
    g_m[1][((size_t)(n*LL + s0 + ty))*CH + h*DH + tx] = acc;
}

// ---------------- generic SGEMM: C[M,N] = A[M,K] @ B[N,K]^T (optional relu) ----------------
__global__ void sgemm_bt_kernel(const float* __restrict__ A, const float* __restrict__ Bw,
                                float* __restrict__ Cm, int M, int N, int K, int relu) {
    __shared__ float As[16][64];
    __shared__ float Bs[16][64];
    int t = threadIdx.x;
    int bm0 = blockIdx.y * 64;
    int bn0 = blockIdx.x * 64;
    int tx = t & 15, ty = t >> 4;
    int lr = t >> 2;
    int lc = (t & 3) << 2;
    float acc[4][4];
    #pragma unroll
    for (int i = 0; i < 4; i++)
        #pragma unroll
        for (int j = 0; j < 4; j++) acc[i][j] = 0.f;
    for (int kt = 0; kt < K; kt += 16) {
        float4 a4 = *(const float4*)(A  + (size_t)(bm0+lr)*K + kt + lc);
        float4 b4 = *(const float4*)(Bw + (size_t)(bn0+lr)*K + kt + lc);
        As[lc+0][lr]=a4.x; As[lc+1][lr]=a4.y; As[lc+2][lr]=a4.z; As[lc+3][lr]=a4.w;
        Bs[lc+0][lr]=b4.x; Bs[lc+1][lr]=b4.y; Bs[lc+2][lr]=b4.z; Bs[lc+3][lr]=b4.w;
        __syncthreads();
        #pragma unroll
        for (int k = 0; k < 16; k++) {
            float4 av = *(const float4*)&As[k][ty<<2];
            float4 bv = *(const float4*)&Bs[k][tx<<2];
            acc[0][0]+=av.x*bv.x; acc[0][1]+=av.x*bv.y; acc[0][2]+=av.x*bv.z; acc[0][3]+=av.x*bv.w;
            acc[1][0]+=av.y*bv.x; acc[1][1]+=av.y*bv.y; acc[1][2]+=av.y*bv.z; acc[1][3]+=av.y*bv.w;
            acc[2][0]+=av.z*bv.x; acc[2][1]+=av.z*bv.y; acc[2][2]+=av.z*bv.z; acc[2][3]+=av.z*bv.w;
            acc[3][0]+=av.w*bv.x; acc[3][1]+=av.w*bv.y; acc[3][2]+=av.w*bv.z; acc[3][3]+=av.w*bv.w;
        }
        __syncthreads();
    }
    #pragma unroll
    for (int i = 0; i < 4; i++) {
        int row = bm0 + (ty<<2) + i;
        #pragma unroll
        for (int j = 0; j < 4; j++) {
            float v = acc[i][j];
            if (relu) v = fmaxf(v, 0.f);
            Cm[(size_t)row*N + bn0 + (tx<<2) + j] = v;
        }
    }
}

// ---------------- 9a. copy x into U[:, 0:256] (tile transpose) ----------------
__global__ void xcopy_kernel(const float* __restrict__ x1, const float* __restrict__ x2) {
    int xt = blockIdx.x % (WW/32);
    int ct = blockIdx.x / (WW/32);
    int y  = blockIdx.y;
    int n  = blockIdx.z % BATCH;
    int o  = blockIdx.z / BATCH;
    const float* xs = o ? x2 : x1;
    int tx = threadIdx.x, ty = threadIdx.y;
    int c0 = ct*32, x0 = xt*32;
    __shared__ float sh[32][33];
    sh[ty][tx] = xs[(((size_t)(n*CH + c0+ty))*HH + y)*WW + x0 + tx];
    __syncthreads();
    size_t rbase = (size_t)o*NPIX + (size_t)n*HH*WW + (size_t)y*WW;
    g_u[(rbase + x0 + ty)*C2 + c0 + tx] = sh[tx][ty];
}

// ---------------- 9b. bilinear x4 upsample of merged map into U[:, 256:512] ----------------
__global__ void upsample_kernel() {
    int pix = blockIdx.x;                       // over 2*B*H*W
    int x = pix % WW;
    int y = (pix / WW) % HH;
    int n = (pix / (WW*HH)) % BATCH;
    int o =  pix / (WW*HH*BATCH);
    int c = threadIdx.x;
    float sy = (y + 0.5f)*0.25f - 0.5f;
    float sx = (x + 0.5f)*0.25f - 0.5f;
    int y0 = (int)floorf(sy), x0 = (int)floorf(sx);
    float fy = sy - (float)y0, fx = sx - (float)x0;
    int y0c = min(max(y0, 0), HP-1), y1c = min(max(y0+1, 0), HP-1);
    int x0c = min(max(x0, 0), WP-1), x1c = min(max(x0+1, 0), WP-1);
    const float* mm = g_mm[o] + (size_t)n*LL*CH;
    float v00 = mm[(size_t)(y0c*WP + x0c)*CH + c];
    float v01 = mm[(size_t)(y0c*WP + x1c)*CH + c];
    float v10 = mm[(size_t)(y1c*WP + x0c)*CH + c];
    float v11 = mm[(size_t)(y1c*WP + x1c)*CH + c];
    float val = (1.f-fy)*((1.f-fx)*v00 + fx*v01) + fy*((1.f-fx)*v10 + fx*v11);
    g_u[(size_t)pix*C2 + CH + c] = val;
}

// ---------------- 10. LN stats over z2 rows ----------------
__global__ void lnstat_kernel() {
    int warp = threadIdx.x >> 5, lane = threadIdx.x & 31;
    int r = blockIdx.x*8 + warp;
    const float* row = g_z2 + (size_t)r*CH;
    float s = 0.f, sq = 0.f;
    for (int c = lane; c < CH; c += 32) { float v = row[c]; s += v; sq += v*v; }
    #pragma unroll
    for (int o = 16; o; o >>= 1) {
        s  += __shfl_xor_sync(0xffffffffu, s,  o);
        sq += __shfl_xor_sync(0xffffffffu, sq, o);
    }
    if (!lane) {
        float mu = s * (1.0f/CH);
        float var = sq * (1.0f/CH) - mu*mu;
        g_mu[r] = mu;
        g_rstd[r] = rsqrtf(var + EPSF);
    }
}

// ---------------- 11. LN apply + residual + transposed write-out ----------------
__global__ void out_kernel(const float* __restrict__ x1, const float* __restrict__ x2,
                           const float* __restrict__ lg, const float* __restrict__ lb,
                           float* __restrict__ out) {
    int xt = blockIdx.x % (WW/32);
    int ct = blockIdx.x / (WW/32);
    int y  = blockIdx.y;
    int n  = blockIdx.z % BATCH;
    int o  = blockIdx.z / BATCH;
    int tx = threadIdx.x, ty = threadIdx.y;
    int c0 = ct*32, x0 = xt*32;
    size_t rbase = (size_t)o*NPIX + (size_t)n*HH*WW + (size_t)y*WW;
    __shared__ float sh[32][33];
    {
        size_t r = rbase + x0 + ty;
        float v = g_z2[r*CH + c0 + tx];
        sh[ty][tx] = lg[c0+tx]*(v - g_mu[r])*g_rstd[r] + lb[c0+tx];
    }
    __syncthreads();
    const float* xs = o ? x2 : x1;
    size_t gi = (((size_t)(n*CH + c0+ty))*HH + y)*WW + x0 + tx;
    out[(size_t)o*NPIX*CH + gi] = xs[gi] + sh[tx][ty];
}

// ---------------- launch ----------------
extern "C" void kernel_launch(void* const* d_in, const int* in_sizes, int n_in,
                              void* d_out, int out_size) {
    const float* x1     = (const float*)d_in[0];
    const float* x2     = (const float*)d_in[1];
    const float* qk_w   = (const float*)d_in[2];
    const float* qk_g   = (const float*)d_in[3];
    const float* qk_b   = (const float*)d_in[4];
    const float* qk_m   = (const float*)d_in[5];
    const float* qk_v   = (const float*)d_in[6];
    const float* v_w    = (const float*)d_in[7];
    const float* v_g    = (const float*)d_in[8];
    const float* v_b    = (const float*)d_in[9];
    const float* v_m    = (const float*)d_in[10];
    const float* v_v    = (const float*)d_in[11];
    const float* ln1_g  = (const float*)d_in[12];
    const float* ln1_b  = (const float*)d_in[13];
    const float* ln2_g  = (const float*)d_in[14];
    const float* ln2_b  = (const float*)d_in[15];
    const float* merge_w= (const float*)d_in[16];
    const float* mlp_w1 = (const float*)d_in[17];
    const float* mlp_w2 = (const float*)d_in[18];
    float* out = (float*)d_out;

    float *pm, *pmm, *pu, *pz1, *pz2;
    cudaGetSymbolAddress((void**)&pm,  g_m);
    cudaGetSymbolAddress((void**)&pmm, g_mm);
    cudaGetSymbolAddress((void**)&pu,  g_u);
    cudaGetSymbolAddress((void**)&pz1, g_z1);
    cudaGetSymbolAddress((void**)&pz2, g_z2);
    const size_t MSTRIDE = (size_t)BATCH*LL*CH;

    // pooled + LN features
    pool_kernel<<<BATCH*CH, 1024>>>(x1, 0);
    pool_kernel<<<BATCH*CH, 1024>>>(x2, 1);
    lnc_kernel<<<BATCH*LL, 256>>>(0, ln1_g, ln1_b);
    lnc_kernel<<<BATCH*LL, 256>>>(1, ln1_g, ln1_b);

    // dwconv + BN -> heads
    dwbn_kernel<<<BATCH*CH, 1024>>>(0, 0, qk_w, qk_g, qk_b, qk_m, qk_v); // query
    dwbn_kernel<<<BATCH*CH, 1024>>>(1, 0, qk_w, qk_g, qk_b, qk_m, qk_v); // key
    dwbn_kernel<<<BATCH*CH, 1024>>>(0, 1, v_w,  v_g,  v_b,  v_m,  v_v ); // v1h
    dwbn_kernel<<<BATCH*CH, 1024>>>(1, 1, v_w,  v_g,  v_b,  v_m,  v_v ); // v2h

    // attention
    qk_gemm_kernel<<<dim3(LL/32, LL/32, BATCH*NHEAD), dim3(32,32)>>>();
    rowstat_kernel<<<BATCH*NHEAD*LL/8, 256>>>();
    m1_gemm_kernel<<<dim3(LL/32, BATCH*NHEAD), dim3(32,32)>>>();
    s2_kernel<<<(BATCH*LL*LL)/256, 256>>>();
    m2_gemm_kernel<<<dim3(LL/32, BATCH*NHEAD), dim3(32,32)>>>();

    // merge linear (per output)
    sgemm_bt_kernel<<<dim3(CH/64, (BATCH*LL)/64), 256>>>(pm,           merge_w, pmm,           BATCH*LL, CH, CH, 0);
    sgemm_bt_kernel<<<dim3(CH/64, (BATCH*LL)/64), 256>>>(pm + MSTRIDE, merge_w, pmm + MSTRIDE, BATCH*LL, CH, CH, 0);

    // build concat input U
    xcopy_kernel<<<dim3((WW/32)*(CH/32), HH, 2*BATCH), dim3(32,32)>>>(x1, x2);
    upsample_kernel<<<2*BATCH*HH*WW, 256>>>();

    // MLP
    sgemm_bt_kernel<<<dim3(C2/64, NROWS/64), 256>>>(pu,  mlp_w1, pz1, NROWS, C2, C2, 1);
    sgemm_bt_kernel<<<dim3(CH/64, NROWS/64), 256>>>(pz1, mlp_w2, pz2, NROWS, CH, C2, 0);

    // LN + residual + write out
    lnstat_kernel<<<NROWS/8, 256>>>();
    out_kernel<<<dim3((WW/32)*(CH/32), HH, 2*BATCH), dim3(32,32)>>>(x1, x2, ln2_g, ln2_b, out);
}

// round 3
// speedup vs baseline: 2.0156x; 2.0156x over previous
#include <cuda_runtime.h>
#include <cstdint>

#define BATCH 4
#define CH 256
#define HH 128
#define WW 128
#define POOLW 4
#define HP 32
#define WP 32
#define LL 1024
#define NHEAD 8
#define DH 32
#define C2 512
#define NPIX (BATCH*HH*WW)      /* 65536 */
#define NROWS (2*NPIX)          /* 131072 */
#define EPSF 1e-5f
#define TSCALE 0.17677669529663687f
#define NEGINF (-3.402823466e38f)

// ---------------- scratch (device globals; no allocation) ----------------
__device__ float g_p[2][BATCH*CH*LL];          // pooled + LN'd features, [n][c][sp]
__device__ float g_q[2][(size_t)BATCH*LL*CH];  // qk-branch heads: [0]=query(x1), [1]=key(x2)
__device__ float g_v[2][(size_t)BATCH*LL*CH];  // v-branch heads:  [0]=v1h,       [1]=v2h
__device__ float g_qk[(size_t)BATCH*NHEAD*LL*LL];  // t*QK, later overwritten by S2
__device__ float g_rmax[BATCH*NHEAD*LL];
__device__ float g_rinv[BATCH*NHEAD*LL];
__device__ float g_m[2][(size_t)BATCH*LL*CH];   // m1, m2  [n][l][c]
__device__ float g_mm[2][(size_t)BATCH*LL*CH];  // after merge linear
__device__ float g_u[(size_t)NROWS*C2];         // concat MLP input
__device__ float g_z1[(size_t)NROWS*C2];        // after relu(W1)
__device__ float g_z2[(size_t)NROWS*CH];        // after W2
__device__ float g_mu[NROWS];
__device__ float g_rstd[NROWS];

// ================= mma.sync TF32 GEMM =================
// C[M,N] = A[M,K] @ B[N,K]^T (both K-major), optional relu.
// CTA tile 128x128, 8 warps (warp tile 32x64), BK=32, cp.async double buffer.
#define BK 32
#define PADK 36                        /* floats per smem row (32 data + 4 pad) */
#define TILE_FLOATS (128*PADK)         /* 4608 floats per operand tile */
#define GEMM_SMEM (4*TILE_FLOATS*4)    /* 2 stages x (A+B) = 73728 bytes */

__device__ __forceinline__ uint32_t smem_u32(const void* p) {
    uint32_t a;
    asm("{ .reg .u64 t; cvta.to.shared.u64 t, %1; cvt.u32.u64 %0, t; }" : "=r"(a) : "l"(p));
    return a;
}
__device__ __forceinline__ uint32_t f2tf(float x) {
    uint32_t r; asm("cvt.rna.tf32.f32 %0, %1;" : "=r"(r) : "f"(x)); return r;
}
#define CP_ASYNC16(dst, src) \
    asm volatile("cp.async.cg.shared.global [%0], [%1], 16;" :: "r"(dst), "l"(src) : "memory")
#define CP_COMMIT() asm volatile("cp.async.commit_group;" ::: "memory")
#define CP_WAIT(n)  asm volatile("cp.async.wait_group %0;" :: "n"(n) : "memory")

__device__ __forceinline__ void mma_tf32(float* d, const uint32_t* a, uint32_t b0, uint32_t b1) {
    asm volatile(
        "mma.sync.aligned.m16n8k8.row.col.f32.tf32.tf32.f32 "
        "{%0,%1,%2,%3}, {%4,%5,%6,%7}, {%8,%9}, {%0,%1,%2,%3};"
        : "+f"(d[0]), "+f"(d[1]), "+f"(d[2]), "+f"(d[3])
        : "r"(a[0]), "r"(a[1]), "r"(a[2]), "r"(a[3]), "r"(b0), "r"(b1));
}

__global__ __launch_bounds__(256) void mma_gemm_kernel(
        const float* __restrict__ A, const float* __restrict__ Bw, float* __restrict__ C,
        int M, int N, int K, int relu) {
    extern __shared__ float sm[];
    int tid = threadIdx.x, wid = tid >> 5, lane = tid & 31;
    int g = lane >> 2, t = lane & 3;
    int wm = wid >> 1, wn = wid & 1;             // warp tile origin: (wm*32, wn*64)
    size_t am0 = (size_t)blockIdx.y * 128;
    size_t bn0 = (size_t)blockIdx.x * 128;

    float* As[2] = { sm,                sm + 2*TILE_FLOATS };
    float* Bs[2] = { sm + TILE_FLOATS,  sm + 3*TILE_FLOATS };
    uint32_t asmem[2] = { smem_u32(As[0]), smem_u32(As[1]) };
    uint32_t bsmem[2] = { smem_u32(Bs[0]), smem_u32(Bs[1]) };

    int nchunk = K >> 5;
    float acc[2][8][4];
    #pragma unroll
    for (int mt = 0; mt < 2; mt++)
        #pragma unroll
        for (int nt = 0; nt < 8; nt++)
            #pragma unroll
            for (int i = 0; i < 4; i++) acc[mt][nt][i] = 0.f;

    // issue chunk 0
    {
        const float* Ag = A + am0 * K;
        const float* Bg = Bw + bn0 * K;
        #pragma unroll
        for (int j = 0; j < 4; j++) {
            int idx = tid + j * 256;
            int row = idx >> 3, seg = idx & 7;
            CP_ASYNC16(asmem[0] + (row*PADK + seg*4)*4, Ag + (size_t)row*K + seg*4);
            CP_ASYNC16(bsmem[0] + (row*PADK + seg*4)*4, Bg + (size_t)row*K + seg*4);
        }
        CP_COMMIT();
    }

    for (int i = 0; i < nchunk; i++) {
        int s = i & 1;
        if (i + 1 < nchunk) {
            int s1 = s ^ 1;
            const float* Ag = A + am0 * K + (i+1)*BK;
            const float* Bg = Bw + bn0 * K + (i+1)*BK;
            #pragma unroll
            for (int j = 0; j < 4; j++) {
                int idx = tid + j * 256;
                int row = idx >> 3, seg = idx & 7;
                CP_ASYNC16(asmem[s1] + (row*PADK + seg*4)*4, Ag + (size_t)row*K + seg*4);
                CP_ASYNC16(bsmem[s1] + (row*PADK + seg*4)*4, Bg + (size_t)row*K + seg*4);
            }
            CP_COMMIT();
            CP_WAIT(1);
        } else {
            CP_WAIT(0);
        }
        __syncthreads();

        const float* as = As[s] + wm*32*PADK;
        const float* bs = Bs[s] + wn*64*PADK;
        #pragma unroll
        for (int ks = 0; ks < 4; ks++) {
            int k0 = ks * 8;
            uint32_t af[2][4];
            #pragma unroll
            for (int mt = 0; mt < 2; mt++) {
                const float* ap = as + (mt*16 + g)*PADK + k0 + t;
                af[mt][0] = f2tf(ap[0]);
                af[mt][1] = f2tf(ap[8*PADK]);
                af[mt][2] = f2tf(ap[4]);
                af[mt][3] = f2tf(ap[8*PADK + 4]);
            }
            #pragma unroll
            for (int nt = 0; nt < 8; nt++) {
                const float* bp = bs + (nt*8 + g)*PADK + k0 + t;
                uint32_t b0 = f2tf(bp[0]);
                uint32_t b1 = f2tf(bp[4]);
                mma_tf32(acc[0][nt], af[0], b0, b1);
                mma_tf32(acc[1][nt], af[1], b0, b1);
            }
        }
        __syncthreads();
    }

    // epilogue
    #pragma unroll
    for (int mt = 0; mt < 2; mt++) {
        size_t row = am0 + wm*32 + mt*16 + g;
        #pragma unroll
        for (int nt = 0; nt < 8; nt++) {
            size_t col = bn0 + wn*64 + nt*8 + 2*t;
            float2 v0 = { acc[mt][nt][0], acc[mt][nt][1] };
            float2 v1 = { acc[mt][nt][2], acc[mt][nt][3] };
            if (relu) {
                v0.x = fmaxf(v0.x, 0.f); v0.y = fmaxf(v0.y, 0.f);
                v1.x = fmaxf(v1.x, 0.f); v1.y = fmaxf(v1.y, 0.f);
            }
            *(float2*)(C + row*N + col)     = v0;
            *(float2*)(C + (row+8)*N + col) = v1;
        }
    }
}

// ---------------- 1. maxpool 4x4 ----------------
__global__ void pool_kernel(const float* __restrict__ x, int o) {
    int nc = blockIdx.x;                // n*CH + c
    int t = threadIdx.x;                // 0..1023 = i*32+j
    int i = t >> 5, j = t & 31;
    const float* xp = x + (size_t)nc*HH*WW + (size_t)(i*POOLW)*WW + j*POOLW;
    float m = NEGINF;
    #pragma unroll
    for (int a = 0; a < POOLW; a++)
        #pragma unroll
        for (int b = 0; b < POOLW; b++)
            m = fmaxf(m, xp[a*WW + b]);
    g_p[o][(size_t)nc*LL + t] = m;
}

// ---------------- 2. LayerNorm over channels (in-place) ----------------
__global__ void lnc_kernel(int o, const float* __restrict__ g, const float* __restrict__ b) {
    int sp = blockIdx.x % LL;
    int n  = blockIdx.x / LL;
    int c  = threadIdx.x;               // 0..255
    size_t idx = ((size_t)(n*CH + c))*LL + sp;
    float v = g_p[o][idx];
    __shared__ float ssum[256], ssq[256];
    ssum[c] = v; ssq[c] = v*v;
    __syncthreads();
    for (int off = 128; off; off >>= 1) {
        if (c < off) { ssum[c] += ssum[c+off]; ssq[c] += ssq[c+off]; }
        __syncthreads();
    }
    float mu  = ssum[0] * (1.0f/CH);
    float var = ssq[0] * (1.0f/CH) - mu*mu;
    float r   = rsqrtf(var + EPSF);
    g_p[o][idx] = g[c]*(v-mu)*r + b[c];
}

// ---------------- 3. depthwise conv3x3 + BN -> heads layout [n][l][c] ----------------
__global__ void dwbn_kernel(int o, int branch,
                            const float* __restrict__ w, const float* __restrict__ g,
                            const float* __restrict__ b, const float* __restrict__ rm,
                            const float* __restrict__ rv) {
    int nc = blockIdx.x;
    int c = nc % CH, n = nc / CH;
    int t = threadIdx.x;
    int i = t >> 5, j = t & 31;
    __shared__ float sp[LL];
    __shared__ float wsh[9];
    sp[t] = g_p[o][(size_t)nc*LL + t];
    if (t < 9) wsh[t] = w[c*9 + t];
    __syncthreads();
    float acc = 0.f;
    #pragma unroll
    for (int di = 0; di < 3; di++) {
        int ii = i + di - 1;
        if (ii < 0 || ii >= HP) continue;
        #pragma unroll
        for (int dj = 0; dj < 3; dj++) {
            int jj = j + dj - 1;
            if (jj < 0 || jj >= WP) continue;
            acc += wsh[di*3+dj] * sp[ii*WP + jj];
        }
    }
    float sc = g[c] * rsqrtf(rv[c] + EPSF);
    float val = sc*(acc - rm[c]) + b[c];
    float* out = branch ? g_v[o] : g_q[o];
    out[((size_t)(n*LL) + t)*CH + c] = val;
}

// ---------------- 4. QK gemm: qk[n][h][l][s] = t * <q[l],k[s]> ----------------
__global__ void qk_gemm_kernel() {
    int h = blockIdx.z % NHEAD, n = blockIdx.z / NHEAD;
    int tx = threadIdx.x, ty = threadIdx.y;
    __shared__ float Qs[32][33], Ks[32][33];
    Qs[ty][tx] = g_q[0][((size_t)(n*LL + blockIdx.y*32 + ty))*CH + h*DH + tx];
    Ks[ty][tx] = g_q[1][((size_t)(n*LL + blockIdx.x*32 + ty))*CH + h*DH + tx];
    __syncthreads();
    float acc = 0.f;
    #pragma unroll
    for (int kk = 0; kk < DH; kk++) acc += Qs[ty][kk]*Ks[tx][kk];
    int l = blockIdx.y*32 + ty, s = blockIdx.x*32 + tx;
    g_qk[(((size_t)(n*NHEAD + h))*LL + l)*LL + s] = TSCALE * acc;
}

// ---------------- 5. per-row softmax stats (over s) ----------------
__global__ void rowstat_kernel() {
    int warp = threadIdx.x >> 5, lane = threadIdx.x & 31;
    int r = blockIdx.x*8 + warp;        // row over B*NH*L
    const float* row = g_qk + (size_t)r*LL;
    float mx = NEGINF;
    for (int s = lane; s < LL; s += 32) mx = fmaxf(mx, row[s]);
    #pragma unroll
    for (int o = 16; o; o >>= 1) mx = fmaxf(mx, __shfl_xor_sync(0xffffffffu, mx, o));
    float sm = 0.f;
    for (int s = lane; s < LL; s += 32) sm += __expf(row[s] - mx);
    #pragma unroll
    for (int o = 16; o; o >>= 1) sm += __shfl_xor_sync(0xffffffffu, sm, o);
    if (lane == 0) { g_rmax[r] = mx; g_rinv[r] = 1.f/sm; }
}

// ---------------- 6. m1 = S1 @ v2h  (softmax computed on the fly) ----------------
__global__ void m1_gemm_kernel() {
    int h = blockIdx.y % NHEAD, n = blockIdx.y / NHEAD;
    int tx = threadIdx.x, ty = threadIdx.y;
    int l0 = blockIdx.x*32;
    int r = (n*NHEAD + h)*LL + l0 + ty;
    float mx = g_rmax[r], ri = g_rinv[r];
    __shared__ float Ps[32][33], Vs[32][33];
    float acc = 0.f;
    for (int st = 0; st < LL; st += 32) {
        Ps[ty][tx] = __expf(g_qk[(size_t)r*LL + st + tx] - mx) * ri;
        Vs[ty][tx] = g_v[1][((size_t)(n*LL + st + ty))*CH + h*DH + tx];
        __syncthreads();
        #pragma unroll
        for (int kk = 0; kk < 32; kk++) acc += Ps[ty][kk]*Vs[kk][tx];
        __syncthreads();
    }
    g_m[0][((size_t)(n*LL + l0 + ty))*CH + h*DH + tx] = acc;
}

// ---------------- 7. S2 = softmax over heads, in place ----------------
__global__ void s2_kernel() {
    size_t idx = (size_t)blockIdx.x*blockDim.x + threadIdx.x; // over B*L*L
    int s = (int)(idx % LL);
    int l = (int)((idx / LL) % LL);
    int n = (int)(idx / ((size_t)LL*LL));
    float v[NHEAD];
    float mx = NEGINF;
    #pragma unroll
    for (int h = 0; h < NHEAD; h++) {
        v[h] = g_qk[(((size_t)(n*NHEAD + h))*LL + l)*LL + s];
        mx = fmaxf(mx, v[h]);
    }
    float sm = 0.f;
    #pragma unroll
    for (int h = 0; h < NHEAD; h++) { v[h] = __expf(v[h]-mx); sm += v[h]; }
    float ri = 1.f/sm;
    #pragma unroll
    for (int h = 0; h < NHEAD; h++)
        g_qk[(((size_t)(n*NHEAD + h))*LL + l)*LL + s] = v[h]*ri;
}

// ---------------- 8. m2[n][s][h][d] = sum_l S2[l][s] * v1[l][d] ----------------
__global__ void m2_gemm_kernel() {
    int h = blockIdx.y % NHEAD, n = blockIdx.y / NHEAD;
    int tx = threadIdx.x, ty = threadIdx.y;
    int s0 = blockIdx.x*32;
    __shared__ float As[32][33], Vs[32][33];
    float acc = 0.f;
    for (int lt = 0; lt < LL; lt += 32) {
        As[ty][tx] = g_qk[(((size_t)(n*NHEAD + h))*LL + lt + ty)*LL + s0 + tx];
        Vs[ty][tx] = g_v[0][((size_t)(n*LL + lt + ty))*CH + h*DH + tx];
        __syncthreads();
        #pragma unroll
        for (int kk = 0; kk < 32; kk++) acc += As[kk][ty]*Vs[kk][tx];
        __syncthreads();
    }
    g_m[1][((size_t)(n*LL + s0 + ty))*CH + h*DH + tx] = acc;
}

// ---------------- 9a. copy x into U[:, 0:256] (tile transpose) ----------------
__global__ void xcopy_kernel(const float* __restrict__ x1, const float* __restrict__ x2) {
    int xt = blockIdx.x % (WW/32);
    int ct = blockIdx.x / (WW/32);
    int y  = blockIdx.y;
    int n  = blockIdx.z % BATCH;
    int o  = blockIdx.z / BATCH;
    const float* xs = o ? x2 : x1;
    int tx = threadIdx.x, ty = threadIdx.y;
    int c0 = ct*32, x0 = xt*32;
    __shared__ float sh[32][33];
    sh[ty][tx] = xs[(((size_t)(n*CH + c0+ty))*HH + y)*WW + x0 + tx];
    __syncthreads();
    size_t rbase = (size_t)o*NPIX + (size_t)n*HH*WW + (size_t)y*WW;
    g_u[(rbase + x0 + ty)*C2 + c0 + tx] = sh[tx][ty];
}

// ---------------- 9b. bilinear x4 upsample of merged map into U[:, 256:512] ----------------
__global__ void upsample_kernel() {
    int pix = blockIdx.x;                       // over 2*B*H*W
    int x = pix % WW;
    int y = (pix / WW) % HH;
    int n = (pix / (WW*HH)) % BATCH;
    int o =  pix / (WW*HH*BATCH);
    int c = threadIdx.x;
    float sy = (y + 0.5f)*0.25f - 0.5f;
    float sx = (x + 0.5f)*0.25f - 0.5f;
    int y0 = (int)floorf(sy), x0 = (int)floorf(sx);
    float fy = sy - (float)y0, fx = sx - (float)x0;
    int y0c = min(max(y0, 0), HP-1), y1c = min(max(y0+1, 0), HP-1);
    int x0c = min(max(x0, 0), WP-1), x1c = min(max(x0+1, 0), WP-1);
    const float* mm = g_mm[o] + (size_t)n*LL*CH;
    float v00 = mm[(size_t)(y0c*WP + x0c)*CH + c];
    float v01 = mm[(size_t)(y0c*WP + x1c)*CH + c];
    float v10 = mm[(size_t)(y1c*WP + x0c)*CH + c];
    float v11 = mm[(size_t)(y1c*WP + x1c)*CH + c];
    float val = (1.f-fy)*((1.f-fx)*v00 + fx*v01) + fy*((1.f-fx)*v10 + fx*v11);
    g_u[(size_t)pix*C2 + CH + c] = val;
}

// ---------------- 10. LN stats over z2 rows ----------------
__global__ void lnstat_kernel() {
    int warp = threadIdx.x >> 5, lane = threadIdx.x & 31;
    int r = blockIdx.x*8 + warp;
    const float* row = g_z2 + (size_t)r*CH;
    float s = 0.f, sq = 0.f;
    for (int c = lane; c < CH; c += 32) { float v = row[c]; s += v; sq += v*v; }
    #pragma unroll
    for (int o = 16; o; o >>= 1) {
        s  += __shfl_xor_sync(0xffffffffu, s,  o);
        sq += __shfl_xor_sync(0xffffffffu, sq, o);
    }
    if (!lane) {
        float mu = s * (1.0f/CH);
        float var = sq * (1.0f/CH) - mu*mu;
        g_mu[r] = mu;
        g_rstd[r] = rsqrtf(var + EPSF);
    }
}

// ---------------- 11. LN apply + residual + transposed write-out ----------------
__global__ void out_kernel(const float* __restrict__ x1, const float* __restrict__ x2,
                           const float* __restrict__ lg, const float* __restrict__ lb,
                           float* __restrict__ out) {
    int xt = blockIdx.x % (WW/32);
    int ct = blockIdx.x / (WW/32);
    int y  = blockIdx.y;
    int n  = blockIdx.z % BATCH;
    int o  = blockIdx.z / BATCH;
    int tx = threadIdx.x, ty = threadIdx.y;
    int c0 = ct*32, x0 = xt*32;
    size_t rbase = (size_t)o*NPIX + (size_t)n*HH*WW + (size_t)y*WW;
    __shared__ float sh[32][33];
    {
        size_t r = rbase + x0 + ty;
        float v = g_z2[r*CH + c0 + tx];
        sh[ty][tx] = lg[c0+tx]*(v - g_mu[r])*g_rstd[r] + lb[c0+tx];
    }
    __syncthreads();
    const float* xs = o ? x2 : x1;
    size_t gi = (((size_t)(n*CH + c0+ty))*HH + y)*WW + x0 + tx;
    out[(size_t)o*NPIX*CH + gi] = xs[gi] + sh[tx][ty];
}

// ---------------- launch ----------------
extern "C" void kernel_launch(void* const* d_in, const int* in_sizes, int n_in,
                              void* d_out, int out_size) {
    const float* x1     = (const float*)d_in[0];
    const float* x2     = (const float*)d_in[1];
    const float* qk_w   = (const float*)d_in[2];
    const float* qk_g   = (const float*)d_in[3];
    const float* qk_b   = (const float*)d_in[4];
    const float* qk_m   = (const float*)d_in[5];
    const float* qk_v   = (const float*)d_in[6];
    const float* v_w    = (const float*)d_in[7];
    const float* v_g    = (const float*)d_in[8];
    const float* v_b    = (const float*)d_in[9];
    const float* v_m    = (const float*)d_in[10];
    const float* v_v    = (const float*)d_in[11];
    const float* ln1_g  = (const float*)d_in[12];
    const float* ln1_b  = (const float*)d_in[13];
    const float* ln2_g  = (const float*)d_in[14];
    const float* ln2_b  = (const float*)d_in[15];
    const float* merge_w= (const float*)d_in[16];
    const float* mlp_w1 = (const float*)d_in[17];
    const float* mlp_w2 = (const float*)d_in[18];
    float* out = (float*)d_out;

    float *pm, *pmm, *pu, *pz1, *pz2;
    cudaGetSymbolAddress((void**)&pm,  g_m);
    cudaGetSymbolAddress((void**)&pmm, g_mm);
    cudaGetSymbolAddress((void**)&pu,  g_u);
    cudaGetSymbolAddress((void**)&pz1, g_z1);
    cudaGetSymbolAddress((void**)&pz2, g_z2);

    cudaFuncSetAttribute(mma_gemm_kernel, cudaFuncAttributeMaxDynamicSharedMemorySize,
                         GEMM_SMEM);

    // pooled + LN features
    pool_kernel<<<BATCH*CH, 1024>>>(x1, 0);
    pool_kernel<<<BATCH*CH, 1024>>>(x2, 1);
    lnc_kernel<<<BATCH*LL, 256>>>(0, ln1_g, ln1_b);
    lnc_kernel<<<BATCH*LL, 256>>>(1, ln1_g, ln1_b);

    // dwconv + BN -> heads
    dwbn_kernel<<<BATCH*CH, 1024>>>(0, 0, qk_w, qk_g, qk_b, qk_m, qk_v); // query
    dwbn_kernel<<<BATCH*CH, 1024>>>(1, 0, qk_w, qk_g, qk_b, qk_m, qk_v); // key
    dwbn_kernel<<<BATCH*CH, 1024>>>(0, 1, v_w,  v_g,  v_b,  v_m,  v_v ); // v1h
    dwbn_kernel<<<BATCH*CH, 1024>>>(1, 1, v_w,  v_g,  v_b,  v_m,  v_v ); // v2h

    // attention
    qk_gemm_kernel<<<dim3(LL/32, LL/32, BATCH*NHEAD), dim3(32,32)>>>();
    rowstat_kernel<<<BATCH*NHEAD*LL/8, 256>>>();
    m1_gemm_kernel<<<dim3(LL/32, BATCH*NHEAD), dim3(32,32)>>>();
    s2_kernel<<<(BATCH*LL*LL)/256, 256>>>();
    m2_gemm_kernel<<<dim3(LL/32, BATCH*NHEAD), dim3(32,32)>>>();

    // merge linear: both outputs in one GEMM (g_m / g_mm contiguous [2][B*L][C])
    mma_gemm_kernel<<<dim3(CH/128, (2*BATCH*LL)/128), 256, GEMM_SMEM>>>(
        pm, merge_w, pmm, 2*BATCH*LL, CH, CH, 0);

    // build concat input U
    xcopy_kernel<<<dim3((WW/32)*(CH/32), HH, 2*BATCH), dim3(32,32)>>>(x1, x2);
    upsample_kernel<<<2*BATCH*HH*WW, 256>>>();

    // MLP (tensor-core tf32)
    mma_gemm_kernel<<<dim3(C2/128, NROWS/128), 256, GEMM_SMEM>>>(
        pu, mlp_w1, pz1, NROWS, C2, C2, 1);
    mma_gemm_kernel<<<dim3(CH/128, NROWS/128), 256, GEMM_SMEM>>>(
        pz1, mlp_w2, pz2, NROWS, CH, C2, 0);

    // LN + residual + write out
    lnstat_kernel<<<NROWS/8, 256>>>();
    out_kernel<<<dim3((WW/32)*(CH/32), HH, 2*BATCH), dim3(32,32)>>>(x1, x2, ln2_g, ln2_b, out);
}

// round 4
// speedup vs baseline: 2.8937x; 1.4357x over previous
#include <cuda_runtime.h>
#include <cstdint>

#define BATCH 4
#define CH 256
#define HH 128
#define WW 128
#define POOLW 4
#define HP 32
#define WP 32
#define LL 1024
#define NHEAD 8
#define DH 32
#define C2 512
#define NPIX (BATCH*HH*WW)      /* 65536 */
#define NROWS (2*NPIX)          /* 131072 */
#define EPSF 1e-5f
#define TSCALE 0.17677669529663687f
#define NEGINF (-3.402823466e38f)

// ---------------- scratch (device globals; no allocation) ----------------
__device__ float g_p[2][BATCH*CH*LL];          // pooled + LN'd features, [n][c][sp]
__device__ float g_q[2][(size_t)BATCH*LL*CH];  // qk-branch heads
__device__ float g_v[2][(size_t)BATCH*LL*CH];  // v-branch heads
__device__ float g_qk[(size_t)BATCH*NHEAD*LL*LL];  // t*QK, later overwritten by S2
__device__ float g_rmax[BATCH*NHEAD*LL];
__device__ float g_rinv[BATCH*NHEAD*LL];
__device__ float g_m[2][(size_t)BATCH*LL*CH];   // m1, m2 (tf32-rounded)
__device__ float g_mm[2][(size_t)BATCH*LL*CH];  // after merge linear
__device__ float g_u[(size_t)NROWS*C2];         // concat MLP input (tf32-rounded)
__device__ float g_z1[(size_t)NROWS*C2];        // relu(W1) (tf32-rounded)
__device__ float g_z2[(size_t)NROWS*CH];        // after W2
__device__ float g_mu[NROWS];
__device__ float g_rstd[NROWS];
__device__ float g_mwr[CH*CH];                  // rounded weights
__device__ float g_w1r[C2*C2];
__device__ float g_w2r[CH*C2];

// ================= helpers =================
__device__ __forceinline__ uint32_t smem_u32(const void* p) {
    uint32_t a;
    asm("{ .reg .u64 t; cvta.to.shared.u64 t, %1; cvt.u32.u64 %0, t; }" : "=r"(a) : "l"(p));
    return a;
}
__device__ __forceinline__ uint32_t f2tf(float x) {
    uint32_t r; asm("cvt.rna.tf32.f32 %0, %1;" : "=r"(r) : "f"(x)); return r;
}
__device__ __forceinline__ float rnd_tf(float x) { return __uint_as_float(f2tf(x)); }
#define CP_ASYNC16(dst, src) \
    asm volatile("cp.async.cg.shared.global [%0], [%1], 16;" :: "r"(dst), "l"(src) : "memory")
#define CP_COMMIT() asm volatile("cp.async.commit_group;" ::: "memory")
#define CP_WAIT(n)  asm volatile("cp.async.wait_group %0;" :: "n"(n) : "memory")

__device__ __forceinline__ void mma_tf32(float* d, const uint32_t* a, uint32_t b0, uint32_t b1) {
    asm volatile(
        "mma.sync.aligned.m16n8k8.row.col.f32.tf32.tf32.f32 "
        "{%0,%1,%2,%3}, {%4,%5,%6,%7}, {%8,%9}, {%0,%1,%2,%3};"
        : "+f"(d[0]), "+f"(d[1]), "+f"(d[2]), "+f"(d[3])
        : "r"(a[0]), "r"(a[1]), "r"(a[2]), "r"(a[3]), "r"(b0), "r"(b1));
}

// ================= mma.sync TF32 GEMM (operands pre-rounded to tf32) =================
#define BK 32
#define PADK 36
#define TILE_FLOATS (128*PADK)
#define GEMM_SMEM (4*TILE_FLOATS*4)

__global__ __launch_bounds__(256) void mma_gemm_kernel(
        const float* __restrict__ A, const float* __restrict__ Bw, float* __restrict__ C,
        int M, int N, int K, int relu, int rnd) {
    extern __shared__ float sm[];
    int tid = threadIdx.x, wid = tid >> 5, lane = tid & 31;
    int g = lane >> 2, t = lane & 3;
    int wm = wid >> 1, wn = wid & 1;
    size_t am0 = (size_t)blockIdx.y * 128;
    size_t bn0 = (size_t)blockIdx.x * 128;

    float* As[2] = { sm,                sm + 2*TILE_FLOATS };
    float* Bs[2] = { sm + TILE_FLOATS,  sm + 3*TILE_FLOATS };
    uint32_t asmem[2] = { smem_u32(As[0]), smem_u32(As[1]) };
    uint32_t bsmem[2] = { smem_u32(Bs[0]), smem_u32(Bs[1]) };

    int nchunk = K >> 5;
    float acc[2][8][4];
    #pragma unroll
    for (int mt = 0; mt < 2; mt++)
        #pragma unroll
        for (int nt = 0; nt < 8; nt++)
            #pragma unroll
            for (int i = 0; i < 4; i++) acc[mt][nt][i] = 0.f;

    {
        const float* Ag = A + am0 * K;
        const float* Bg = Bw + bn0 * K;
        #pragma unroll
        for (int j = 0; j < 4; j++) {
            int idx = tid + j * 256;
            int row = idx >> 3, seg = idx & 7;
            CP_ASYNC16(asmem[0] + (row*PADK + seg*4)*4, Ag + (size_t)row*K + seg*4);
            CP_ASYNC16(bsmem[0] + (row*PADK + seg*4)*4, Bg + (size_t)row*K + seg*4);
        }
        CP_COMMIT();
    }

    for (int i = 0; i < nchunk; i++) {
        int s = i & 1;
        if (i + 1 < nchunk) {
            int s1 = s ^ 1;
            const float* Ag = A + am0 * K + (i+1)*BK;
            const float* Bg = Bw + bn0 * K + (i+1)*BK;
            #pragma unroll
            for (int j = 0; j < 4; j++) {
                int idx = tid + j * 256;
                int row = idx >> 3, seg = idx & 7;
                CP_ASYNC16(asmem[s1] + (row*PADK + seg*4)*4, Ag + (size_t)row*K + seg*4);
                CP_ASYNC16(bsmem[s1] + (row*PADK + seg*4)*4, Bg + (size_t)row*K + seg*4);
            }
            CP_COMMIT();
            CP_WAIT(1);
        } else {
            CP_WAIT(0);
        }
        __syncthreads();

        const float* as = As[s] + wm*32*PADK;
        const float* bs = Bs[s] + wn*64*PADK;
        #pragma unroll
        for (int ks = 0; ks < 4; ks++) {
            int k0 = ks * 8;
            uint32_t af[2][4];
            #pragma unroll
            for (int mt = 0; mt < 2; mt++) {
                const float* ap = as + (mt*16 + g)*PADK + k0 + t;
                af[mt][0] = __float_as_uint(ap[0]);
                af[mt][1] = __float_as_uint(ap[8*PADK]);
                af[mt][2] = __float_as_uint(ap[4]);
                af[mt][3] = __float_as_uint(ap[8*PADK + 4]);
            }
            #pragma unroll
            for (int nt = 0; nt < 8; nt++) {
                const float* bp = bs + (nt*8 + g)*PADK + k0 + t;
                uint32_t b0 = __float_as_uint(bp[0]);
                uint32_t b1 = __float_as_uint(bp[4]);
                mma_tf32(acc[0][nt], af[0], b0, b1);
                mma_tf32(acc[1][nt], af[1], b0, b1);
            }
        }
        __syncthreads();
    }

    #pragma unroll
    for (int mt = 0; mt < 2; mt++) {
        size_t row = am0 + wm*32 + mt*16 + g;
        #pragma unroll
        for (int nt = 0; nt < 8; nt++) {
            size_t col = bn0 + wn*64 + nt*8 + 2*t;
            float2 v0 = { acc[mt][nt][0], acc[mt][nt][1] };
            float2 v1 = { acc[mt][nt][2], acc[mt][nt][3] };
            if (relu) {
                v0.x = fmaxf(v0.x, 0.f); v0.y = fmaxf(v0.y, 0.f);
                v1.x = fmaxf(v1.x, 0.f); v1.y = fmaxf(v1.y, 0.f);
            }
            if (rnd) {
                v0.x = rnd_tf(v0.x); v0.y = rnd_tf(v0.y);
                v1.x = rnd_tf(v1.x); v1.y = rnd_tf(v1.y);
            }
            *(float2*)(C + row*N + col)     = v0;
            *(float2*)(C + (row+8)*N + col) = v1;
        }
    }
}

// ---------------- weight tf32 rounding prepass ----------------
__global__ void roundw_kernel(const float* __restrict__ a, float* __restrict__ b, int n) {
    int i = blockIdx.x*256 + threadIdx.x;
    if (i < n) b[i] = rnd_tf(a[i]);
}

// ---------------- 1. maxpool 4x4 ----------------
__global__ void pool_kernel(const float* __restrict__ x, int o) {
    int nc = blockIdx.x;
    int t = threadIdx.x;
    int i = t >> 5, j = t & 31;
    const float* xp = x + (size_t)nc*HH*WW + (size_t)(i*POOLW)*WW + j*POOLW;
    float m = NEGINF;
    #pragma unroll
    for (int a = 0; a < POOLW; a++)
        #pragma unroll
        for (int b = 0; b < POOLW; b++)
            m = fmaxf(m, xp[a*WW + b]);
    g_p[o][(size_t)nc*LL + t] = m;
}

// ---------------- 2. LayerNorm over channels (in-place) ----------------
__global__ void lnc_kernel(int o, const float* __restrict__ g, const float* __restrict__ b) {
    int sp = blockIdx.x % LL;
    int n  = blockIdx.x / LL;
    int c  = threadIdx.x;
    size_t idx = ((size_t)(n*CH + c))*LL + sp;
    float v = g_p[o][idx];
    __shared__ float ssum[256], ssq[256];
    ssum[c] = v; ssq[c] = v*v;
    __syncthreads();
    for (int off = 128; off; off >>= 1) {
        if (c < off) { ssum[c] += ssum[c+off]; ssq[c] += ssq[c+off]; }
        __syncthreads();
    }
    float mu  = ssum[0] * (1.0f/CH);
    float var = ssq[0] * (1.0f/CH) - mu*mu;
    float r   = rsqrtf(var + EPSF);
    g_p[o][idx] = g[c]*(v-mu)*r + b[c];
}

// ---------------- 3. fused dual-branch dwconv3x3 + BN, coalesced writes ----------------
__global__ __launch_bounds__(256) void dwbn2_kernel(
        const float* __restrict__ qw, const float* __restrict__ qg, const float* __restrict__ qb,
        const float* __restrict__ qm, const float* __restrict__ qvv,
        const float* __restrict__ vw, const float* __restrict__ vg, const float* __restrict__ vb,
        const float* __restrict__ vm, const float* __restrict__ vvv) {
    int c0 = blockIdx.x * 8;
    int n  = blockIdx.y;
    int o  = blockIdx.z;
    __shared__ float sp[8*1028];
    int t = threadIdx.x;
    #pragma unroll
    for (int cc = 0; cc < 8; cc++)
        #pragma unroll
        for (int it = 0; it < 4; it++) {
            int spi = t + it*256;
            sp[cc*1028 + spi] = g_p[o][((size_t)(n*CH + c0+cc))*LL + spi];
        }
    __syncthreads();

    int cc = t & 7, jq = t >> 3;           // jq = column 0..31
    int c = c0 + cc;
    float wq[9], wv[9];
    #pragma unroll
    for (int k = 0; k < 9; k++) { wq[k] = qw[c*9+k]; wv[k] = vw[c*9+k]; }
    float scq = qg[c]*rsqrtf(qvv[c]+EPSF), bq = qb[c] - scq*qm[c];
    float scv = vg[c]*rsqrtf(vvv[c]+EPSF), bv = vb[c] - scv*vm[c];
    const float* s = sp + cc*1028;
    float* oq = g_q[o] + (size_t)(n*LL)*CH + c;
    float* ov = g_v[o] + (size_t)(n*LL)*CH + c;

    for (int i = 0; i < 32; i++) {
        float aq = 0.f, av = 0.f;
        #pragma unroll
        for (int di = 0; di < 3; di++) {
            int ii = i + di - 1;
            if (ii < 0 || ii >= HP) continue;
            #pragma unroll
            for (int dj = 0; dj < 3; dj++) {
                int jj = jq + dj - 1;
                if (jj < 0 || jj >= WP) continue;
                float x = s[ii*32 + jj];
                aq += wq[di*3+dj]*x;
                av += wv[di*3+dj]*x;
            }
        }
        int l = i*32 + jq;
        oq[(size_t)l*CH] = scq*aq + bq;
        ov[(size_t)l*CH] = scv*av + bv;
    }
}

// ---------------- 4. QK: 64x64 tile, 4x4 per thread ----------------
__global__ __launch_bounds__(256) void qk64_kernel() {
    int n = blockIdx.z >> 3, h = blockIdx.z & 7;
    int l0 = blockIdx.y*64, s0 = blockIdx.x*64;
    __shared__ float As[32][68], Bs[32][68];
    int t = threadIdx.x;
    const float* Aq = g_q[0] + ((size_t)(n*LL + l0))*CH + h*DH;
    const float* Bq = g_q[1] + ((size_t)(n*LL + s0))*CH + h*DH;
    #pragma unroll
    for (int i = 0; i < 2; i++) {
        int id = t + i*256;
        int row = id >> 3, seg = id & 7;
        float4 a4 = *(const float4*)(Aq + (size_t)row*CH + seg*4);
        float4 b4 = *(const float4*)(Bq + (size_t)row*CH + seg*4);
        As[seg*4+0][row]=a4.x; As[seg*4+1][row]=a4.y; As[seg*4+2][row]=a4.z; As[seg*4+3][row]=a4.w;
        Bs[seg*4+0][row]=b4.x; Bs[seg*4+1][row]=b4.y; Bs[seg*4+2][row]=b4.z; Bs[seg*4+3][row]=b4.w;
    }
    __syncthreads();
    int tx = t & 15, ty = t >> 4;
    float acc[4][4] = {};
    #pragma unroll
    for (int k = 0; k < 32; k++) {
        float4 av = *(const float4*)&As[k][ty*4];
        float4 bv = *(const float4*)&Bs[k][tx*4];
        acc[0][0]+=av.x*bv.x; acc[0][1]+=av.x*bv.y; acc[0][2]+=av.x*bv.z; acc[0][3]+=av.x*bv.w;
        acc[1][0]+=av.y*bv.x; acc[1][1]+=av.y*bv.y; acc[1][2]+=av.y*bv.z; acc[1][3]+=av.y*bv.w;
        acc[2][0]+=av.z*bv.x; acc[2][1]+=av.z*bv.y; acc[2][2]+=av.z*bv.z; acc[2][3]+=av.z*bv.w;
        acc[3][0]+=av.w*bv.x; acc[3][1]+=av.w*bv.y; acc[3][2]+=av.w*bv.z; acc[3][3]+=av.w*bv.w;
    }
    float* Cb = g_qk + (((size_t)(n*NHEAD + h))*LL + l0 + ty*4)*LL + s0 + tx*4;
    #pragma unroll
    for (int i = 0; i < 4; i++) {
        float4 v = { TSCALE*acc[i][0], TSCALE*acc[i][1], TSCALE*acc[i][2], TSCALE*acc[i][3] };
        *(float4*)(Cb + (size_t)i*LL) = v;
    }
}

// ---------------- 5. per-row softmax stats (over s) ----------------
__global__ void rowstat_kernel() {
    int warp = threadIdx.x >> 5, lane = threadIdx.x & 31;
    int r = blockIdx.x*8 + warp;
    const float* row = g_qk + (size_t)r*LL;
    float mx = NEGINF;
    for (int s = lane; s < LL; s += 32) mx = fmaxf(mx, row[s]);
    #pragma unroll
    for (int o = 16; o; o >>= 1) mx = fmaxf(mx, __shfl_xor_sync(0xffffffffu, mx, o));
    float sm = 0.f;
    for (int s = lane; s < LL; s += 32) sm += __expf(row[s] - mx);
    #pragma unroll
    for (int o = 16; o; o >>= 1) sm += __shfl_xor_sync(0xffffffffu, sm, o);
    if (lane == 0) { g_rmax[r] = mx; g_rinv[r] = 1.f/sm; }
}

// ---------------- 6. m1 = S1 @ v2h: 128x32 tile, 4x4 per thread ----------------
__global__ __launch_bounds__(256) void m1_kernel() {
    int n = blockIdx.y >> 3, h = blockIdx.y & 7;
    int l0 = blockIdx.x * 128;
    __shared__ float Ps[32][132], Vs[32][36], mxs[128], ris[128];
    int t = threadIdx.x;
    int rbase = (n*NHEAD + h)*LL + l0;
    if (t < 128) { mxs[t] = g_rmax[rbase + t]; ris[t] = g_rinv[rbase + t]; }
    __syncthreads();
    int tx = t & 7, ty = t >> 3;
    float acc[4][4] = {};
    for (int st = 0; st < LL; st += 32) {
        #pragma unroll
        for (int i = 0; i < 4; i++) {
            int id = t + i*256;
            int lrow = id >> 3, sseg = id & 7;
            float4 p4 = *(const float4*)(g_qk + ((size_t)(rbase + lrow))*LL + st + sseg*4);
            float mx = mxs[lrow], ri = ris[lrow];
            Ps[sseg*4+0][lrow] = __expf(p4.x - mx)*ri;
            Ps[sseg*4+1][lrow] = __expf(p4.y - mx)*ri;
            Ps[sseg*4+2][lrow] = __expf(p4.z - mx)*ri;
            Ps[sseg*4+3][lrow] = __expf(p4.w - mx)*ri;
        }
        {
            int srow = t >> 3, dseg = t & 7;
            *(float4*)&Vs[srow][dseg*4] =
                *(const float4*)(g_v[1] + ((size_t)(n*LL + st + srow))*CH + h*DH + dseg*4);
        }
        __syncthreads();
        #pragma unroll
        for (int k = 0; k < 32; k++) {
            float4 av = *(const float4*)&Ps[k][ty*4];
            float4 bv = *(const float4*)&Vs[k][tx*4];
            acc[0][0]+=av.x*bv.x; acc[0][1]+=av.x*bv.y; acc[0][2]+=av.x*bv.z; acc[0][3]+=av.x*bv.w;
            acc[1][0]+=av.y*bv.x; acc[1][1]+=av.y*bv.y; acc[1][2]+=av.y*bv.z; acc[1][3]+=av.y*bv.w;
            acc[2][0]+=av.z*bv.x; acc[2][1]+=av.z*bv.y; acc[2][2]+=av.z*bv.z; acc[2][3]+=av.z*bv.w;
            acc[3][0]+=av.w*bv.x; acc[3][1]+=av.w*bv.y; acc[3][2]+=av.w*bv.z; acc[3][3]+=av.w*bv.w;
        }
        __syncthreads();
    }
    #pragma unroll
    for (int i = 0; i < 4; i++) {
        int l = l0 + ty*4 + i;
        float4 v = { rnd_tf(acc[i][0]), rnd_tf(acc[i][1]), rnd_tf(acc[i][2]), rnd_tf(acc[i][3]) };
        *(float4*)(g_m[0] + ((size_t)(n*LL + l))*CH + h*DH + tx*4) = v;
    }
}

// ---------------- 7. S2 = softmax over heads, in place ----------------
__global__ void s2_kernel() {
    size_t idx = (size_t)blockIdx.x*blockDim.x + threadIdx.x;
    int s = (int)(idx % LL);
    int l = (int)((idx / LL) % LL);
    int n = (int)(idx / ((size_t)LL*LL));
    float v[NHEAD];
    float mx = NEGINF;
    #pragma unroll
    for (int h = 0; h < NHEAD; h++) {
        v[h] = g_qk[(((size_t)(n*NHEAD + h))*LL + l)*LL + s];
        mx = fmaxf(mx, v[h]);
    }
    float sm = 0.f;
    #pragma unroll
    for (int h = 0; h < NHEAD; h++) { v[h] = __expf(v[h]-mx); sm += v[h]; }
    float ri = 1.f/sm;
    #pragma unroll
    for (int h = 0; h < NHEAD; h++)
        g_qk[(((size_t)(n*NHEAD + h))*LL + l)*LL + s] = v[h]*ri;
}

// ---------------- 8. m2 = S2^T @ v1h: 128x32 tile, 4x4 per thread ----------------
__global__ __launch_bounds__(256) void m2_kernel() {
    int n = blockIdx.y >> 3, h = blockIdx.y & 7;
    int s0 = blockIdx.x * 128;
    __shared__ float As[32][132], Vs[32][36];
    int t = threadIdx.x;
    size_t qbase = ((size_t)(n*NHEAD + h))*LL;
    int tx = t & 7, ty = t >> 3;
    float acc[4][4] = {};
    for (int lt = 0; lt < LL; lt += 32) {
        #pragma unroll
        for (int i = 0; i < 4; i++) {
            int id = t + i*256;
            int lrow = id >> 5, sseg = id & 31;
            *(float4*)&As[lrow][sseg*4] =
                *(const float4*)(g_qk + (qbase + lt + lrow)*LL + s0 + sseg*4);
        }
        {
            int srow = t >> 3, dseg = t & 7;
            *(float4*)&Vs[srow][dseg*4] =
                *(const float4*)(g_v[0] + ((size_t)(n*LL + lt + srow))*CH + h*DH + dseg*4);
        }
        __syncthreads();
        #pragma unroll
        for (int k = 0; k < 32; k++) {
            float4 av = *(const float4*)&As[k][ty*4];
            float4 bv = *(const float4*)&Vs[k][tx*4];
            acc[0][0]+=av.x*bv.x; acc[0][1]+=av.x*bv.y; acc[0][2]+=av.x*bv.z; acc[0][3]+=av.x*bv.w;
            acc[1][0]+=av.y*bv.x; acc[1][1]+=av.y*bv.y; acc[1][2]+=av.y*bv.z; acc[1][3]+=av.y*bv.w;
            acc[2][0]+=av.z*bv.x; acc[2][1]+=av.z*bv.y; acc[2][2]+=av.z*bv.z; acc[2][3]+=av.z*bv.w;
            acc[3][0]+=av.w*bv.x; acc[3][1]+=av.w*bv.y; acc[3][2]+=av.w*bv.z; acc[3][3]+=av.w*bv.w;
        }
        __syncthreads();
    }
    #pragma unroll
    for (int i = 0; i < 4; i++) {
        int s = s0 + ty*4 + i;
        float4 v = { rnd_tf(acc[i][0]), rnd_tf(acc[i][1]), rnd_tf(acc[i][2]), rnd_tf(acc[i][3]) };
        *(float4*)(g_m[1] + ((size_t)(n*LL + s))*CH + h*DH + tx*4) = v;
    }
}

// ---------------- 9a. copy x into U[:, 0:256] (tile transpose, tf32-rounded) ----------------
__global__ void xcopy_kernel(const float* __restrict__ x1, const float* __restrict__ x2) {
    int xt = blockIdx.x % (WW/32);
    int ct = blockIdx.x / (WW/32);
    int y  = blockIdx.y;
    int n  = blockIdx.z % BATCH;
    int o  = blockIdx.z / BATCH;
    const float* xs = o ? x2 : x1;
    int tx = threadIdx.x, ty = threadIdx.y;
    int c0 = ct*32, x0 = xt*32;
    __shared__ float sh[32][33];
    sh[ty][tx] = xs[(((size_t)(n*CH + c0+ty))*HH + y)*WW + x0 + tx];
    __syncthreads();
    size_t rbase = (size_t)o*NPIX + (size_t)n*HH*WW + (size_t)y*WW;
    g_u[(rbase + x0 + ty)*C2 + c0 + tx] = rnd_tf(sh[tx][ty]);
}

// ---------------- 9b. bilinear x4 upsample into U[:, 256:512] (tf32-rounded) ----------------
__global__ void upsample_kernel() {
    int pix = blockIdx.x;
    int x = pix % WW;
    int y = (pix / WW) % HH;
    int n = (pix / (WW*HH)) % BATCH;
    int o =  pix / (WW*HH*BATCH);
    int c = threadIdx.x;
    float sy = (y + 0.5f)*0.25f - 0.5f;
    float sx = (x + 0.5f)*0.25f - 0.5f;
    int y0 = (int)floorf(sy), x0 = (int)floorf(sx);
    float fy = sy - (float)y0, fx = sx - (float)x0;
    int y0c = min(max(y0, 0), HP-1), y1c = min(max(y0+1, 0), HP-1);
    int x0c = min(max(x0, 0), WP-1), x1c = min(max(x0+1, 0), WP-1);
    const float* mm = g_mm[o] + (size_t)n*LL*CH;
    float v00 = mm[(size_t)(y0c*WP + x0c)*CH + c];
    float v01 = mm[(size_t)(y0c*WP + x1c)*CH + c];
    float v10 = mm[(size_t)(y1c*WP + x0c)*CH + c];
    float v11 = mm[(size_t)(y1c*WP + x1c)*CH + c];
    float val = (1.f-fy)*((1.f-fx)*v00 + fx*v01) + fy*((1.f-fx)*v10 + fx*v11);
    g_u[(size_t)pix*C2 + CH + c] = rnd_tf(val);
}

// ---------------- 10. LN stats over z2 rows ----------------
__global__ void lnstat_kernel() {
    int warp = threadIdx.x >> 5, lane = threadIdx.x & 31;
    int r = blockIdx.x*8 + warp;
    const float* row = g_z2 + (size_t)r*CH;
    float s = 0.f, sq = 0.f;
    for (int c = lane; c < CH; c += 32) { float v = row[c]; s += v; sq += v*v; }
    #pragma unroll
    for (int o = 16; o; o >>= 1) {
        s  += __shfl_xor_sync(0xffffffffu, s,  o);
        sq += __shfl_xor_sync(0xffffffffu, sq, o);
    }
    if (!lane) {
        float mu = s * (1.0f/CH);
        float var = sq * (1.0f/CH) - mu*mu;
        g_mu[r] = mu;
        g_rstd[r] = rsqrtf(var + EPSF);
    }
}

// ---------------- 11. LN apply + residual + transposed write-out ----------------
__global__ void out_kernel(const float* __restrict__ x1, const float* __restrict__ x2,
                           const float* __restrict__ lg, const float* __restrict__ lb,
                           float* __restrict__ out) {
    int xt = blockIdx.x % (WW/32);
    int ct = blockIdx.x / (WW/32);
    int y  = blockIdx.y;
    int n  = blockIdx.z % BATCH;
    int o  = blockIdx.z / BATCH;
    int tx = threadIdx.x, ty = threadIdx.y;
    int c0 = ct*32, x0 = xt*32;
    size_t rbase = (size_t)o*NPIX + (size_t)n*HH*WW + (size_t)y*WW;
    __shared__ float sh[32][33];
    {
        size_t r = rbase + x0 + ty;
        float v = g_z2[r*CH + c0 + tx];
        sh[ty][tx] = lg[c0+tx]*(v - g_mu[r])*g_rstd[r] + lb[c0+tx];
    }
    __syncthreads();
    const float* xs = o ? x2 : x1;
    size_t gi = (((size_t)(n*CH + c0+ty))*HH + y)*WW + x0 + tx;
    out[(size_t)o*NPIX*CH + gi] = xs[gi] + sh[tx][ty];
}

// ---------------- launch ----------------
extern "C" void kernel_launch(void* const* d_in, const int* in_sizes, int n_in,
                              void* d_out, int out_size) {
    const float* x1     = (const float*)d_in[0];
    const float* x2     = (const float*)d_in[1];
    const float* qk_w   = (const float*)d_in[2];
    const float* qk_g   = (const float*)d_in[3];
    const float* qk_b   = (const float*)d_in[4];
    const float* qk_m   = (const float*)d_in[5];
    const float* qk_v   = (const float*)d_in[6];
    const float* v_w    = (const float*)d_in[7];
    const float* v_g    = (const float*)d_in[8];
    const float* v_b    = (const float*)d_in[9];
    const float* v_m    = (const float*)d_in[10];
    const float* v_v    = (const float*)d_in[11];
    const float* ln1_g  = (const float*)d_in[12];
    const float* ln1_b  = (const float*)d_in[13];
    const float* ln2_g  = (const float*)d_in[14];
    const float* ln2_b  = (const float*)d_in[15];
    const float* merge_w= (const float*)d_in[16];
    const float* mlp_w1 = (const float*)d_in[17];
    const float* mlp_w2 = (const float*)d_in[18];
    float* out = (float*)d_out;

    float *pm, *pmm, *pu, *pz1, *pz2, *pmw, *pw1, *pw2;
    cudaGetSymbolAddress((void**)&pm,  g_m);
    cudaGetSymbolAddress((void**)&pmm, g_mm);
    cudaGetSymbolAddress((void**)&pu,  g_u);
    cudaGetSymbolAddress((void**)&pz1, g_z1);
    cudaGetSymbolAddress((void**)&pz2, g_z2);
    cudaGetSymbolAddress((void**)&pmw, g_mwr);
    cudaGetSymbolAddress((void**)&pw1, g_w1r);
    cudaGetSymbolAddress((void**)&pw2, g_w2r);

    cudaFuncSetAttribute(mma_gemm_kernel, cudaFuncAttributeMaxDynamicSharedMemorySize,
                         GEMM_SMEM);

    // weight rounding prepass
    roundw_kernel<<<(CH*CH+255)/256, 256>>>(merge_w, pmw, CH*CH);
    roundw_kernel<<<(C2*C2+255)/256, 256>>>(mlp_w1, pw1, C2*C2);
    roundw_kernel<<<(CH*C2+255)/256, 256>>>(mlp_w2, pw2, CH*C2);

    // pooled + LN features
    pool_kernel<<<BATCH*CH, 1024>>>(x1, 0);
    pool_kernel<<<BATCH*CH, 1024>>>(x2, 1);
    lnc_kernel<<<BATCH*LL, 256>>>(0, ln1_g, ln1_b);
    lnc_kernel<<<BATCH*LL, 256>>>(1, ln1_g, ln1_b);

    // fused dwconv + BN (both branches) -> heads
    dwbn2_kernel<<<dim3(CH/8, BATCH, 2), 256>>>(qk_w, qk_g, qk_b, qk_m, qk_v,
                                                v_w, v_g, v_b, v_m, v_v);

    // attention
    qk64_kernel<<<dim3(LL/64, LL/64, BATCH*NHEAD), 256>>>();
    rowstat_kernel<<<BATCH*NHEAD*LL/8, 256>>>();
    m1_kernel<<<dim3(LL/128, BATCH*NHEAD), 256>>>();
    s2_kernel<<<(BATCH*LL*LL)/256, 256>>>();
    m2_kernel<<<dim3(LL/128, BATCH*NHEAD), 256>>>();

    // merge linear: both outputs in one GEMM
    mma_gemm_kernel<<<dim3(CH/128, (2*BATCH*LL)/128), 256, GEMM_SMEM>>>(
        pm, pmw, pmm, 2*BATCH*LL, CH, CH, 0, 0);

    // build concat input U
    xcopy_kernel<<<dim3((WW/32)*(CH/32), HH, 2*BATCH), dim3(32,32)>>>(x1, x2);
    upsample_kernel<<<2*BATCH*HH*WW, 256>>>();

    // MLP (tensor-core tf32; z1 re-rounded for next GEMM)
    mma_gemm_kernel<<<dim3(C2/128, NROWS/128), 256, GEMM_SMEM>>>(
        pu, pw1, pz1, NROWS, C2, C2, 1, 1);
    mma_gemm_kernel<<<dim3(CH/128, NROWS/128), 256, GEMM_SMEM>>>(
        pz1, pw2, pz2, NROWS, CH, C2, 0, 0);

    // LN + residual + write out
    lnstat_kernel<<<NROWS/8, 256>>>();
    out_kernel<<<dim3((WW/32)*(CH/32), HH, 2*BATCH), dim3(32,32)>>>(x1, x2, ln2_g, ln2_b, out);
}

// round 6
// speedup vs baseline: 3.2128x; 1.1103x over previous
#include <cuda_runtime.h>
#include <cuda_fp16.h>
#include <cstdint>

#define BATCH 4
#define CH 256
#define HH 128
#define WW 128
#define POOLW 4
#define HP 32
#define WP 32
#define LL 1024
#define NHEAD 8
#define DH 32
#define C2 512
#define NPIX (BATCH*HH*WW)      /* 65536 */
#define NROWS (2*NPIX)          /* 131072 */
#define EPSF 1e-5f
#define TSCALE 0.17677669529663687f
#define NEGINF (-3.402823466e38f)
#define NTILES 16               /* 1024/64 s-tiles per row */

// ---------------- scratch ----------------
__device__ float  g_p[2][BATCH*CH*LL];
__device__ float  g_q[2][(size_t)BATCH*LL*CH];
__device__ float  g_v[2][(size_t)BATCH*LL*CH];
__device__ float  g_qk[(size_t)BATCH*NHEAD*LL*LL];
__device__ float  g_pmax[(size_t)BATCH*NHEAD*LL*NTILES];
__device__ float  g_psum[(size_t)BATCH*NHEAD*LL*NTILES];
__device__ float  g_rmax[BATCH*NHEAD*LL];
__device__ float  g_rinv[BATCH*NHEAD*LL];
__device__ __half g_m[2][(size_t)BATCH*LL*CH];   // m1, m2 (half)
__device__ float  g_mm[2][(size_t)BATCH*LL*CH];  // merge output (fp32)
__device__ __half g_u[(size_t)NROWS*C2];         // MLP input (half)
__device__ __half g_z1[(size_t)NROWS*C2];        // relu(W1) (half)
__device__ float  g_z2[(size_t)NROWS*CH];
__device__ __half g_mwh[CH*CH];                  // half weights
__device__ __half g_w1h[C2*C2];
__device__ __half g_w2h[CH*C2];

// ================= helpers =================
__device__ __forceinline__ uint32_t smem_u32(const void* p) {
    uint32_t a;
    asm("{ .reg .u64 t; cvta.to.shared.u64 t, %1; cvt.u32.u64 %0, t; }" : "=r"(a) : "l"(p));
    return a;
}
#define CP_ASYNC16(dst, src) \
    asm volatile("cp.async.cg.shared.global [%0], [%1], 16;" :: "r"(dst), "l"(src) : "memory")
#define CP_COMMIT() asm volatile("cp.async.commit_group;" ::: "memory")
#define CP_WAIT(n)  asm volatile("cp.async.wait_group %0;" :: "n"(n) : "memory")

__device__ __forceinline__ void mma_f16(float* d, const uint32_t* a, uint32_t b0, uint32_t b1) {
    asm volatile(
        "mma.sync.aligned.m16n8k16.row.col.f32.f16.f16.f32 "
        "{%0,%1,%2,%3}, {%4,%5,%6,%7}, {%8,%9}, {%0,%1,%2,%3};"
        : "+f"(d[0]), "+f"(d[1]), "+f"(d[2]), "+f"(d[3])
        : "r"(a[0]), "r"(a[1]), "r"(a[2]), "r"(a[3]), "r"(b0), "r"(b1));
}

// ================= fp16 mma GEMM: C[M,N] = A[M,K] @ B[N,K]^T =================
// CTA 128x128, 8 warps (warp 32x64), BK=64, cp.async double buffer.
#define BKH 64
#define PADH 72                       /* halfs per smem row */
#define TILEH (128*PADH)              /* halfs per operand tile */
#define GEMM_SMEM (4*TILEH*2)         /* 73728 bytes */

__global__ __launch_bounds__(256) void hgemm_kernel(
        const __half* __restrict__ A, const __half* __restrict__ Bw, void* __restrict__ C,
        int M, int N, int K, int relu, int outHalf) {
    extern __shared__ __half smh[];
    int tid = threadIdx.x, wid = tid >> 5, lane = tid & 31;
    int g = lane >> 2, t = lane & 3;
    int wm = wid >> 1, wn = wid & 1;
    size_t am0 = (size_t)blockIdx.y * 128;
    size_t bn0 = (size_t)blockIdx.x * 128;

    uint32_t abase[2] = { smem_u32(smh), smem_u32(smh + 2*TILEH) };
    int nchunk = K >> 6;
    float acc[2][8][4];
    #pragma unroll
    for (int mt = 0; mt < 2; mt++)
        #pragma unroll
        for (int nt = 0; nt < 8; nt++)
            #pragma unroll
            for (int i = 0; i < 4; i++) acc[mt][nt][i] = 0.f;

    // prologue: chunk 0
    {
        const __half* Ag = A + am0 * K;
        const __half* Bg = Bw + bn0 * K;
        #pragma unroll
        for (int j = 0; j < 4; j++) {
            int idx = tid + j * 256;
            int row = idx >> 3, seg = idx & 7;
            uint32_t d = (uint32_t)((row*PADH + seg*8) * 2);
            CP_ASYNC16(abase[0] + d,            Ag + (size_t)row*K + seg*8);
            CP_ASYNC16(abase[0] + TILEH*2 + d,  Bg + (size_t)row*K + seg*8);
        }
        CP_COMMIT();
    }

    for (int i = 0; i < nchunk; i++) {
        int s = i & 1;
        if (i + 1 < nchunk) {
            int s1 = s ^ 1;
            const __half* Ag = A + am0 * K + (i+1)*BKH;
            const __half* Bg = Bw + bn0 * K + (i+1)*BKH;
            #pragma unroll
            for (int j = 0; j < 4; j++) {
                int idx = tid + j * 256;
                int row = idx >> 3, seg = idx & 7;
                uint32_t d = (uint32_t)((row*PADH + seg*8) * 2);
                CP_ASYNC16(abase[s1] + d,           Ag + (size_t)row*K + seg*8);
                CP_ASYNC16(abase[s1] + TILEH*2 + d, Bg + (size_t)row*K + seg*8);
            }
            CP_COMMIT();
            CP_WAIT(1);
        } else {
            CP_WAIT(0);
        }
        __syncthreads();

        const __half* as = smh + s*2*TILEH + wm*32*PADH;
        const __half* bs = smh + s*2*TILEH + TILEH + wn*64*PADH;
        #pragma unroll
        for (int ks = 0; ks < 4; ks++) {
            int k0 = ks * 16;
            uint32_t af[2][4];
            #pragma unroll
            for (int mt = 0; mt < 2; mt++) {
                const __half* ap = as + (mt*16 + g)*PADH + k0 + 2*t;
                af[mt][0] = *(const uint32_t*)(ap);
                af[mt][1] = *(const uint32_t*)(ap + 8*PADH);
                af[mt][2] = *(const uint32_t*)(ap + 8);
                af[mt][3] = *(const uint32_t*)(ap + 8*PADH + 8);
            }
            #pragma unroll
            for (int nt = 0; nt < 8; nt++) {
                const __half* bp = bs + (nt*8 + g)*PADH + k0 + 2*t;
                uint32_t b0 = *(const uint32_t*)(bp);
                uint32_t b1 = *(const uint32_t*)(bp + 8);
                mma_f16(acc[0][nt], af[0], b0, b1);
                mma_f16(acc[1][nt], af[1], b0, b1);
            }
        }
        __syncthreads();
    }

    // epilogue
    #pragma unroll
    for (int mt = 0; mt < 2; mt++) {
        size_t row = am0 + wm*32 + mt*16 + g;
        #pragma unroll
        for (int nt = 0; nt < 8; nt++) {
            size_t col = bn0 + wn*64 + nt*8 + 2*t;
            float v0 = acc[mt][nt][0], v1 = acc[mt][nt][1];
            float v2 = acc[mt][nt][2], v3 = acc[mt][nt][3];
            if (relu) {
                v0 = fmaxf(v0,0.f); v1 = fmaxf(v1,0.f);
                v2 = fmaxf(v2,0.f); v3 = fmaxf(v3,0.f);
            }
            if (outHalf) {
                __half* Ch = (__half*)C;
                *(__half2*)(Ch + row*N + col)     = __floats2half2_rn(v0, v1);
                *(__half2*)(Ch + (row+8)*N + col) = __floats2half2_rn(v2, v3);
            } else {
                float* Cf = (float*)C;
                *(float2*)(Cf + row*N + col)     = make_float2(v0, v1);
                *(float2*)(Cf + (row+8)*N + col) = make_float2(v2, v3);
            }
        }
    }
}

// ---------------- weight fp16 rounding prepass ----------------
__global__ void roundh_kernel(const float* __restrict__ a, __half* __restrict__ b, int n) {
    int i = blockIdx.x*256 + threadIdx.x;
    if (i < n) b[i] = __float2half_rn(a[i]);
}

// ---------------- 1. maxpool 4x4 ----------------
__global__ void pool_kernel(const float* __restrict__ x, int o) {
    int nc = blockIdx.x;
    int t = threadIdx.x;
    int i = t >> 5, j = t & 31;
    const float* xp = x + (size_t)nc*HH*WW + (size_t)(i*POOLW)*WW + j*POOLW;
    float m = NEGINF;
    #pragma unroll
    for (int a = 0; a < POOLW; a++)
        #pragma unroll
        for (int b = 0; b < POOLW; b++)
            m = fmaxf(m, xp[a*WW + b]);
    g_p[o][(size_t)nc*LL + t] = m;
}

// ---------------- 2. LayerNorm over channels ----------------
__global__ void lnc_kernel(int o, const float* __restrict__ g, const float* __restrict__ b) {
    int sp = blockIdx.x % LL;
    int n  = blockIdx.x / LL;
    int c  = threadIdx.x;
    size_t idx = ((size_t)(n*CH + c))*LL + sp;
    float v = g_p[o][idx];
    __shared__ float ssum[256], ssq[256];
    ssum[c] = v; ssq[c] = v*v;
    __syncthreads();
    for (int off = 128; off; off >>= 1) {
        if (c < off) { ssum[c] += ssum[c+off]; ssq[c] += ssq[c+off]; }
        __syncthreads();
    }
    float mu  = ssum[0] * (1.0f/CH);
    float var = ssq[0] * (1.0f/CH) - mu*mu;
    float r   = rsqrtf(var + EPSF);
    g_p[o][idx] = g[c]*(v-mu)*r + b[c];
}

// ---------------- 3. fused dual-branch dwconv3x3 + BN ----------------
__global__ __launch_bounds__(256) void dwbn2_kernel(
        const float* __restrict__ qw, const float* __restrict__ qg, const float* __restrict__ qb,
        const float* __restrict__ qm, const float* __restrict__ qvv,
        const float* __restrict__ vw, const float* __restrict__ vg, const float* __restrict__ vb,
        const float* __restrict__ vm, const float* __restrict__ vvv) {
    int c0 = blockIdx.x * 8;
    int n  = blockIdx.y;
    int o  = blockIdx.z;
    __shared__ float sp[8*1028];
    int t = threadIdx.x;
    #pragma unroll
    for (int cc = 0; cc < 8; cc++)
        #pragma unroll
        for (int it = 0; it < 4; it++) {
            int spi = t + it*256;
            sp[cc*1028 + spi] = g_p[o][((size_t)(n*CH + c0+cc))*LL + spi];
        }
    __syncthreads();

    int cc = t & 7, jq = t >> 3;
    int c = c0 + cc;
    float wq[9], wv[9];
    #pragma unroll
    for (int k = 0; k < 9; k++) { wq[k] = qw[c*9+k]; wv[k] = vw[c*9+k]; }
    float scq = qg[c]*rsqrtf(qvv[c]+EPSF), bq = qb[c] - scq*qm[c];
    float scv = vg[c]*rsqrtf(vvv[c]+EPSF), bv = vb[c] - scv*vm[c];
    const float* s = sp + cc*1028;
    float* oq = g_q[o] + (size_t)(n*LL)*CH + c;
    float* ov = g_v[o] + (size_t)(n*LL)*CH + c;

    for (int i = 0; i < 32; i++) {
        float aq = 0.f, av = 0.f;
        #pragma unroll
        for (int di = 0; di < 3; di++) {
            int ii = i + di - 1;
            if (ii < 0 || ii >= HP) continue;
            #pragma unroll
            for (int dj = 0; dj < 3; dj++) {
                int jj = jq + dj - 1;
                if (jj < 0 || jj >= WP) continue;
                float x = s[ii*32 + jj];
                aq += wq[di*3+dj]*x;
                av += wv[di*3+dj]*x;
            }
        }
        int l = i*32 + jq;
        oq[(size_t)l*CH] = scq*aq + bq;
        ov[(size_t)l*CH] = scv*av + bv;
    }
}

// ---------------- 4. QK 64x64 tile + per-tile softmax partials ----------------
__global__ __launch_bounds__(256) void qk64_kernel() {
    int n = blockIdx.z >> 3, h = blockIdx.z & 7;
    int l0 = blockIdx.y*64, s0 = blockIdx.x*64;
    __shared__ float As[32][68], Bs[32][68];
    int t = threadIdx.x;
    const float* Aq = g_q[0] + ((size_t)(n*LL + l0))*CH + h*DH;
    const float* Bq = g_q[1] + ((size_t)(n*LL + s0))*CH + h*DH;
    #pragma unroll
    for (int i = 0; i < 2; i++) {
        int id = t + i*256;
        int row = id >> 3, seg = id & 7;
        float4 a4 = *(const float4*)(Aq + (size_t)row*CH + seg*4);
        float4 b4 = *(const float4*)(Bq + (size_t)row*CH + seg*4);
        As[seg*4+0][row]=a4.x; As[seg*4+1][row]=a4.y; As[seg*4+2][row]=a4.z; As[seg*4+3][row]=a4.w;
        Bs[seg*4+0][row]=b4.x; Bs[seg*4+1][row]=b4.y; Bs[seg*4+2][row]=b4.z; Bs[seg*4+3][row]=b4.w;
    }
    __syncthreads();
    int tx = t & 15, ty = t >> 4;
    float acc[4][4] = {};
    #pragma unroll
    for (int k = 0; k < 32; k++) {
        float4 av = *(const float4*)&As[k][ty*4];
        float4 bv = *(const float4*)&Bs[k][tx*4];
        acc[0][0]+=av.x*bv.x; acc[0][1]+=av.x*bv.y; acc[0][2]+=av.x*bv.z; acc[0][3]+=av.x*bv.w;
        acc[1][0]+=av.y*bv.x; acc[1][1]+=av.y*bv.y; acc[1][2]+=av.y*bv.z; acc[1][3]+=av.y*bv.w;
        acc[2][0]+=av.z*bv.x; acc[2][1]+=av.z*bv.y; acc[2][2]+=av.z*bv.z; acc[2][3]+=av.z*bv.w;
        acc[3][0]+=av.w*bv.x; acc[3][1]+=av.w*bv.y; acc[3][2]+=av.w*bv.z; acc[3][3]+=av.w*bv.w;
    }
    size_t rowbase = ((size_t)(n*NHEAD + h))*LL + l0 + ty*4;
    float* Cb = g_qk + rowbase*LL + s0 + tx*4;
    int tile = s0 >> 6;
    #pragma unroll
    for (int i = 0; i < 4; i++) {
        float v0 = TSCALE*acc[i][0], v1 = TSCALE*acc[i][1];
        float v2 = TSCALE*acc[i][2], v3 = TSCALE*acc[i][3];
        *(float4*)(Cb + (size_t)i*LL) = make_float4(v0, v1, v2, v3);
        float mx = fmaxf(fmaxf(v0, v1), fmaxf(v2, v3));
        #pragma unroll
        for (int off = 8; off; off >>= 1)
            mx = fmaxf(mx, __shfl_xor_sync(0xffffffffu, mx, off));
        float sm = __expf(v0-mx) + __expf(v1-mx) + __expf(v2-mx) + __expf(v3-mx);
        #pragma unroll
        for (int off = 8; off; off >>= 1)
            sm += __shfl_xor_sync(0xffffffffu, sm, off);
        if (tx == 0) {
            g_pmax[(rowbase + i)*NTILES + tile] = mx;
            g_psum[(rowbase + i)*NTILES + tile] = sm;
        }
    }
}

// ---------------- 5. combine tile partials into row stats ----------------
__global__ void rowstat2_kernel() {
    int r = blockIdx.x*256 + threadIdx.x;
    float pm[NTILES];
    float m = NEGINF;
    #pragma unroll
    for (int i = 0; i < NTILES; i++) {
        pm[i] = g_pmax[(size_t)r*NTILES + i];
        m = fmaxf(m, pm[i]);
    }
    float sum = 0.f;
    #pragma unroll
    for (int i = 0; i < NTILES; i++)
        sum += g_psum[(size_t)r*NTILES + i] * __expf(pm[i] - m);
    g_rmax[r] = m;
    g_rinv[r] = 1.f/sum;
}

// ---------------- 6. m1 = S1 @ v2h ----------------
__global__ __launch_bounds__(256) void m1_kernel() {
    int n = blockIdx.y >> 3, h = blockIdx.y & 7;
    int l0 = blockIdx.x * 128;
    __shared__ float Ps[32][132], Vs[32][36], mxs[128], ris[128];
    int t = threadIdx.x;
    int rbase = (n*NHEAD + h)*LL + l0;
    if (t < 128) { mxs[t] = g_rmax[rbase + t]; ris[t] = g_rinv[rbase + t]; }
    __syncthreads();
    int tx = t & 7, ty = t >> 3;
    float acc[4][4] = {};
    for (int st = 0; st < LL; st += 32) {
        #pragma unroll
        for (int i = 0; i < 4; i++) {
            int id = t + i*256;
            int lrow = id >> 3, sseg = id & 7;
            float4 p4 = *(const float4*)(g_qk + ((size_t)(rbase + lrow))*LL + st + sseg*4);
            float mx = mxs[lrow], ri = ris[lrow];
            Ps[sseg*4+0][lrow] = __expf(p4.x - mx)*ri;
            Ps[sseg*4+1][lrow] = __expf(p4.y - mx)*ri;
            Ps[sseg*4+2][lrow] = __expf(p4.z - mx)*ri;
            Ps[sseg*4+3][lrow] = __expf(p4.w - mx)*ri;
        }
        {
            int srow = t >> 3, dseg = t & 7;
            *(float4*)&Vs[srow][dseg*4] =
                *(const float4*)(g_v[1] + ((size_t)(n*LL + st + srow))*CH + h*DH + dseg*4);
        }
        __syncthreads();
        #pragma unroll
        for (int k = 0; k < 32; k++) {
            float4 av = *(const float4*)&Ps[k][ty*4];
            float4 bv = *(const float4*)&Vs[k][tx*4];
            acc[0][0]+=av.x*bv.x; acc[0][1]+=av.x*bv.y; acc[0][2]+=av.x*bv.z; acc[0][3]+=av.x*bv.w;
            acc[1][0]+=av.y*bv.x; acc[1][1]+=av.y*bv.y; acc[1][2]+=av.y*bv.z; acc[1][3]+=av.y*bv.w;
            acc[2][0]+=av.z*bv.x; acc[2][1]+=av.z*bv.y; acc[2][2]+=av.z*bv.z; acc[2][3]+=av.z*bv.w;
            acc[3][0]+=av.w*bv.x; acc[3][1]+=av.w*bv.y; acc[3][2]+=av.w*bv.z; acc[3][3]+=av.w*bv.w;
        }
        __syncthreads();
    }
    #pragma unroll
    for (int i = 0; i < 4; i++) {
        int l = l0 + ty*4 + i;
        __half2* dst = (__half2*)(g_m[0] + ((size_t)(n*LL + l))*CH + h*DH + tx*4);
        dst[0] = __floats2half2_rn(acc[i][0], acc[i][1]);
        dst[1] = __floats2half2_rn(acc[i][2], acc[i][3]);
    }
}

// ---------------- 7. S2 = softmax over heads ----------------
__global__ void s2_kernel() {
    size_t idx = (size_t)blockIdx.x*blockDim.x + threadIdx.x;
    int s = (int)(idx % LL);
    int l = (int)((idx / LL) % LL);
    int n = (int)(idx / ((size_t)LL*LL));
    float v[NHEAD];
    float mx = NEGINF;
    #pragma unroll
    for (int h = 0; h < NHEAD; h++) {
        v[h] = g_qk[(((size_t)(n*NHEAD + h))*LL + l)*LL + s];
        mx = fmaxf(mx, v[h]);
    }
    float sm = 0.f;
    #pragma unroll
    for (int h = 0; h < NHEAD; h++) { v[h] = __expf(v[h]-mx); sm += v[h]; }
    float ri = 1.f/sm;
    #pragma unroll
    for (int h = 0; h < NHEAD; h++)
        g_qk[(((size_t)(n*NHEAD + h))*LL + l)*LL + s] = v[h]*ri;
}

// ---------------- 8. m2 = S2^T @ v1h ----------------
__global__ __launch_bounds__(256) void m2_kernel() {
    int n = blockIdx.y >> 3, h = blockIdx.y & 7;
    int s0 = blockIdx.x * 128;
    __shared__ float As[32][132], Vs[32][36];
    int t = threadIdx.x;
    size_t qbase = ((size_t)(n*NHEAD + h))*LL;
    int tx = t & 7, ty = t >> 3;
    float acc[4][4] = {};
    for (int lt = 0; lt < LL; lt += 32) {
        #pragma unroll
        for (int i = 0; i < 4; i++) {
            int id = t + i*256;
            int lrow = id >> 5, sseg = id & 31;
            *(float4*)&As[lrow][sseg*4] =
                *(const float4*)(g_qk + (qbase + lt + lrow)*LL + s0 + sseg*4);
        }
        {
            int srow = t >> 3, dseg = t & 7;
            *(float4*)&Vs[srow][dseg*4] =
                *(const float4*)(g_v[0] + ((size_t)(n*LL + lt + srow))*CH + h*DH + dseg*4);
        }
        __syncthreads();
        #pragma unroll
        for (int k = 0; k < 32; k++) {
            float4 av = *(const float4*)&As[k][ty*4];
            float4 bv = *(const float4*)&Vs[k][tx*4];
            acc[0][0]+=av.x*bv.x; acc[0][1]+=av.x*bv.y; acc[0][2]+=av.x*bv.z; acc[0][3]+=av.x*bv.w;
            acc[1][0]+=av.y*bv.x; acc[1][1]+=av.y*bv.y; acc[1][2]+=av.y*bv.z; acc[1][3]+=av.y*bv.w;
            acc[2][0]+=av.z*bv.x; acc[2][1]+=av.z*bv.y; acc[2][2]+=av.z*bv.z; acc[2][3]+=av.z*bv.w;
            acc[3][0]+=av.w*bv.x; acc[3][1]+=av.w*bv.y; acc[3][2]+=av.w*bv.z; acc[3][3]+=av.w*bv.w;
        }
        __syncthreads();
    }
    #pragma unroll
    for (int i = 0; i < 4; i++) {
        int s = s0 + ty*4 + i;
        __half2* dst = (__half2*)(g_m[1] + ((size_t)(n*LL + s))*CH + h*DH + tx*4);
        dst[0] = __floats2half2_rn(acc[i][0], acc[i][1]);
        dst[1] = __floats2half2_rn(acc[i][2], acc[i][3]);
    }
}

// ---------------- 9a. copy x into U[:, 0:256] (transpose, fp16) ----------------
__global__ void xcopy_kernel(const float* __restrict__ x1, const float* __restrict__ x2) {
    int xt = blockIdx.x % (WW/32);
    int ct = blockIdx.x / (WW/32);
    int y  = blockIdx.y;
    int n  = blockIdx.z % BATCH;
    int o  = blockIdx.z / BATCH;
    const float* xs = o ? x2 : x1;
    int tx = threadIdx.x, ty = threadIdx.y;
    int c0 = ct*32, x0 = xt*32;
    __shared__ float sh[32][33];
    sh[ty][tx] = xs[(((size_t)(n*CH + c0+ty))*HH + y)*WW + x0 + tx];
    __syncthreads();
    size_t rbase = (size_t)o*NPIX + (size_t)n*HH*WW + (size_t)y*WW;
    g_u[(rbase + x0 + ty)*C2 + c0 + tx] = __float2half_rn(sh[tx][ty]);
}

// ---------------- 9b. bilinear x4 upsample into U[:, 256:512] (fp16) ----------------
__global__ void upsample_kernel() {
    int tid = threadIdx.x;
    int pix = blockIdx.x*4 + (tid >> 6);
    int cg = (tid & 63) * 4;
    int x = pix % WW;
    int y = (pix / WW) % HH;
    int n = (pix / (WW*HH)) % BATCH;
    int o =  pix / (WW*HH*BATCH);
    float sy = (y + 0.5f)*0.25f - 0.5f;
    float sx = (x + 0.5f)*0.25f - 0.5f;
    int y0 = (int)floorf(sy), x0 = (int)floorf(sx);
    float fy = sy - (float)y0, fx = sx - (float)x0;
    int y0c = min(max(y0, 0), HP-1), y1c = min(max(y0+1, 0), HP-1);
    int x0c = min(max(x0, 0), WP-1), x1c = min(max(x0+1, 0), WP-1);
    const float* mm = g_mm[o] + (size_t)n*LL*CH;
    float4 v00 = *(const float4*)(mm + (size_t)(y0c*WP + x0c)*CH + cg);
    float4 v01 = *(const float4*)(mm + (size_t)(y0c*WP + x1c)*CH + cg);
    float4 v10 = *(const float4*)(mm + (size_t)(y1c*WP + x0c)*CH + cg);
    float4 v11 = *(const float4*)(mm + (size_t)(y1c*WP + x1c)*CH + cg);
    float w00 = (1.f-fy)*(1.f-fx), w01 = (1.f-fy)*fx, w10 = fy*(1.f-fx), w11 = fy*fx;
    __half2 h0 = __floats2half2_rn(w00*v00.x + w01*v01.x + w10*v10.x + w11*v11.x,
                                   w00*v00.y + w01*v01.y + w10*v10.y + w11*v11.y);
    __half2 h1 = __floats2half2_rn(w00*v00.z + w01*v01.z + w10*v10.z + w11*v11.z,
                                   w00*v00.w + w01*v01.w + w10*v10.w + w11*v11.w);
    __half2* dst = (__half2*)(g_u + (size_t)pix*C2 + CH + cg);
    dst[0] = h0; dst[1] = h1;
}

// ---------------- 10. fused LN stats + apply + residual + write-out ----------------
__global__ __launch_bounds__(256) void out_fused_kernel(
        const float* __restrict__ x1, const float* __restrict__ x2,
        const float* __restrict__ lg, const float* __restrict__ lb,
        float* __restrict__ out) {
    int xt = blockIdx.x;              // 0..3
    int y  = blockIdx.y;
    int n  = blockIdx.z % BATCH;
    int o  = blockIdx.z / BATCH;
    __shared__ float zsh[32][257];
    __shared__ float smu[32], srs[32];
    int tid = threadIdx.x;
    size_t rbase = (size_t)o*NPIX + (size_t)n*HH*WW + (size_t)y*WW + xt*32;
    // load 32 pixels x 256 channels (scalar smem stores: 257-pitch rows are not
    // 16B-aligned for odd px, so no float4 STS here)
    #pragma unroll
    for (int j = 0; j < 4; j++) {
        int px = j*8 + (tid >> 5);
        int c = (tid & 31) * 8;
        const float* zr = g_z2 + (rbase + px)*CH + c;
        float4 a = *(const float4*)zr;
        float4 b = *(const float4*)(zr + 4);
        zsh[px][c+0] = a.x; zsh[px][c+1] = a.y; zsh[px][c+2] = a.z; zsh[px][c+3] = a.w;
        zsh[px][c+4] = b.x; zsh[px][c+5] = b.y; zsh[px][c+6] = b.z; zsh[px][c+7] = b.w;
    }
    __syncthreads();
    int w = tid >> 5, lane = tid & 31;
    #pragma unroll
    for (int i = 0; i < 4; i++) {
        int px = w*4 + i;
        float s = 0.f, sq = 0.f;
        #pragma unroll
        for (int k = 0; k < 8; k++) { float v = zsh[px][lane + k*32]; s += v; sq += v*v; }
        #pragma unroll
        for (int off = 16; off; off >>= 1) {
            s  += __shfl_xor_sync(0xffffffffu, s,  off);
            sq += __shfl_xor_sync(0xffffffffu, sq, off);
        }
        if (!lane) {
            float mu = s * (1.0f/CH);
            smu[px] = mu;
            srs[px] = rsqrtf(sq * (1.0f/CH) - mu*mu + EPSF);
        }
    }
    __syncthreads();
    const float* xs = o ? x2 : x1;
    int cth = tid >> 5, tx = tid & 31;
    float mu = smu[tx], rs = srs[tx];
    size_t xbase = ((size_t)(n*CH))*HH*WW + (size_t)y*WW + xt*32 + tx;
    float* outb = out + (size_t)o*NPIX*CH;
    #pragma unroll 8
    for (int cc = 0; cc < 32; cc++) {
        int c = cc*8 + cth;
        float val = lg[c]*(zsh[tx][c] - mu)*rs + lb[c];
        size_t gi = xbase + (size_t)c*HH*WW;
        outb[gi] = xs[gi] + val;
    }
}

// ---------------- launch ----------------
extern "C" void kernel_launch(void* const* d_in, const int* in_sizes, int n_in,
                              void* d_out, int out_size) {
    const float* x1     = (const float*)d_in[0];
    const float* x2     = (const float*)d_in[1];
    const float* qk_w   = (const float*)d_in[2];
    const float* qk_g   = (const float*)d_in[3];
    const float* qk_b   = (const float*)d_in[4];
    const float* qk_m   = (const float*)d_in[5];
    const float* qk_v   = (const float*)d_in[6];
    const float* v_w    = (const float*)d_in[7];
    const float* v_g    = (const float*)d_in[8];
    const float* v_b    = (const float*)d_in[9];
    const float* v_m    = (const float*)d_in[10];
    const float* v_v    = (const float*)d_in[11];
    const float* ln1_g  = (const float*)d_in[12];
    const float* ln1_b  = (const float*)d_in[13];
    const float* ln2_g  = (const float*)d_in[14];
    const float* ln2_b  = (const float*)d_in[15];
    const float* merge_w= (const float*)d_in[16];
    const float* mlp_w1 = (const float*)d_in[17];
    const float* mlp_w2 = (const float*)d_in[18];
    float* out = (float*)d_out;

    __half *pm, *pu, *pz1, *pmw, *pw1, *pw2;
    float *pmm, *pz2;
    cudaGetSymbolAddress((void**)&pm,  g_m);
    cudaGetSymbolAddress((void**)&pmm, g_mm);
    cudaGetSymbolAddress((void**)&pu,  g_u);
    cudaGetSymbolAddress((void**)&pz1, g_z1);
    cudaGetSymbolAddress((void**)&pz2, g_z2);
    cudaGetSymbolAddress((void**)&pmw, g_mwh);
    cudaGetSymbolAddress((void**)&pw1, g_w1h);
    cudaGetSymbolAddress((void**)&pw2, g_w2h);

    cudaFuncSetAttribute(hgemm_kernel, cudaFuncAttributeMaxDynamicSharedMemorySize, GEMM_SMEM);

    // weight fp16 prepass
    roundh_kernel<<<(CH*CH+255)/256, 256>>>(merge_w, pmw, CH*CH);
    roundh_kernel<<<(C2*C2+255)/256, 256>>>(mlp_w1, pw1, C2*C2);
    roundh_kernel<<<(CH*C2+255)/256, 256>>>(mlp_w2, pw2, CH*C2);

    // pooled + LN features
    pool_kernel<<<BATCH*CH, 1024>>>(x1, 0);
    pool_kernel<<<BATCH*CH, 1024>>>(x2, 1);
    lnc_kernel<<<BATCH*LL, 256>>>(0, ln1_g, ln1_b);
    lnc_kernel<<<BATCH*LL, 256>>>(1, ln1_g, ln1_b);

    // fused dwconv + BN -> heads
    dwbn2_kernel<<<dim3(CH/8, BATCH, 2), 256>>>(qk_w, qk_g, qk_b, qk_m, qk_v,
                                                v_w, v_g, v_b, v_m, v_v);

    // attention
    qk64_kernel<<<dim3(LL/64, LL/64, BATCH*NHEAD), 256>>>();
    rowstat2_kernel<<<BATCH*NHEAD*LL/256, 256>>>();
    m1_kernel<<<dim3(LL/128, BATCH*NHEAD), 256>>>();
    s2_kernel<<<(BATCH*LL*LL)/256, 256>>>();
    m2_kernel<<<dim3(LL/128, BATCH*NHEAD), 256>>>();

    // merge linear (both outputs in one GEMM) -> fp32 g_mm
    hgemm_kernel<<<dim3(CH/128, (2*BATCH*LL)/128), 256, GEMM_SMEM>>>(
        pm, pmw, pmm, 2*BATCH*LL, CH, CH, 0, 0);

    // build concat input U (fp16)
    xcopy_kernel<<<dim3((WW/32)*(CH/32), HH, 2*BATCH), dim3(32,32)>>>(x1, x2);
    upsample_kernel<<<NROWS/4, 256>>>();

    // MLP (fp16 tensor cores)
    hgemm_kernel<<<dim3(C2/128, NROWS/128), 256, GEMM_SMEM>>>(
        pu, pw1, pz1, NROWS, C2, C2, 1, 1);
    hgemm_kernel<<<dim3(CH/128, NROWS/128), 256, GEMM_SMEM>>>(
        pz1, pw2, pz2, NROWS, CH, C2, 0, 0);

    // fused LN + residual + write out
    out_fused_kernel<<<dim3(WW/32, HH, 2*BATCH), 256>>>(x1, x2, ln2_g, ln2_b, out);
}

// round 7
// speedup vs baseline: 4.8965x; 1.5241x over previous
#include <cuda_runtime.h>
#include <cuda_fp16.h>
#include <cstdint>

#define BATCH 4
#define CH 256
#define HH 128
#define WW 128
#define POOLW 4
#define HP 32
#define WP 32
#define LL 1024
#define NHEAD 8
#define DH 32
#define C2 512
#define NPIX (BATCH*HH*WW)      /* 65536 */
#define NROWS (2*NPIX)          /* 131072 */
#define EPSF 1e-5f
#define TSCALE 0.17677669529663687f
#define NEGINF (-3.402823466e38f)
#define NTILES 16               /* 1024/64 s-tiles per row */

// ---------------- scratch ----------------
__device__ float  g_p[2][BATCH*CH*LL];
__device__ float  g_q[2][(size_t)BATCH*LL*CH];
__device__ float  g_v[2][(size_t)BATCH*LL*CH];
__device__ float  g_qk[(size_t)BATCH*NHEAD*LL*LL];
__device__ float  g_pmax[(size_t)BATCH*NHEAD*LL*NTILES];
__device__ float  g_psum[(size_t)BATCH*NHEAD*LL*NTILES];
__device__ float  g_rmax[BATCH*NHEAD*LL];
__device__ float  g_rinv[BATCH*NHEAD*LL];
__device__ __half g_m[2][(size_t)BATCH*LL*CH];   // m1, m2 (half)
__device__ float  g_mm[2][(size_t)BATCH*LL*CH];  // merge output (fp32)
__device__ __half g_u[(size_t)NROWS*C2];         // MLP input (half)
__device__ __half g_z1[(size_t)NROWS*C2];        // relu(W1) (half)
__device__ float  g_z2[(size_t)NROWS*CH];
__device__ __half g_mwh[CH*CH];                  // half weights
__device__ __half g_w1h[C2*C2];
__device__ __half g_w2h[CH*C2];

// ================= helpers =================
__device__ __forceinline__ uint32_t smem_u32(const void* p) {
    uint32_t a;
    asm("{ .reg .u64 t; cvta.to.shared.u64 t, %1; cvt.u32.u64 %0, t; }" : "=r"(a) : "l"(p));
    return a;
}
#define CP_ASYNC16(dst, src) \
    asm volatile("cp.async.cg.shared.global [%0], [%1], 16;" :: "r"(dst), "l"(src) : "memory")
#define CP_COMMIT() asm volatile("cp.async.commit_group;" ::: "memory")
#define CP_WAIT(n)  asm volatile("cp.async.wait_group %0;" :: "n"(n) : "memory")
#define LDSM_X4(r0, r1, r2, r3, addr) \
    asm volatile("ldmatrix.sync.aligned.m8n8.x4.shared.b16 {%0,%1,%2,%3}, [%4];" \
        : "=r"(r0), "=r"(r1), "=r"(r2), "=r"(r3) : "r"(addr))

__device__ __forceinline__ void mma_f16(float* d, const uint32_t* a, uint32_t b0, uint32_t b1) {
    asm volatile(
        "mma.sync.aligned.m16n8k16.row.col.f32.f16.f16.f32 "
        "{%0,%1,%2,%3}, {%4,%5,%6,%7}, {%8,%9}, {%0,%1,%2,%3};"
        : "+f"(d[0]), "+f"(d[1]), "+f"(d[2]), "+f"(d[3])
        : "r"(a[0]), "r"(a[1]), "r"(a[2]), "r"(a[3]), "r"(b0), "r"(b1));
}

// ================= fp16 mma GEMM: C[M,N] = A[M,K] @ B[N,K]^T =================
// CTA 128x128, 8 warps (warp 32x64), BK=64, cp.async 3-stage, ldmatrix fragments.
#define BKH 64
#define PADH 72                        /* halfs per smem row */
#define TILEH (128*PADH)               /* halfs per operand tile */
#define TILE_BYTES (TILEH*2)           /* 18432 */
#define STAGE_BYTES (2*TILE_BYTES)     /* A+B per stage = 36864 */
#define GEMM_SMEM (3*STAGE_BYTES)      /* 110592 bytes */

__global__ __launch_bounds__(256) void hgemm_kernel(
        const __half* __restrict__ A, const __half* __restrict__ Bw, void* __restrict__ C,
        int M, int N, int K, int relu, int outHalf) {
    extern __shared__ __half smh[];
    int tid = threadIdx.x, wid = tid >> 5, lane = tid & 31;
    int g = lane >> 2, t = lane & 3;
    int r = lane & 7, quad = lane >> 3;
    int wm = wid >> 1, wn = wid & 1;
    size_t am0 = (size_t)blockIdx.y * 128;
    size_t bn0 = (size_t)blockIdx.x * 128;
    uint32_t smembase = smem_u32(smh);

    // ldmatrix lane offsets (bytes, relative to tile base)
    uint32_t a_off[2], b_off[4];
    #pragma unroll
    for (int mt = 0; mt < 2; mt++)
        a_off[mt] = (uint32_t)(((wm*32 + mt*16 + (quad&1)*8 + r)*PADH + (quad>>1)*8) * 2);
    #pragma unroll
    for (int p = 0; p < 4; p++)
        b_off[p] = (uint32_t)(((wn*64 + p*16 + (quad>>1)*8 + r)*PADH + (quad&1)*8) * 2);

    int nchunk = K >> 6;
    float acc[2][8][4];
    #pragma unroll
    for (int mt = 0; mt < 2; mt++)
        #pragma unroll
        for (int nt = 0; nt < 8; nt++)
            #pragma unroll
            for (int i = 0; i < 4; i++) acc[mt][nt][i] = 0.f;

    auto issue = [&](int ch, int st) {
        const __half* Ag = A + am0 * K + ch*BKH;
        const __half* Bg = Bw + bn0 * K + ch*BKH;
        uint32_t base = smembase + st*STAGE_BYTES;
        #pragma unroll
        for (int j = 0; j < 4; j++) {
            int idx = tid + j * 256;
            int row = idx >> 3, seg = idx & 7;
            uint32_t d = (uint32_t)((row*PADH + seg*8) * 2);
            CP_ASYNC16(base + d,              Ag + (size_t)row*K + seg*8);
            CP_ASYNC16(base + TILE_BYTES + d, Bg + (size_t)row*K + seg*8);
        }
        CP_COMMIT();
    };

    issue(0, 0);
    if (nchunk > 1) issue(1, 1);

    for (int i = 0; i < nchunk; i++) {
        int s = i % 3;
        if (i + 2 < nchunk) { issue(i + 2, (i + 2) % 3); CP_WAIT(2); }
        else if (i + 1 < nchunk) { CP_WAIT(1); }
        else { CP_WAIT(0); }
        __syncthreads();

        uint32_t abase = smembase + s*STAGE_BYTES;
        uint32_t bbase = abase + TILE_BYTES;
        #pragma unroll
        for (int ks = 0; ks < 4; ks++) {
            uint32_t koff = (uint32_t)(ks * 32);     // 16 halfs = 32 bytes
            uint32_t af[2][4];
            LDSM_X4(af[0][0], af[0][1], af[0][2], af[0][3], abase + a_off[0] + koff);
            LDSM_X4(af[1][0], af[1][1], af[1][2], af[1][3], abase + a_off[1] + koff);
            #pragma unroll
            for (int p = 0; p < 4; p++) {
                uint32_t b0, b1, b2, b3;
                LDSM_X4(b0, b1, b2, b3, bbase + b_off[p] + koff);
                mma_f16(acc[0][2*p],   af[0], b0, b1);
                mma_f16(acc[1][2*p],   af[1], b0, b1);
                mma_f16(acc[0][2*p+1], af[0], b2, b3);
                mma_f16(acc[1][2*p+1], af[1], b2, b3);
            }
        }
        __syncthreads();
    }

    // epilogue
    #pragma unroll
    for (int mt = 0; mt < 2; mt++) {
        size_t row = am0 + wm*32 + mt*16 + g;
        #pragma unroll
        for (int nt = 0; nt < 8; nt++) {
            size_t col = bn0 + wn*64 + nt*8 + 2*t;
            float v0 = acc[mt][nt][0], v1 = acc[mt][nt][1];
            float v2 = acc[mt][nt][2], v3 = acc[mt][nt][3];
            if (relu) {
                v0 = fmaxf(v0,0.f); v1 = fmaxf(v1,0.f);
                v2 = fmaxf(v2,0.f); v3 = fmaxf(v3,0.f);
            }
            if (outHalf) {
                __half* Ch = (__half*)C;
                *(__half2*)(Ch + row*N + col)     = __floats2half2_rn(v0, v1);
                *(__half2*)(Ch + (row+8)*N + col) = __floats2half2_rn(v2, v3);
            } else {
                float* Cf = (float*)C;
                *(float2*)(Cf + row*N + col)     = make_float2(v0, v1);
                *(float2*)(Cf + (row+8)*N + col) = make_float2(v2, v3);
            }
        }
    }
}

// ---------------- weight fp16 rounding prepass ----------------
__global__ void roundh_kernel(const float* __restrict__ a, __half* __restrict__ b, int n) {
    int i = blockIdx.x*256 + threadIdx.x;
    if (i < n) b[i] = __float2half_rn(a[i]);
}

// ---------------- 1. maxpool 4x4 ----------------
__global__ void pool_kernel(const float* __restrict__ x, int o) {
    int nc = blockIdx.x;
    int t = threadIdx.x;
    int i = t >> 5, j = t & 31;
    const float* xp = x + (size_t)nc*HH*WW + (size_t)(i*POOLW)*WW + j*POOLW;
    float m = NEGINF;
    #pragma unroll
    for (int a = 0; a < POOLW; a++)
        #pragma unroll
        for (int b = 0; b < POOLW; b++)
            m = fmaxf(m, xp[a*WW + b]);
    g_p[o][(size_t)nc*LL + t] = m;
}

// ---------------- 2. LayerNorm over channels ----------------
__global__ void lnc_kernel(int o, const float* __restrict__ g, const float* __restrict__ b) {
    int sp = blockIdx.x % LL;
    int n  = blockIdx.x / LL;
    int c  = threadIdx.x;
    size_t idx = ((size_t)(n*CH + c))*LL + sp;
    float v = g_p[o][idx];
    __shared__ float ssum[256], ssq[256];
    ssum[c] = v; ssq[c] = v*v;
    __syncthreads();
    for (int off = 128; off; off >>= 1) {
        if (c < off) { ssum[c] += ssum[c+off]; ssq[c] += ssq[c+off]; }
        __syncthreads();
    }
    float mu  = ssum[0] * (1.0f/CH);
    float var = ssq[0] * (1.0f/CH) - mu*mu;
    float rr  = rsqrtf(var + EPSF);
    g_p[o][idx] = g[c]*(v-mu)*rr + b[c];
}

// ---------------- 3. fused dual-branch dwconv3x3 + BN ----------------
__global__ __launch_bounds__(256) void dwbn2_kernel(
        const float* __restrict__ qw, const float* __restrict__ qg, const float* __restrict__ qb,
        const float* __restrict__ qm, const float* __restrict__ qvv,
        const float* __restrict__ vw, const float* __restrict__ vg, const float* __restrict__ vb,
        const float* __restrict__ vm, const float* __restrict__ vvv) {
    int c0 = blockIdx.x * 8;
    int n  = blockIdx.y;
    int o  = blockIdx.z;
    __shared__ float sp[8*1028];
    int t = threadIdx.x;
    #pragma unroll
    for (int cc = 0; cc < 8; cc++)
        #pragma unroll
        for (int it = 0; it < 4; it++) {
            int spi = t + it*256;
            sp[cc*1028 + spi] = g_p[o][((size_t)(n*CH + c0+cc))*LL + spi];
        }
    __syncthreads();

    int cc = t & 7, jq = t >> 3;
    int c = c0 + cc;
    float wq[9], wv[9];
    #pragma unroll
    for (int k = 0; k < 9; k++) { wq[k] = qw[c*9+k]; wv[k] = vw[c*9+k]; }
    float scq = qg[c]*rsqrtf(qvv[c]+EPSF), bq = qb[c] - scq*qm[c];
    float scv = vg[c]*rsqrtf(vvv[c]+EPSF), bv = vb[c] - scv*vm[c];
    const float* s = sp + cc*1028;
    float* oq = g_q[o] + (size_t)(n*LL)*CH + c;
    float* ov = g_v[o] + (size_t)(n*LL)*CH + c;

    for (int i = 0; i < 32; i++) {
        float aq = 0.f, av = 0.f;
        #pragma unroll
        for (int di = 0; di < 3; di++) {
            int ii = i + di - 1;
            if (ii < 0 || ii >= HP) continue;
            #pragma unroll
            for (int dj = 0; dj < 3; dj++) {
                int jj = jq + dj - 1;
                if (jj < 0 || jj >= WP) continue;
                float x = s[ii*32 + jj];
                aq += wq[di*3+dj]*x;
                av += wv[di*3+dj]*x;
            }
        }
        int l = i*32 + jq;
        oq[(size_t)l*CH] = scq*aq + bq;
        ov[(size_t)l*CH] = scv*av + bv;
    }
}

// ---------------- 4. QK 64x64 tile + per-tile softmax partials ----------------
__global__ __launch_bounds__(256) void qk64_kernel() {
    int n = blockIdx.z >> 3, h = blockIdx.z & 7;
    int l0 = blockIdx.y*64, s0 = blockIdx.x*64;
    __shared__ float As[32][68], Bs[32][68];
    int t = threadIdx.x;
    const float* Aq = g_q[0] + ((size_t)(n*LL + l0))*CH + h*DH;
    const float* Bq = g_q[1] + ((size_t)(n*LL + s0))*CH + h*DH;
    #pragma unroll
    for (int i = 0; i < 2; i++) {
        int id = t + i*256;
        int row = id >> 3, seg = id & 7;
        float4 a4 = *(const float4*)(Aq + (size_t)row*CH + seg*4);
        float4 b4 = *(const float4*)(Bq + (size_t)row*CH + seg*4);
        As[seg*4+0][row]=a4.x; As[seg*4+1][row]=a4.y; As[seg*4+2][row]=a4.z; As[seg*4+3][row]=a4.w;
        Bs[seg*4+0][row]=b4.x; Bs[seg*4+1][row]=b4.y; Bs[seg*4+2][row]=b4.z; Bs[seg*4+3][row]=b4.w;
    }
    __syncthreads();
    int tx = t & 15, ty = t >> 4;
    float acc[4][4] = {};
    #pragma unroll
    for (int k = 0; k < 32; k++) {
        float4 av = *(const float4*)&As[k][ty*4];
        float4 bv = *(const float4*)&Bs[k][tx*4];
        acc[0][0]+=av.x*bv.x; acc[0][1]+=av.x*bv.y; acc[0][2]+=av.x*bv.z; acc[0][3]+=av.x*bv.w;
        acc[1][0]+=av.y*bv.x; acc[1][1]+=av.y*bv.y; acc[1][2]+=av.y*bv.z; acc[1][3]+=av.y*bv.w;
        acc[2][0]+=av.z*bv.x; acc[2][1]+=av.z*bv.y; acc[2][2]+=av.z*bv.z; acc[2][3]+=av.z*bv.w;
        acc[3][0]+=av.w*bv.x; acc[3][1]+=av.w*bv.y; acc[3][2]+=av.w*bv.z; acc[3][3]+=av.w*bv.w;
    }
    size_t rowbase = ((size_t)(n*NHEAD + h))*LL + l0 + ty*4;
    float* Cb = g_qk + rowbase*LL + s0 + tx*4;
    int tile = s0 >> 6;
    #pragma unroll
    for (int i = 0; i < 4; i++) {
        float v0 = TSCALE*acc[i][0], v1 = TSCALE*acc[i][1];
        float v2 = TSCALE*acc[i][2], v3 = TSCALE*acc[i][3];
        *(float4*)(Cb + (size_t)i*LL) = make_float4(v0, v1, v2, v3);
        float mx = fmaxf(fmaxf(v0, v1), fmaxf(v2, v3));
        #pragma unroll
        for (int off = 8; off; off >>= 1)
            mx = fmaxf(mx, __shfl_xor_sync(0xffffffffu, mx, off));
        float sm = __expf(v0-mx) + __expf(v1-mx) + __expf(v2-mx) + __expf(v3-mx);
        #pragma unroll
        for (int off = 8; off; off >>= 1)
            sm += __shfl_xor_sync(0xffffffffu, sm, off);
        if (tx == 0) {
            g_pmax[(rowbase + i)*NTILES + tile] = mx;
            g_psum[(rowbase + i)*NTILES + tile] = sm;
        }
    }
}

// ---------------- 5. combine tile partials into row stats ----------------
__global__ void rowstat2_kernel() {
    int r = blockIdx.x*256 + threadIdx.x;
    float pm[NTILES];
    float m = NEGINF;
    #pragma unroll
    for (int i = 0; i < NTILES; i++) {
        pm[i] = g_pmax[(size_t)r*NTILES + i];
        m = fmaxf(m, pm[i]);
    }
    float sum = 0.f;
    #pragma unroll
    for (int i = 0; i < NTILES; i++)
        sum += g_psum[(size_t)r*NTILES + i] * __expf(pm[i] - m);
    g_rmax[r] = m;
    g_rinv[r] = 1.f/sum;
}

// ---------------- 6. m1 = S1 @ v2h ----------------
__global__ __launch_bounds__(256) void m1_kernel() {
    int n = blockIdx.y >> 3, h = blockIdx.y & 7;
    int l0 = blockIdx.x * 128;
    __shared__ float Ps[32][132], Vs[32][36], mxs[128], ris[128];
    int t = threadIdx.x;
    int rbase = (n*NHEAD + h)*LL + l0;
    if (t < 128) { mxs[t] = g_rmax[rbase + t]; ris[t] = g_rinv[rbase + t]; }
    __syncthreads();
    int tx = t & 7, ty = t >> 3;
    float acc[4][4] = {};
    for (int st = 0; st < LL; st += 32) {
        #pragma unroll
        for (int i = 0; i < 4; i++) {
            int id = t + i*256;
            int lrow = id >> 3, sseg = id & 7;
            float4 p4 = *(const float4*)(g_qk + ((size_t)(rbase + lrow))*LL + st + sseg*4);
            float mx = mxs[lrow], ri = ris[lrow];
            Ps[sseg*4+0][lrow] = __expf(p4.x - mx)*ri;
            Ps[sseg*4+1][lrow] = __expf(p4.y - mx)*ri;
            Ps[sseg*4+2][lrow] = __expf(p4.z - mx)*ri;
            Ps[sseg*4+3][lrow] = __expf(p4.w - mx)*ri;
        }
        {
            int srow = t >> 3, dseg = t & 7;
            *(float4*)&Vs[srow][dseg*4] =
                *(const float4*)(g_v[1] + ((size_t)(n*LL + st + srow))*CH + h*DH + dseg*4);
        }
        __syncthreads();
        #pragma unroll
        for (int k = 0; k < 32; k++) {
            float4 av = *(const float4*)&Ps[k][ty*4];
            float4 bv = *(const float4*)&Vs[k][tx*4];
            acc[0][0]+=av.x*bv.x; acc[0][1]+=av.x*bv.y; acc[0][2]+=av.x*bv.z; acc[0][3]+=av.x*bv.w;
            acc[1][0]+=av.y*bv.x; acc[1][1]+=av.y*bv.y; acc[1][2]+=av.y*bv.z; acc[1][3]+=av.y*bv.w;
            acc[2][0]+=av.z*bv.x; acc[2][1]+=av.z*bv.y; acc[2][2]+=av.z*bv.z; acc[2][3]+=av.z*bv.w;
            acc[3][0]+=av.w*bv.x; acc[3][1]+=av.w*bv.y; acc[3][2]+=av.w*bv.z; acc[3][3]+=av.w*bv.w;
        }
        __syncthreads();
    }
    #pragma unroll
    for (int i = 0; i < 4; i++) {
        int l = l0 + ty*4 + i;
        __half2* dst = (__half2*)(g_m[0] + ((size_t)(n*LL + l))*CH + h*DH + tx*4);
        dst[0] = __floats2half2_rn(acc[i][0], acc[i][1]);
        dst[1] = __floats2half2_rn(acc[i][2], acc[i][3]);
    }
}

// ---------------- 7. S2 = softmax over heads ----------------
__global__ void s2_kernel() {
    size_t idx = (size_t)blockIdx.x*blockDim.x + threadIdx.x;
    int s = (int)(idx % LL);
    int l = (int)((idx / LL) % LL);
    int n = (int)(idx / ((size_t)LL*LL));
    float v[NHEAD];
    float mx = NEGINF;
    #pragma unroll
    for (int h = 0; h < NHEAD; h++) {
        v[h] = g_qk[(((size_t)(n*NHEAD + h))*LL + l)*LL + s];
        mx = fmaxf(mx, v[h]);
    }
    float sm = 0.f;
    #pragma unroll
    for (int h = 0; h < NHEAD; h++) { v[h] = __expf(v[h]-mx); sm += v[h]; }
    float ri = 1.f/sm;
    #pragma unroll
    for (int h = 0; h < NHEAD; h++)
        g_qk[(((size_t)(n*NHEAD + h))*LL + l)*LL + s] = v[h]*ri;
}

// ---------------- 8. m2 = S2^T @ v1h ----------------
__global__ __launch_bounds__(256) void m2_kernel() {
    int n = blockIdx.y >> 3, h = blockIdx.y & 7;
    int s0 = blockIdx.x * 128;
    __shared__ float As[32][132], Vs[32][36];
    int t = threadIdx.x;
    size_t qbase = ((size_t)(n*NHEAD + h))*LL;
    int tx = t & 7, ty = t >> 3;
    float acc[4][4] = {};
    for (int lt = 0; lt < LL; lt += 32) {
        #pragma unroll
        for (int i = 0; i < 4; i++) {
            int id = t + i*256;
            int lrow = id >> 5, sseg = id & 31;
            *(float4*)&As[lrow][sseg*4] =
                *(const float4*)(g_qk + (qbase + lt + lrow)*LL + s0 + sseg*4);
        }
        {
            int srow = t >> 3, dseg = t & 7;
            *(float4*)&Vs[srow][dseg*4] =
                *(const float4*)(g_v[0] + ((size_t)(n*LL + lt + srow))*CH + h*DH + dseg*4);
        }
        __syncthreads();
        #pragma unroll
        for (int k = 0; k < 32; k++) {
            float4 av = *(const float4*)&As[k][ty*4];
            float4 bv = *(const float4*)&Vs[k][tx*4];
            acc[0][0]+=av.x*bv.x; acc[0][1]+=av.x*bv.y; acc[0][2]+=av.x*bv.z; acc[0][3]+=av.x*bv.w;
            acc[1][0]+=av.y*bv.x; acc[1][1]+=av.y*bv.y; acc[1][2]+=av.y*bv.z; acc[1][3]+=av.y*bv.w;
            acc[2][0]+=av.z*bv.x; acc[2][1]+=av.z*bv.y; acc[2][2]+=av.z*bv.z; acc[2][3]+=av.z*bv.w;
            acc[3][0]+=av.w*bv.x; acc[3][1]+=av.w*bv.y; acc[3][2]+=av.w*bv.z; acc[3][3]+=av.w*bv.w;
        }
        __syncthreads();
    }
    #pragma unroll
    for (int i = 0; i < 4; i++) {
        int s = s0 + ty*4 + i;
        __half2* dst = (__half2*)(g_m[1] + ((size_t)(n*LL + s))*CH + h*DH + tx*4);
        dst[0] = __floats2half2_rn(acc[i][0], acc[i][1]);
        dst[1] = __floats2half2_rn(acc[i][2], acc[i][3]);
    }
}

// ---------------- 9a. copy x into U[:, 0:256] (transpose, fp16) ----------------
__global__ void xcopy_kernel(const float* __restrict__ x1, const float* __restrict__ x2) {
    int xt = blockIdx.x % (WW/32);
    int ct = blockIdx.x / (WW/32);
    int y  = blockIdx.y;
    int n  = blockIdx.z % BATCH;
    int o  = blockIdx.z / BATCH;
    const float* xs = o ? x2 : x1;
    int tx = threadIdx.x, ty = threadIdx.y;
    int c0 = ct*32, x0 = xt*32;
    __shared__ float sh[32][33];
    sh[ty][tx] = xs[(((size_t)(n*CH + c0+ty))*HH + y)*WW + x0 + tx];
    __syncthreads();
    size_t rbase = (size_t)o*NPIX + (size_t)n*HH*WW + (size_t)y*WW;
    g_u[(rbase + x0 + ty)*C2 + c0 + tx] = __float2half_rn(sh[tx][ty]);
}

// ---------------- 9b. bilinear x4 upsample into U[:, 256:512] (fp16) ----------------
__global__ void upsample_kernel() {
    int tid = threadIdx.x;
    int pix = blockIdx.x*4 + (tid >> 6);
    int cg = (tid & 63) * 4;
    int x = pix % WW;
    int y = (pix / WW) % HH;
    int n = (pix / (WW*HH)) % BATCH;
    int o =  pix / (WW*HH*BATCH);
    float sy = (y + 0.5f)*0.25f - 0.5f;
    float sx = (x + 0.5f)*0.25f - 0.5f;
    int y0 = (int)floorf(sy), x0 = (int)floorf(sx);
    float fy = sy - (float)y0, fx = sx - (float)x0;
    int y0c = min(max(y0, 0), HP-1), y1c = min(max(y0+1, 0), HP-1);
    int x0c = min(max(x0, 0), WP-1), x1c = min(max(x0+1, 0), WP-1);
    const float* mm = g_mm[o] + (size_t)n*LL*CH;
    float4 v00 = *(const float4*)(mm + (size_t)(y0c*WP + x0c)*CH + cg);
    float4 v01 = *(const float4*)(mm + (size_t)(y0c*WP + x1c)*CH + cg);
    float4 v10 = *(const float4*)(mm + (size_t)(y1c*WP + x0c)*CH + cg);
    float4 v11 = *(const float4*)(mm + (size_t)(y1c*WP + x1c)*CH + cg);
    float w00 = (1.f-fy)*(1.f-fx), w01 = (1.f-fy)*fx, w10 = fy*(1.f-fx), w11 = fy*fx;
    __half2 h0 = __floats2half2_rn(w00*v00.x + w01*v01.x + w10*v10.x + w11*v11.x,
                                   w00*v00.y + w01*v01.y + w10*v10.y + w11*v11.y);
    __half2 h1 = __floats2half2_rn(w00*v00.z + w01*v01.z + w10*v10.z + w11*v11.z,
                                   w00*v00.w + w01*v01.w + w10*v10.w + w11*v11.w);
    __half2* dst = (__half2*)(g_u + (size_t)pix*C2 + CH + cg);
    dst[0] = h0; dst[1] = h1;
}

// ---------------- 10. fused LN stats + apply + residual + write-out ----------------
__global__ __launch_bounds__(256) void out_fused_kernel(
        const float* __restrict__ x1, const float* __restrict__ x2,
        const float* __restrict__ lg, const float* __restrict__ lb,
        float* __restrict__ out) {
    int xt = blockIdx.x;              // 0..3
    int y  = blockIdx.y;
    int n  = blockIdx.z % BATCH;
    int o  = blockIdx.z / BATCH;
    __shared__ float zsh[32][257];
    __shared__ float smu[32], srs[32];
    int tid = threadIdx.x;
    size_t rbase = (size_t)o*NPIX + (size_t)n*HH*WW + (size_t)y*WW + xt*32;
    #pragma unroll
    for (int j = 0; j < 4; j++) {
        int px = j*8 + (tid >> 5);
        int c = (tid & 31) * 8;
        const float* zr = g_z2 + (rbase + px)*CH + c;
        float4 a = *(const float4*)zr;
        float4 b = *(const float4*)(zr + 4);
        zsh[px][c+0] = a.x; zsh[px][c+1] = a.y; zsh[px][c+2] = a.z; zsh[px][c+3] = a.w;
        zsh[px][c+4] = b.x; zsh[px][c+5] = b.y; zsh[px][c+6] = b.z; zsh[px][c+7] = b.w;
    }
    __syncthreads();
    int w = tid >> 5, lane = tid & 31;
    #pragma unroll
    for (int i = 0; i < 4; i++) {
        int px = w*4 + i;
        float s = 0.f, sq = 0.f;
        #pragma unroll
        for (int k = 0; k < 8; k++) { float v = zsh[px][lane + k*32]; s += v; sq += v*v; }
        #pragma unroll
        for (int off = 16; off; off >>= 1) {
            s  += __shfl_xor_sync(0xffffffffu, s,  off);
            sq += __shfl_xor_sync(0xffffffffu, sq, off);
        }
        if (!lane) {
            float mu = s * (1.0f/CH);
            smu[px] = mu;
            srs[px] = rsqrtf(sq * (1.0f/CH) - mu*mu + EPSF);
        }
    }
    __syncthreads();
    const float* xs = o ? x2 : x1;
    int cth = tid >> 5, tx = tid & 31;
    float mu = smu[tx], rs = srs[tx];
    size_t xbase = ((size_t)(n*CH))*HH*WW + (size_t)y*WW + xt*32 + tx;
    float* outb = out + (size_t)o*NPIX*CH;
    #pragma unroll 8
    for (int cc = 0; cc < 32; cc++) {
        int c = cc*8 + cth;
        float val = lg[c]*(zsh[tx][c] - mu)*rs + lb[c];
        size_t gi = xbase + (size_t)c*HH*WW;
        outb[gi] = xs[gi] + val;
    }
}

// ---------------- launch ----------------
extern "C" void kernel_launch(void* const* d_in, const int* in_sizes, int n_in,
                              void* d_out, int out_size) {
    const float* x1     = (const float*)d_in[0];
    const float* x2     = (const float*)d_in[1];
    const float* qk_w   = (const float*)d_in[2];
    const float* qk_g   = (const float*)d_in[3];
    const float* qk_b   = (const float*)d_in[4];
    const float* qk_m   = (const float*)d_in[5];
    const float* qk_v   = (const float*)d_in[6];
    const float* v_w    = (const float*)d_in[7];
    const float* v_g    = (const float*)d_in[8];
    const float* v_b    = (const float*)d_in[9];
    const float* v_m    = (const float*)d_in[10];
    const float* v_v    = (const float*)d_in[11];
    const float* ln1_g  = (const float*)d_in[12];
    const float* ln1_b  = (const float*)d_in[13];
    const float* ln2_g  = (const float*)d_in[14];
    const float* ln2_b  = (const float*)d_in[15];
    const float* merge_w= (const float*)d_in[16];
    const float* mlp_w1 = (const float*)d_in[17];
    const float* mlp_w2 = (const float*)d_in[18];
    float* out = (float*)d_out;

    __half *pm, *pu, *pz1, *pmw, *pw1, *pw2;
    float *pmm, *pz2;
    cudaGetSymbolAddress((void**)&pm,  g_m);
    cudaGetSymbolAddress((void**)&pmm, g_mm);
    cudaGetSymbolAddress((void**)&pu,  g_u);
    cudaGetSymbolAddress((void**)&pz1, g_z1);
    cudaGetSymbolAddress((void**)&pz2, g_z2);
    cudaGetSymbolAddress((void**)&pmw, g_mwh);
    cudaGetSymbolAddress((void**)&pw1, g_w1h);
    cudaGetSymbolAddress((void**)&pw2, g_w2h);

    cudaFuncSetAttribute(hgemm_kernel, cudaFuncAttributeMaxDynamicSharedMemorySize, GEMM_SMEM);

    // weight fp16 prepass
    roundh_kernel<<<(CH*CH+255)/256, 256>>>(merge_w, pmw, CH*CH);
    roundh_kernel<<<(C2*C2+255)/256, 256>>>(mlp_w1, pw1, C2*C2);
    roundh_kernel<<<(CH*C2+255)/256, 256>>>(mlp_w2, pw2, CH*C2);

    // pooled + LN features
    pool_kernel<<<BATCH*CH, 1024>>>(x1, 0);
    pool_kernel<<<BATCH*CH, 1024>>>(x2, 1);
    lnc_kernel<<<BATCH*LL, 256>>>(0, ln1_g, ln1_b);
    lnc_kernel<<<BATCH*LL, 256>>>(1, ln1_g, ln1_b);

    // fused dwconv + BN -> heads
    dwbn2_kernel<<<dim3(CH/8, BATCH, 2), 256>>>(qk_w, qk_g, qk_b, qk_m, qk_v,
                                                v_w, v_g, v_b, v_m, v_v);

    // attention
    qk64_kernel<<<dim3(LL/64, LL/64, BATCH*NHEAD), 256>>>();
    rowstat2_kernel<<<BATCH*NHEAD*LL/256, 256>>>();
    m1_kernel<<<dim3(LL/128, BATCH*NHEAD), 256>>>();
    s2_kernel<<<(BATCH*LL*LL)/256, 256>>>();
    m2_kernel<<<dim3(LL/128, BATCH*NHEAD), 256>>>();

    // merge linear (both outputs in one GEMM) -> fp32 g_mm
    hgemm_kernel<<<dim3(CH/128, (2*BATCH*LL)/128), 256, GEMM_SMEM>>>(
        pm, pmw, pmm, 2*BATCH*LL, CH, CH, 0, 0);

    // build concat input U (fp16)
    xcopy_kernel<<<dim3((WW/32)*(CH/32), HH, 2*BATCH), dim3(32,32)>>>(x1, x2);
    upsample_kernel<<<NROWS/4, 256>>>();

    // MLP (fp16 tensor cores, ldmatrix fragments)
    hgemm_kernel<<<dim3(C2/128, NROWS/128), 256, GEMM_SMEM>>>(
        pu, pw1, pz1, NROWS, C2, C2, 1, 1);
    hgemm_kernel<<<dim3(CH/128, NROWS/128), 256, GEMM_SMEM>>>(
        pz1, pw2, pz2, NROWS, CH, C2, 0, 0);

    // fused LN + residual + write out
    out_fused_kernel<<<dim3(WW/32, HH, 2*BATCH), 256>>>(x1, x2, ln2_g, ln2_b, out);
}

// round 8
// speedup vs baseline: 5.6986x; 1.1638x over previous
#include <cuda_runtime.h>
#include <cuda_fp16.h>
#include <cstdint>

#define BATCH 4
#define CH 256
#define HH 128
#define WW 128
#define POOLW 4
#define HP 32
#define WP 32
#define LL 1024
#define NHEAD 8
#define DH 32
#define C2 512
#define NPIX (BATCH*HH*WW)      /* 65536 */
#define NROWS (2*NPIX)          /* 131072 */
#define EPSF 1e-5f
#define TSCALE 0.17677669529663687f
#define NEGINF (-3.402823466e38f)
#define NTILES 16               /* 1024/64 s-tiles per row */

// ---------------- scratch ----------------
__device__ float  g_p[2][BATCH*CH*LL];
__device__ float  g_q[2][(size_t)BATCH*LL*CH];
__device__ float  g_v[2][(size_t)BATCH*LL*CH];
__device__ __half g_qkh[(size_t)BATCH*NHEAD*LL*LL];   // fp16 logits, then S2 in place
__device__ float  g_pmax[(size_t)BATCH*NHEAD*LL*NTILES];
__device__ float  g_psum[(size_t)BATCH*NHEAD*LL*NTILES];
__device__ float  g_rmax[BATCH*NHEAD*LL];
__device__ float  g_rinv[BATCH*NHEAD*LL];
__device__ __half g_m[2][(size_t)BATCH*LL*CH];   // m1, m2 (half)
__device__ float  g_mm[2][(size_t)BATCH*LL*CH];  // merge output (fp32)
__device__ __half g_u[(size_t)NROWS*C2];         // MLP input (half)
__device__ __half g_z1[(size_t)NROWS*C2];        // relu(W1) (half)
__device__ float  g_z2[(size_t)NROWS*CH];
__device__ __half g_mwh[CH*CH];                  // half weights
__device__ __half g_w1h[C2*C2];
__device__ __half g_w2h[CH*C2];

// ================= helpers =================
__device__ __forceinline__ uint32_t smem_u32(const void* p) {
    uint32_t a;
    asm("{ .reg .u64 t; cvta.to.shared.u64 t, %1; cvt.u32.u64 %0, t; }" : "=r"(a) : "l"(p));
    return a;
}
#define CP_ASYNC16(dst, src) \
    asm volatile("cp.async.cg.shared.global [%0], [%1], 16;" :: "r"(dst), "l"(src) : "memory")
#define CP_COMMIT() asm volatile("cp.async.commit_group;" ::: "memory")
#define CP_WAIT(n)  asm volatile("cp.async.wait_group %0;" :: "n"(n) : "memory")
#define LDSM_X4(r0, r1, r2, r3, addr) \
    asm volatile("ldmatrix.sync.aligned.m8n8.x4.shared.b16 {%0,%1,%2,%3}, [%4];" \
        : "=r"(r0), "=r"(r1), "=r"(r2), "=r"(r3) : "r"(addr))

__device__ __forceinline__ void mma_f16(float* d, const uint32_t* a, uint32_t b0, uint32_t b1) {
    asm volatile(
        "mma.sync.aligned.m16n8k16.row.col.f32.f16.f16.f32 "
        "{%0,%1,%2,%3}, {%4,%5,%6,%7}, {%8,%9}, {%0,%1,%2,%3};"
        : "+f"(d[0]), "+f"(d[1]), "+f"(d[2]), "+f"(d[3])
        : "r"(a[0]), "r"(a[1]), "r"(a[2]), "r"(a[3]), "r"(b0), "r"(b1));
}

// ================= fp16 mma GEMM (unchanged from R7) =================
#define BKH 64
#define PADH 72
#define TILEH (128*PADH)
#define TILE_BYTES (TILEH*2)
#define STAGE_BYTES (2*TILE_BYTES)
#define GEMM_SMEM (3*STAGE_BYTES)

__global__ __launch_bounds__(256) void hgemm_kernel(
        const __half* __restrict__ A, const __half* __restrict__ Bw, void* __restrict__ C,
        int M, int N, int K, int relu, int outHalf) {
    extern __shared__ __half smh[];
    int tid = threadIdx.x, wid = tid >> 5, lane = tid & 31;
    int g = lane >> 2, t = lane & 3;
    int r = lane & 7, quad = lane >> 3;
    int wm = wid >> 1, wn = wid & 1;
    size_t am0 = (size_t)blockIdx.y * 128;
    size_t bn0 = (size_t)blockIdx.x * 128;
    uint32_t smembase = smem_u32(smh);

    uint32_t a_off[2], b_off[4];
    #pragma unroll
    for (int mt = 0; mt < 2; mt++)
        a_off[mt] = (uint32_t)(((wm*32 + mt*16 + (quad&1)*8 + r)*PADH + (quad>>1)*8) * 2);
    #pragma unroll
    for (int p = 0; p < 4; p++)
        b_off[p] = (uint32_t)(((wn*64 + p*16 + (quad>>1)*8 + r)*PADH + (quad&1)*8) * 2);

    int nchunk = K >> 6;
    float acc[2][8][4];
    #pragma unroll
    for (int mt = 0; mt < 2; mt++)
        #pragma unroll
        for (int nt = 0; nt < 8; nt++)
            #pragma unroll
            for (int i = 0; i < 4; i++) acc[mt][nt][i] = 0.f;

    auto issue = [&](int ch, int st) {
        const __half* Ag = A + am0 * K + ch*BKH;
        const __half* Bg = Bw + bn0 * K + ch*BKH;
        uint32_t base = smembase + st*STAGE_BYTES;
        #pragma unroll
        for (int j = 0; j < 4; j++) {
            int idx = tid + j * 256;
            int row = idx >> 3, seg = idx & 7;
            uint32_t d = (uint32_t)((row*PADH + seg*8) * 2);
            CP_ASYNC16(base + d,              Ag + (size_t)row*K + seg*8);
            CP_ASYNC16(base + TILE_BYTES + d, Bg + (size_t)row*K + seg*8);
        }
        CP_COMMIT();
    };

    issue(0, 0);
    if (nchunk > 1) issue(1, 1);

    for (int i = 0; i < nchunk; i++) {
        int s = i % 3;
        if (i + 2 < nchunk) { issue(i + 2, (i + 2) % 3); CP_WAIT(2); }
        else if (i + 1 < nchunk) { CP_WAIT(1); }
        else { CP_WAIT(0); }
        __syncthreads();

        uint32_t abase = smembase + s*STAGE_BYTES;
        uint32_t bbase = abase + TILE_BYTES;
        #pragma unroll
        for (int ks = 0; ks < 4; ks++) {
            uint32_t koff = (uint32_t)(ks * 32);
            uint32_t af[2][4];
            LDSM_X4(af[0][0], af[0][1], af[0][2], af[0][3], abase + a_off[0] + koff);
            LDSM_X4(af[1][0], af[1][1], af[1][2], af[1][3], abase + a_off[1] + koff);
            #pragma unroll
            for (int p = 0; p < 4; p++) {
                uint32_t b0, b1, b2, b3;
                LDSM_X4(b0, b1, b2, b3, bbase + b_off[p] + koff);
                mma_f16(acc[0][2*p],   af[0], b0, b1);
                mma_f16(acc[1][2*p],   af[1], b0, b1);
                mma_f16(acc[0][2*p+1], af[0], b2, b3);
                mma_f16(acc[1][2*p+1], af[1], b2, b3);
            }
        }
        __syncthreads();
    }

    #pragma unroll
    for (int mt = 0; mt < 2; mt++) {
        size_t row = am0 + wm*32 + mt*16 + g;
        #pragma unroll
        for (int nt = 0; nt < 8; nt++) {
            size_t col = bn0 + wn*64 + nt*8 + 2*t;
            float v0 = acc[mt][nt][0], v1 = acc[mt][nt][1];
            float v2 = acc[mt][nt][2], v3 = acc[mt][nt][3];
            if (relu) {
                v0 = fmaxf(v0,0.f); v1 = fmaxf(v1,0.f);
                v2 = fmaxf(v2,0.f); v3 = fmaxf(v3,0.f);
            }
            if (outHalf) {
                __half* Ch = (__half*)C;
                *(__half2*)(Ch + row*N + col)     = __floats2half2_rn(v0, v1);
                *(__half2*)(Ch + (row+8)*N + col) = __floats2half2_rn(v2, v3);
            } else {
                float* Cf = (float*)C;
                *(float2*)(Cf + row*N + col)     = make_float2(v0, v1);
                *(float2*)(Cf + (row+8)*N + col) = make_float2(v2, v3);
            }
        }
    }
}

// ---------------- merged weight fp16 prepass ----------------
__global__ void roundh3_kernel(const float* __restrict__ mw, const float* __restrict__ w1,
                               const float* __restrict__ w2,
                               __half* __restrict__ mwh, __half* __restrict__ w1h,
                               __half* __restrict__ w2h) {
    int i = blockIdx.x*256 + threadIdx.x;
    if (i < CH*CH) mwh[i] = __float2half_rn(mw[i]);
    if (i < C2*C2) w1h[i] = __float2half_rn(w1[i]);
    if (i < CH*C2) w2h[i] = __float2half_rn(w2[i]);
}

// ---------------- 1. fused maxpool4x4 + xcopy (read x once) ----------------
#define PUX_PITCH 516
#define PUX_SMEM (32*PUX_PITCH*4)
__global__ __launch_bounds__(256) void pux_kernel(const float* __restrict__ x1,
                                                  const float* __restrict__ x2) {
    extern __shared__ float sh[];   // [32][PUX_PITCH]
    int ct = blockIdx.x;            // channel tile 0..7
    int y4 = blockIdx.y;            // pooled row 0..31
    int n  = blockIdx.z & 3;
    int o  = blockIdx.z >> 2;
    const float* xs = o ? x2 : x1;
    int tid = threadIdx.x;
    int c0 = ct*32;
    // load 32 ch x 4 rows x 128 cols
    #pragma unroll
    for (int i = 0; i < 16; i++) {
        int f = tid + i*256;
        int cc = f >> 7, rem = f & 127;
        int yy = rem >> 5, c4 = rem & 31;
        float4 v = *(const float4*)(xs +
            (((size_t)(n*CH + c0+cc))*HH + y4*4+yy)*WW + c4*4);
        *(float4*)&sh[cc*PUX_PITCH + yy*128 + c4*4] = v;
    }
    __syncthreads();
    // pool: thread -> channel tid>>3, 4 outputs starting at (tid&7)*4
    {
        int c = tid >> 3, xo = (tid & 7)*4;
        float4 out;
        float* po = &out.x;
        #pragma unroll
        for (int k = 0; k < 4; k++) {
            int px = xo + k;
            float m = NEGINF;
            #pragma unroll
            for (int yy = 0; yy < 4; yy++) {
                float4 v = *(const float4*)&sh[c*PUX_PITCH + yy*128 + px*4];
                m = fmaxf(m, fmaxf(fmaxf(v.x, v.y), fmaxf(v.z, v.w)));
            }
            po[k] = m;
        }
        *(float4*)(g_p[o] + ((size_t)(n*CH + c0 + c))*LL + y4*32 + xo) = out;
    }
    // U write: 2 pixels per thread, 32 channels each (fp16)
    size_t rbase = (size_t)o*NPIX + (size_t)n*HH*WW + (size_t)(y4*4)*WW;
    #pragma unroll
    for (int j = 0; j < 2; j++) {
        int p = tid + j*256;           // pixel within 4x128 block
        __half2 hb[16];
        #pragma unroll
        for (int cc = 0; cc < 32; cc += 2)
            hb[cc>>1] = __floats2half2_rn(sh[cc*PUX_PITCH + p], sh[(cc+1)*PUX_PITCH + p]);
        uint4* dst = (uint4*)(g_u + (rbase + p)*C2 + c0);
        const uint4* src = (const uint4*)hb;
        dst[0] = src[0]; dst[1] = src[1]; dst[2] = src[2]; dst[3] = src[3];
    }
}

// ---------------- 2. LayerNorm over channels ----------------
__global__ void lnc_kernel(int o, const float* __restrict__ g, const float* __restrict__ b) {
    int sp = blockIdx.x % LL;
    int n  = blockIdx.x / LL;
    int c  = threadIdx.x;
    size_t idx = ((size_t)(n*CH + c))*LL + sp;
    float v = g_p[o][idx];
    __shared__ float ssum[256], ssq[256];
    ssum[c] = v; ssq[c] = v*v;
    __syncthreads();
    for (int off = 128; off; off >>= 1) {
        if (c < off) { ssum[c] += ssum[c+off]; ssq[c] += ssq[c+off]; }
        __syncthreads();
    }
    float mu  = ssum[0] * (1.0f/CH);
    float var = ssq[0] * (1.0f/CH) - mu*mu;
    float rr  = rsqrtf(var + EPSF);
    g_p[o][idx] = g[c]*(v-mu)*rr + b[c];
}

// ---------------- 3. fused dual-branch dwconv3x3 + BN ----------------
__global__ __launch_bounds__(256) void dwbn2_kernel(
        const float* __restrict__ qw, const float* __restrict__ qg, const float* __restrict__ qb,
        const float* __restrict__ qm, const float* __restrict__ qvv,
        const float* __restrict__ vw, const float* __restrict__ vg, const float* __restrict__ vb,
        const float* __restrict__ vm, const float* __restrict__ vvv) {
    int c0 = blockIdx.x * 8;
    int n  = blockIdx.y;
    int o  = blockIdx.z;
    __shared__ float sp[8*1028];
    int t = threadIdx.x;
    #pragma unroll
    for (int cc = 0; cc < 8; cc++)
        #pragma unroll
        for (int it = 0; it < 4; it++) {
            int spi = t + it*256;
            sp[cc*1028 + spi] = g_p[o][((size_t)(n*CH + c0+cc))*LL + spi];
        }
    __syncthreads();

    int cc = t & 7, jq = t >> 3;
    int c = c0 + cc;
    float wq[9], wv[9];
    #pragma unroll
    for (int k = 0; k < 9; k++) { wq[k] = qw[c*9+k]; wv[k] = vw[c*9+k]; }
    float scq = qg[c]*rsqrtf(qvv[c]+EPSF), bq = qb[c] - scq*qm[c];
    float scv = vg[c]*rsqrtf(vvv[c]+EPSF), bv = vb[c] - scv*vm[c];
    const float* s = sp + cc*1028;
    float* oq = g_q[o] + (size_t)(n*LL)*CH + c;
    float* ov = g_v[o] + (size_t)(n*LL)*CH + c;

    for (int i = 0; i < 32; i++) {
        float aq = 0.f, av = 0.f;
        #pragma unroll
        for (int di = 0; di < 3; di++) {
            int ii = i + di - 1;
            if (ii < 0 || ii >= HP) continue;
            #pragma unroll
            for (int dj = 0; dj < 3; dj++) {
                int jj = jq + dj - 1;
                if (jj < 0 || jj >= WP) continue;
                float x = s[ii*32 + jj];
                aq += wq[di*3+dj]*x;
                av += wv[di*3+dj]*x;
            }
        }
        int l = i*32 + jq;
        oq[(size_t)l*CH] = scq*aq + bq;
        ov[(size_t)l*CH] = scv*av + bv;
    }
}

// ---------------- 4. QK 64x64 tile -> fp16 logits + per-tile partials ----------------
__global__ __launch_bounds__(256) void qk64_kernel() {
    int n = blockIdx.z >> 3, h = blockIdx.z & 7;
    int l0 = blockIdx.y*64, s0 = blockIdx.x*64;
    __shared__ float As[32][68], Bs[32][68];
    int t = threadIdx.x;
    const float* Aq = g_q[0] + ((size_t)(n*LL + l0))*CH + h*DH;
    const float* Bq = g_q[1] + ((size_t)(n*LL + s0))*CH + h*DH;
    #pragma unroll
    for (int i = 0; i < 2; i++) {
        int id = t + i*256;
        int row = id >> 3, seg = id & 7;
        float4 a4 = *(const float4*)(Aq + (size_t)row*CH + seg*4);
        float4 b4 = *(const float4*)(Bq + (size_t)row*CH + seg*4);
        As[seg*4+0][row]=a4.x; As[seg*4+1][row]=a4.y; As[seg*4+2][row]=a4.z; As[seg*4+3][row]=a4.w;
        Bs[seg*4+0][row]=b4.x; Bs[seg*4+1][row]=b4.y; Bs[seg*4+2][row]=b4.z; Bs[seg*4+3][row]=b4.w;
    }
    __syncthreads();
    int tx = t & 15, ty = t >> 4;
    float acc[4][4] = {};
    #pragma unroll
    for (int k = 0; k < 32; k++) {
        float4 av = *(const float4*)&As[k][ty*4];
        float4 bv = *(const float4*)&Bs[k][tx*4];
        acc[0][0]+=av.x*bv.x; acc[0][1]+=av.x*bv.y; acc[0][2]+=av.x*bv.z; acc[0][3]+=av.x*bv.w;
        acc[1][0]+=av.y*bv.x; acc[1][1]+=av.y*bv.y; acc[1][2]+=av.y*bv.z; acc[1][3]+=av.y*bv.w;
        acc[2][0]+=av.z*bv.x; acc[2][1]+=av.z*bv.y; acc[2][2]+=av.z*bv.z; acc[2][3]+=av.z*bv.w;
        acc[3][0]+=av.w*bv.x; acc[3][1]+=av.w*bv.y; acc[3][2]+=av.w*bv.z; acc[3][3]+=av.w*bv.w;
    }
    size_t rowbase = ((size_t)(n*NHEAD + h))*LL + l0 + ty*4;
    int tile = s0 >> 6;
    #pragma unroll
    for (int i = 0; i < 4; i++) {
        float v0 = TSCALE*acc[i][0], v1 = TSCALE*acc[i][1];
        float v2 = TSCALE*acc[i][2], v3 = TSCALE*acc[i][3];
        __half2* Cb2 = (__half2*)(g_qkh + (rowbase + i)*LL + s0 + tx*4);
        Cb2[0] = __floats2half2_rn(v0, v1);
        Cb2[1] = __floats2half2_rn(v2, v3);
        float mx = fmaxf(fmaxf(v0, v1), fmaxf(v2, v3));
        #pragma unroll
        for (int off = 8; off; off >>= 1)
            mx = fmaxf(mx, __shfl_xor_sync(0xffffffffu, mx, off));
        float sm = __expf(v0-mx) + __expf(v1-mx) + __expf(v2-mx) + __expf(v3-mx);
        #pragma unroll
        for (int off = 8; off; off >>= 1)
            sm += __shfl_xor_sync(0xffffffffu, sm, off);
        if (tx == 0) {
            g_pmax[(rowbase + i)*NTILES + tile] = mx;
            g_psum[(rowbase + i)*NTILES + tile] = sm;
        }
    }
}

// ---------------- 5. combine tile partials ----------------
__global__ void rowstat2_kernel() {
    int r = blockIdx.x*256 + threadIdx.x;
    float pm[NTILES];
    float m = NEGINF;
    #pragma unroll
    for (int i = 0; i < NTILES; i++) {
        pm[i] = g_pmax[(size_t)r*NTILES + i];
        m = fmaxf(m, pm[i]);
    }
    float sum = 0.f;
    #pragma unroll
    for (int i = 0; i < NTILES; i++)
        sum += g_psum[(size_t)r*NTILES + i] * __expf(pm[i] - m);
    g_rmax[r] = m;
    g_rinv[r] = 1.f/sum;
}

// ---------------- 6. m1 = S1 @ v2h (fp16 logits in) ----------------
__global__ __launch_bounds__(256) void m1_kernel() {
    int n = blockIdx.y >> 3, h = blockIdx.y & 7;
    int l0 = blockIdx.x * 128;
    __shared__ float Ps[32][132], Vs[32][36], mxs[128], ris[128];
    int t = threadIdx.x;
    int rbase = (n*NHEAD + h)*LL + l0;
    if (t < 128) { mxs[t] = g_rmax[rbase + t]; ris[t] = g_rinv[rbase + t]; }
    __syncthreads();
    int tx = t & 7, ty = t >> 3;
    float acc[4][4] = {};
    for (int st = 0; st < LL; st += 32) {
        #pragma unroll
        for (int i = 0; i < 4; i++) {
            int id = t + i*256;
            int lrow = id >> 3, sseg = id & 7;
            uint2 raw = *(const uint2*)(g_qkh + ((size_t)(rbase + lrow))*LL + st + sseg*4);
            float2 f01 = __half22float2(*(__half2*)&raw.x);
            float2 f23 = __half22float2(*(__half2*)&raw.y);
            float mx = mxs[lrow], ri = ris[lrow];
            Ps[sseg*4+0][lrow] = __expf(f01.x - mx)*ri;
            Ps[sseg*4+1][lrow] = __expf(f01.y - mx)*ri;
            Ps[sseg*4+2][lrow] = __expf(f23.x - mx)*ri;
            Ps[sseg*4+3][lrow] = __expf(f23.y - mx)*ri;
        }
        {
            int srow = t >> 3, dseg = t & 7;
            *(float4*)&Vs[srow][dseg*4] =
                *(const float4*)(g_v[1] + ((size_t)(n*LL + st + srow))*CH + h*DH + dseg*4);
        }
        __syncthreads();
        #pragma unroll
        for (int k = 0; k < 32; k++) {
            float4 av = *(const float4*)&Ps[k][ty*4];
            float4 bv = *(const float4*)&Vs[k][tx*4];
            acc[0][0]+=av.x*bv.x; acc[0][1]+=av.x*bv.y; acc[0][2]+=av.x*bv.z; acc[0][3]+=av.x*bv.w;
            acc[1][0]+=av.y*bv.x; acc[1][1]+=av.y*bv.y; acc[1][2]+=av.y*bv.z; acc[1][3]+=av.y*bv.w;
            acc[2][0]+=av.z*bv.x; acc[2][1]+=av.z*bv.y; acc[2][2]+=av.z*bv.z; acc[2][3]+=av.z*bv.w;
            acc[3][0]+=av.w*bv.x; acc[3][1]+=av.w*bv.y; acc[3][2]+=av.w*bv.z; acc[3][3]+=av.w*bv.w;
        }
        __syncthreads();
    }
    #pragma unroll
    for (int i = 0; i < 4; i++) {
        int l = l0 + ty*4 + i;
        __half2* dst = (__half2*)(g_m[0] + ((size_t)(n*LL + l))*CH + h*DH + tx*4);
        dst[0] = __floats2half2_rn(acc[i][0], acc[i][1]);
        dst[1] = __floats2half2_rn(acc[i][2], acc[i][3]);
    }
}

// ---------------- 7. S2 = softmax over heads (fp16 in/out) ----------------
__global__ void s2_kernel() {
    size_t idx = (size_t)blockIdx.x*blockDim.x + threadIdx.x;
    int s = (int)(idx % LL);
    int l = (int)((idx / LL) % LL);
    int n = (int)(idx / ((size_t)LL*LL));
    float v[NHEAD];
    float mx = NEGINF;
    #pragma unroll
    for (int h = 0; h < NHEAD; h++) {
        v[h] = __half2float(g_qkh[(((size_t)(n*NHEAD + h))*LL + l)*LL + s]);
        mx = fmaxf(mx, v[h]);
    }
    float sm = 0.f;
    #pragma unroll
    for (int h = 0; h < NHEAD; h++) { v[h] = __expf(v[h]-mx); sm += v[h]; }
    float ri = 1.f/sm;
    #pragma unroll
    for (int h = 0; h < NHEAD; h++)
        g_qkh[(((size_t)(n*NHEAD + h))*LL + l)*LL + s] = __float2half_rn(v[h]*ri);
}

// ---------------- 8. m2 = S2^T @ v1h (fp16 S2 in) ----------------
__global__ __launch_bounds__(256) void m2_kernel() {
    int n = blockIdx.y >> 3, h = blockIdx.y & 7;
    int s0 = blockIdx.x * 128;
    __shared__ float As[32][132], Vs[32][36];
    int t = threadIdx.x;
    size_t qbase = ((size_t)(n*NHEAD + h))*LL;
    int tx = t & 7, ty = t >> 3;
    float acc[4][4] = {};
    for (int lt = 0; lt < LL; lt += 32) {
        #pragma unroll
        for (int i = 0; i < 4; i++) {
            int id = t + i*256;
            int lrow = id >> 5, sseg = id & 31;
            uint2 raw = *(const uint2*)(g_qkh + (qbase + lt + lrow)*LL + s0 + sseg*4);
            float2 f01 = __half22float2(*(__half2*)&raw.x);
            float2 f23 = __half22float2(*(__half2*)&raw.y);
            As[lrow][sseg*4+0] = f01.x; As[lrow][sseg*4+1] = f01.y;
            As[lrow][sseg*4+2] = f23.x; As[lrow][sseg*4+3] = f23.y;
        }
        {
            int srow = t >> 3, dseg = t & 7;
            *(float4*)&Vs[srow][dseg*4] =
                *(const float4*)(g_v[0] + ((size_t)(n*LL + lt + srow))*CH + h*DH + dseg*4);
        }
        __syncthreads();
        #pragma unroll
        for (int k = 0; k < 32; k++) {
            float4 av = *(const float4*)&As[k][ty*4];
            float4 bv = *(const float4*)&Vs[k][tx*4];
            acc[0][0]+=av.x*bv.x; acc[0][1]+=av.x*bv.y; acc[0][2]+=av.x*bv.z; acc[0][3]+=av.x*bv.w;
            acc[1][0]+=av.y*bv.x; acc[1][1]+=av.y*bv.y; acc[1][2]+=av.y*bv.z; acc[1][3]+=av.y*bv.w;
            acc[2][0]+=av.z*bv.x; acc[2][1]+=av.z*bv.y; acc[2][2]+=av.z*bv.z; acc[2][3]+=av.z*bv.w;
            acc[3][0]+=av.w*bv.x; acc[3][1]+=av.w*bv.y; acc[3][2]+=av.w*bv.z; acc[3][3]+=av.w*bv.w;
        }
        __syncthreads();
    }
    #pragma unroll
    for (int i = 0; i < 4; i++) {
        int s = s0 + ty*4 + i;
        __half2* dst = (__half2*)(g_m[1] + ((size_t)(n*LL + s))*CH + h*DH + tx*4);
        dst[0] = __floats2half2_rn(acc[i][0], acc[i][1]);
        dst[1] = __floats2half2_rn(acc[i][2], acc[i][3]);
    }
}

// ---------------- 9. bilinear x4 upsample into U[:, 256:512] (fp16) ----------------
__global__ void upsample_kernel() {
    int tid = threadIdx.x;
    int pix = blockIdx.x*4 + (tid >> 6);
    int cg = (tid & 63) * 4;
    int x = pix % WW;
    int y = (pix / WW) % HH;
    int n = (pix / (WW*HH)) % BATCH;
    int o =  pix / (WW*HH*BATCH);
    float sy = (y + 0.5f)*0.25f - 0.5f;
    float sx = (x + 0.5f)*0.25f - 0.5f;
    int y0 = (int)floorf(sy), x0 = (int)floorf(sx);
    float fy = sy - (float)y0, fx = sx - (float)x0;
    int y0c = min(max(y0, 0), HP-1), y1c = min(max(y0+1, 0), HP-1);
    int x0c = min(max(x0, 0), WP-1), x1c = min(max(x0+1, 0), WP-1);
    const float* mm = g_mm[o] + (size_t)n*LL*CH;
    float4 v00 = *(const float4*)(mm + (size_t)(y0c*WP + x0c)*CH + cg);
    float4 v01 = *(const float4*)(mm + (size_t)(y0c*WP + x1c)*CH + cg);
    float4 v10 = *(const float4*)(mm + (size_t)(y1c*WP + x0c)*CH + cg);
    float4 v11 = *(const float4*)(mm + (size_t)(y1c*WP + x1c)*CH + cg);
    float w00 = (1.f-fy)*(1.f-fx), w01 = (1.f-fy)*fx, w10 = fy*(1.f-fx), w11 = fy*fx;
    __half2 h0 = __floats2half2_rn(w00*v00.x + w01*v01.x + w10*v10.x + w11*v11.x,
                                   w00*v00.y + w01*v01.y + w10*v10.y + w11*v11.y);
    __half2 h1 = __floats2half2_rn(w00*v00.z + w01*v01.z + w10*v10.z + w11*v11.z,
                                   w00*v00.w + w01*v01.w + w10*v10.w + w11*v11.w);
    __half2* dst = (__half2*)(g_u + (size_t)pix*C2 + CH + cg);
    dst[0] = h0; dst[1] = h1;
}

// ---------------- 10. fused LN stats + apply + residual + write-out ----------------
__global__ __launch_bounds__(256) void out_fused_kernel(
        const float* __restrict__ x1, const float* __restrict__ x2,
        const float* __restrict__ lg, const float* __restrict__ lb,
        float* __restrict__ out) {
    int xt = blockIdx.x;
    int y  = blockIdx.y;
    int n  = blockIdx.z % BATCH;
    int o  = blockIdx.z / BATCH;
    __shared__ float zsh[32][257];
    __shared__ float smu[32], srs[32];
    int tid = threadIdx.x;
    size_t rbase = (size_t)o*NPIX + (size_t)n*HH*WW + (size_t)y*WW + xt*32;
    #pragma unroll
    for (int j = 0; j < 4; j++) {
        int px = j*8 + (tid >> 5);
        int c = (tid & 31) * 8;
        const float* zr = g_z2 + (rbase + px)*CH + c;
        float4 a = *(const float4*)zr;
        float4 b = *(const float4*)(zr + 4);
        zsh[px][c+0] = a.x; zsh[px][c+1] = a.y; zsh[px][c+2] = a.z; zsh[px][c+3] = a.w;
        zsh[px][c+4] = b.x; zsh[px][c+5] = b.y; zsh[px][c+6] = b.z; zsh[px][c+7] = b.w;
    }
    __syncthreads();
    int w = tid >> 5, lane = tid & 31;
    #pragma unroll
    for (int i = 0; i < 4; i++) {
        int px = w*4 + i;
        float s = 0.f, sq = 0.f;
        #pragma unroll
        for (int k = 0; k < 8; k++) { float v = zsh[px][lane + k*32]; s += v; sq += v*v; }
        #pragma unroll
        for (int off = 16; off; off >>= 1) {
            s  += __shfl_xor_sync(0xffffffffu, s,  off);
            sq += __shfl_xor_sync(0xffffffffu, sq, off);
        }
        if (!lane) {
            float mu = s * (1.0f/CH);
            smu[px] = mu;
            srs[px] = rsqrtf(sq * (1.0f/CH) - mu*mu + EPSF);
        }
    }
    __syncthreads();
    const float* xs = o ? x2 : x1;
    int cth = tid >> 5, tx = tid & 31;
    float mu = smu[tx], rs = srs[tx];
    size_t xbase = ((size_t)(n*CH))*HH*WW + (size_t)y*WW + xt*32 + tx;
    float* outb = out + (size_t)o*NPIX*CH;
    #pragma unroll 8
    for (int cc = 0; cc < 32; cc++) {
        int c = cc*8 + cth;
        float val = lg[c]*(zsh[tx][c] - mu)*rs + lb[c];
        size_t gi = xbase + (size_t)c*HH*WW;
        outb[gi] = xs[gi] + val;
    }
}

// ---------------- launch ----------------
extern "C" void kernel_launch(void* const* d_in, const int* in_sizes, int n_in,
                              void* d_out, int out_size) {
    const float* x1     = (const float*)d_in[0];
    const float* x2     = (const float*)d_in[1];
    const float* qk_w   = (const float*)d_in[2];
    const float* qk_g   = (const float*)d_in[3];
    const float* qk_b   = (const float*)d_in[4];
    const float* qk_m   = (const float*)d_in[5];
    const float* qk_v   = (const float*)d_in[6];
    const float* v_w    = (const float*)d_in[7];
    const float* v_g    = (const float*)d_in[8];
    const float* v_b    = (const float*)d_in[9];
    const float* v_m    = (const float*)d_in[10];
    const float* v_v    = (const float*)d_in[11];
    const float* ln1_g  = (const float*)d_in[12];
    const float* ln1_b  = (const float*)d_in[13];
    const float* ln2_g  = (const float*)d_in[14];
    const float* ln2_b  = (const float*)d_in[15];
    const float* merge_w= (const float*)d_in[16];
    const float* mlp_w1 = (const float*)d_in[17];
    const float* mlp_w2 = (const float*)d_in[18];
    float* out = (float*)d_out;

    __half *pm, *pu, *pz1, *pmw, *pw1, *pw2;
    float *pmm, *pz2;
    cudaGetSymbolAddress((void**)&pm,  g_m);
    cudaGetSymbolAddress((void**)&pmm, g_mm);
    cudaGetSymbolAddress((void**)&pu,  g_u);
    cudaGetSymbolAddress((void**)&pz1, g_z1);
    cudaGetSymbolAddress((void**)&pz2, g_z2);
    cudaGetSymbolAddress((void**)&pmw, g_mwh);
    cudaGetSymbolAddress((void**)&pw1, g_w1h);
    cudaGetSymbolAddress((void**)&pw2, g_w2h);

    cudaFuncSetAttribute(hgemm_kernel, cudaFuncAttributeMaxDynamicSharedMemorySize, GEMM_SMEM);
    cudaFuncSetAttribute(pux_kernel,   cudaFuncAttributeMaxDynamicSharedMemorySize, PUX_SMEM);

    // weight fp16 prepass (merged)
    roundh3_kernel<<<(C2*C2+255)/256, 256>>>(merge_w, mlp_w1, mlp_w2, pmw, pw1, pw2);

    // fused maxpool + U-left copy (x read once)
    pux_kernel<<<dim3(CH/32, HP, 2*BATCH), 256, PUX_SMEM>>>(x1, x2);

    // LN over channels
    lnc_kernel<<<BATCH*LL, 256>>>(0, ln1_g, ln1_b);
    lnc_kernel<<<BATCH*LL, 256>>>(1, ln1_g, ln1_b);

    // fused dwconv + BN -> heads
    dwbn2_kernel<<<dim3(CH/8, BATCH, 2), 256>>>(qk_w, qk_g, qk_b, qk_m, qk_v,
                                                v_w, v_g, v_b, v_m, v_v);

    // attention (fp16 logits)
    qk64_kernel<<<dim3(LL/64, LL/64, BATCH*NHEAD), 256>>>();
    rowstat2_kernel<<<BATCH*NHEAD*LL/256, 256>>>();
    m1_kernel<<<dim3(LL/128, BATCH*NHEAD), 256>>>();
    s2_kernel<<<(BATCH*LL*LL)/256, 256>>>();
    m2_kernel<<<dim3(LL/128, BATCH*NHEAD), 256>>>();

    // merge linear (both outputs in one GEMM) -> fp32 g_mm
    hgemm_kernel<<<dim3(CH/128, (2*BATCH*LL)/128), 256, GEMM_SMEM>>>(
        pm, pmw, pmm, 2*BATCH*LL, CH, CH, 0, 0);

    // upsample into U right half
    upsample_kernel<<<NROWS/4, 256>>>();

    // MLP (fp16 tensor cores)
    hgemm_kernel<<<dim3(C2/128, NROWS/128), 256, GEMM_SMEM>>>(
        pu, pw1, pz1, NROWS, C2, C2, 1, 1);
    hgemm_kernel<<<dim3(CH/128, NROWS/128), 256, GEMM_SMEM>>>(
        pz1, pw2, pz2, NROWS, CH, C2, 0, 0);

    // fused LN + residual + write out
    out_fused_kernel<<<dim3(WW/32, HH, 2*BATCH), 256>>>(x1, x2, ln2_g, ln2_b, out);
}

// round 10
// speedup vs baseline: 6.2977x; 1.1051x over previous
#include <cuda_runtime.h>
#include <cuda_fp16.h>
#include <cstdint>

#define BATCH 4
#define CH 256
#define HH 128
#define WW 128
#define HP 32
#define WP 32
#define LL 1024
#define NHEAD 8
#define DH 32
#define C2 512
#define NPIX (BATCH*HH*WW)
#define NROWS (2*NPIX)
#define EPSF 1e-5f
#define TSCALE 0.17677669529663687f
#define NEGINF (-3.402823466e38f)
#define NTILES 16

// ---------------- scratch ----------------
__device__ float  g_p[2][BATCH*CH*LL];                 // raw pooled
__device__ float  g_lnps[2*BATCH*8*LL];                // LN partial sums (8 c-tiles)
__device__ float  g_lnpq[2*BATCH*8*LL];                // LN partial sumsq
__device__ float  g_mu1[2*BATCH*LL];
__device__ float  g_rs1[2*BATCH*LL];
__device__ __half g_qh[2][(size_t)BATCH*LL*CH];        // q/k heads fp16
__device__ float  g_v[2][(size_t)BATCH*LL*CH];         // v heads fp32
__device__ __half g_qkh[(size_t)BATCH*NHEAD*LL*LL];    // fp16 logits, then S2
__device__ float  g_pmax[(size_t)BATCH*NHEAD*LL*NTILES];
__device__ float  g_psum[(size_t)BATCH*NHEAD*LL*NTILES];
__device__ float  g_rmax[BATCH*NHEAD*LL];
__device__ float  g_rinv[BATCH*NHEAD*LL];
__device__ __half g_m[2][(size_t)BATCH*LL*CH];
__device__ float  g_mm[2][(size_t)BATCH*LL*CH];
__device__ __half g_u[(size_t)NROWS*C2];
__device__ __half g_z1[(size_t)NROWS*C2];
__device__ float  g_z2[(size_t)NROWS*CH];
__device__ __half g_mwh[CH*CH];
__device__ __half g_w1h[C2*C2];
__device__ __half g_w2h[CH*C2];

// ================= helpers =================
__device__ __forceinline__ uint32_t smem_u32(const void* p) {
    uint32_t a;
    asm("{ .reg .u64 t; cvta.to.shared.u64 t, %1; cvt.u32.u64 %0, t; }" : "=r"(a) : "l"(p));
    return a;
}
#define CP_ASYNC16(dst, src) \
    asm volatile("cp.async.cg.shared.global [%0], [%1], 16;" :: "r"(dst), "l"(src) : "memory")
#define CP_COMMIT() asm volatile("cp.async.commit_group;" ::: "memory")
#define CP_WAIT(n)  asm volatile("cp.async.wait_group %0;" :: "n"(n) : "memory")
#define LDSM_X4(r0, r1, r2, r3, addr) \
    asm volatile("ldmatrix.sync.aligned.m8n8.x4.shared.b16 {%0,%1,%2,%3}, [%4];" \
        : "=r"(r0), "=r"(r1), "=r"(r2), "=r"(r3) : "r"(addr))

__device__ __forceinline__ void mma_f16(float* d, const uint32_t* a, uint32_t b0, uint32_t b1) {
    asm volatile(
        "mma.sync.aligned.m16n8k16.row.col.f32.f16.f16.f32 "
        "{%0,%1,%2,%3}, {%4,%5,%6,%7}, {%8,%9}, {%0,%1,%2,%3};"
        : "+f"(d[0]), "+f"(d[1]), "+f"(d[2]), "+f"(d[3])
        : "r"(a[0]), "r"(a[1]), "r"(a[2]), "r"(a[3]), "r"(b0), "r"(b1));
}

// ================= fp16 mma GEMM (validated R7 version) =================
#define BKH 64
#define PADH 72
#define TILEH (128*PADH)
#define TILE_BYTES (TILEH*2)
#define STAGE_BYTES (2*TILE_BYTES)
#define GEMM_SMEM (3*STAGE_BYTES)

__global__ __launch_bounds__(256) void hgemm_kernel(
        const __half* __restrict__ A, const __half* __restrict__ Bw, void* __restrict__ C,
        int M, int N, int K, int relu, int outHalf) {
    extern __shared__ __half smh[];
    int tid = threadIdx.x, wid = tid >> 5, lane = tid & 31;
    int g = lane >> 2, t = lane & 3;
    int r = lane & 7, quad = lane >> 3;
    int wm = wid >> 1, wn = wid & 1;
    size_t am0 = (size_t)blockIdx.y * 128;
    size_t bn0 = (size_t)blockIdx.x * 128;
    uint32_t smembase = smem_u32(smh);

    uint32_t a_off[2], b_off[4];
    #pragma unroll
    for (int mt = 0; mt < 2; mt++)
        a_off[mt] = (uint32_t)(((wm*32 + mt*16 + (quad&1)*8 + r)*PADH + (quad>>1)*8) * 2);
    #pragma unroll
    for (int p = 0; p < 4; p++)
        b_off[p] = (uint32_t)(((wn*64 + p*16 + (quad>>1)*8 + r)*PADH + (quad&1)*8) * 2);

    int nchunk = K >> 6;
    float acc[2][8][4];
    #pragma unroll
    for (int mt = 0; mt < 2; mt++)
        #pragma unroll
        for (int nt = 0; nt < 8; nt++)
            #pragma unroll
            for (int i = 0; i < 4; i++) acc[mt][nt][i] = 0.f;

    auto issue = [&](int ch, int st) {
        const __half* Ag = A + am0 * K + ch*BKH;
        const __half* Bg = Bw + bn0 * K + ch*BKH;
        uint32_t base = smembase + st*STAGE_BYTES;
        #pragma unroll
        for (int j = 0; j < 4; j++) {
            int idx = tid + j * 256;
            int row = idx >> 3, seg = idx & 7;
            uint32_t d = (uint32_t)((row*PADH + seg*8) * 2);
            CP_ASYNC16(base + d,              Ag + (size_t)row*K + seg*8);
            CP_ASYNC16(base + TILE_BYTES + d, Bg + (size_t)row*K + seg*8);
        }
        CP_COMMIT();
    };

    issue(0, 0);
    if (nchunk > 1) issue(1, 1);

    for (int i = 0; i < nchunk; i++) {
        int s = i % 3;
        if (i + 2 < nchunk) { issue(i + 2, (i + 2) % 3); CP_WAIT(2); }
        else if (i + 1 < nchunk) { CP_WAIT(1); }
        else { CP_WAIT(0); }
        __syncthreads();

        uint32_t abase = smembase + s*STAGE_BYTES;
        uint32_t bbase = abase + TILE_BYTES;
        #pragma unroll
        for (int ks = 0; ks < 4; ks++) {
            uint32_t koff = (uint32_t)(ks * 32);
            uint32_t af[2][4];
            LDSM_X4(af[0][0], af[0][1], af[0][2], af[0][3], abase + a_off[0] + koff);
            LDSM_X4(af[1][0], af[1][1], af[1][2], af[1][3], abase + a_off[1] + koff);
            #pragma unroll
            for (int p = 0; p < 4; p++) {
                uint32_t b0, b1, b2, b3;
                LDSM_X4(b0, b1, b2, b3, bbase + b_off[p] + koff);
                mma_f16(acc[0][2*p],   af[0], b0, b1);
                mma_f16(acc[1][2*p],   af[1], b0, b1);
                mma_f16(acc[0][2*p+1], af[0], b2, b3);
                mma_f16(acc[1][2*p+1], af[1], b2, b3);
            }
        }
        __syncthreads();
    }

    #pragma unroll
    for (int mt = 0; mt < 2; mt++) {
        size_t row = am0 + wm*32 + mt*16 + g;
        #pragma unroll
        for (int nt = 0; nt < 8; nt++) {
            size_t col = bn0 + wn*64 + nt*8 + 2*t;
            float v0 = acc[mt][nt][0], v1 = acc[mt][nt][1];
            float v2 = acc[mt][nt][2], v3 = acc[mt][nt][3];
            if (relu) {
                v0 = fmaxf(v0,0.f); v1 = fmaxf(v1,0.f);
                v2 = fmaxf(v2,0.f); v3 = fmaxf(v3,0.f);
            }
            if (outHalf) {
                __half* Ch = (__half*)C;
                *(__half2*)(Ch + row*N + col)     = __floats2half2_rn(v0, v1);
                *(__half2*)(Ch + (row+8)*N + col) = __floats2half2_rn(v2, v3);
            } else {
                float* Cf = (float*)C;
                *(float2*)(Cf + row*N + col)     = make_float2(v0, v1);
                *(float2*)(Cf + (row+8)*N + col) = make_float2(v2, v3);
            }
        }
    }
}

// ================= QK tensor-core GEMM: logits + softmax partials =================
#define PADQ 40
__global__ __launch_bounds__(256) void qkmma_kernel() {
    __shared__ __half qs[2][128*PADQ];
    int tid = threadIdx.x, wid = tid >> 5, lane = tid & 31;
    int g = lane >> 2, t = lane & 3;
    int r = lane & 7, quad = lane >> 3;
    int wm = wid >> 1, wn = wid & 1;
    int n = blockIdx.z >> 3, h = blockIdx.z & 7;
    int l0 = blockIdx.y * 128, s0 = blockIdx.x * 128;
    uint32_t abase = smem_u32(qs[0]);
    uint32_t bbase = smem_u32(qs[1]);

    // load A (query rows) and B (key rows): 128 rows x 32 halfs (4 x 16B segs) each
    #pragma unroll
    for (int j = 0; j < 2; j++) {
        int idx = tid + j*256;
        int row = idx >> 2, seg = idx & 3;
        uint32_t d = (uint32_t)((row*PADQ + seg*8) * 2);
        const __half* Aq = g_qh[0] + ((size_t)(n*LL + l0 + row))*CH + h*DH + seg*8;
        const __half* Bq = g_qh[1] + ((size_t)(n*LL + s0 + row))*CH + h*DH + seg*8;
        CP_ASYNC16(abase + d, Aq);
        CP_ASYNC16(bbase + d, Bq);
    }
    CP_COMMIT();
    CP_WAIT(0);
    __syncthreads();

    uint32_t a_off[2], b_off[4];
    #pragma unroll
    for (int mt = 0; mt < 2; mt++)
        a_off[mt] = (uint32_t)(((wm*32 + mt*16 + (quad&1)*8 + r)*PADQ + (quad>>1)*8) * 2);
    #pragma unroll
    for (int p = 0; p < 4; p++)
        b_off[p] = (uint32_t)(((wn*64 + p*16 + (quad>>1)*8 + r)*PADQ + (quad&1)*8) * 2);

    float acc[2][8][4];
    #pragma unroll
    for (int mt = 0; mt < 2; mt++)
        #pragma unroll
        for (int nt = 0; nt < 8; nt++)
            #pragma unroll
            for (int i = 0; i < 4; i++) acc[mt][nt][i] = 0.f;

    #pragma unroll
    for (int ks = 0; ks < 2; ks++) {
        uint32_t koff = (uint32_t)(ks * 32);
        uint32_t af[2][4];
        LDSM_X4(af[0][0], af[0][1], af[0][2], af[0][3], abase + a_off[0] + koff);
        LDSM_X4(af[1][0], af[1][1], af[1][2], af[1][3], abase + a_off[1] + koff);
        #pragma unroll
        for (int p = 0; p < 4; p++) {
            uint32_t b0, b1, b2, b3;
            LDSM_X4(b0, b1, b2, b3, bbase + b_off[p] + koff);
            mma_f16(acc[0][2*p],   af[0], b0, b1);
            mma_f16(acc[1][2*p],   af[1], b0, b1);
            mma_f16(acc[0][2*p+1], af[0], b2, b3);
            mma_f16(acc[1][2*p+1], af[1], b2, b3);
        }
    }

    // epilogue: scale, fp16 store, per-64col-tile row stats
    size_t qkbase = ((size_t)(n*NHEAD + h))*LL;
    int tile = blockIdx.x*2 + wn;
    #pragma unroll
    for (int mt = 0; mt < 2; mt++) {
        int row0 = l0 + wm*32 + mt*16 + g;
        float mx0 = NEGINF, mx1 = NEGINF;
        float vals[8][4];
        #pragma unroll
        for (int nt = 0; nt < 8; nt++) {
            #pragma unroll
            for (int i = 0; i < 4; i++) vals[nt][i] = TSCALE*acc[mt][nt][i];
            int col = s0 + wn*64 + nt*8 + 2*t;
            *(__half2*)(g_qkh + (qkbase + row0)*LL + col)   = __floats2half2_rn(vals[nt][0], vals[nt][1]);
            *(__half2*)(g_qkh + (qkbase + row0+8)*LL + col) = __floats2half2_rn(vals[nt][2], vals[nt][3]);
            mx0 = fmaxf(mx0, fmaxf(vals[nt][0], vals[nt][1]));
            mx1 = fmaxf(mx1, fmaxf(vals[nt][2], vals[nt][3]));
        }
        #pragma unroll
        for (int off = 1; off <= 2; off <<= 1) {
            mx0 = fmaxf(mx0, __shfl_xor_sync(0xffffffffu, mx0, off));
            mx1 = fmaxf(mx1, __shfl_xor_sync(0xffffffffu, mx1, off));
        }
        float sm0 = 0.f, sm1 = 0.f;
        #pragma unroll
        for (int nt = 0; nt < 8; nt++) {
            sm0 += __expf(vals[nt][0]-mx0) + __expf(vals[nt][1]-mx0);
            sm1 += __expf(vals[nt][2]-mx1) + __expf(vals[nt][3]-mx1);
        }
        #pragma unroll
        for (int off = 1; off <= 2; off <<= 1) {
            sm0 += __shfl_xor_sync(0xffffffffu, sm0, off);
            sm1 += __shfl_xor_sync(0xffffffffu, sm1, off);
        }
        if (t == 0) {
            g_pmax[(qkbase + row0)*NTILES + tile]   = mx0;
            g_psum[(qkbase + row0)*NTILES + tile]   = sm0;
            g_pmax[(qkbase + row0+8)*NTILES + tile] = mx1;
            g_psum[(qkbase + row0+8)*NTILES + tile] = sm1;
        }
    }
}

// ---------------- merged weight fp16 prepass ----------------
__global__ void roundh3_kernel(const float* __restrict__ mw, const float* __restrict__ w1,
                               const float* __restrict__ w2,
                               __half* __restrict__ mwh, __half* __restrict__ w1h,
                               __half* __restrict__ w2h) {
    int i = blockIdx.x*256 + threadIdx.x;
    if (i < CH*CH) mwh[i] = __float2half_rn(mw[i]);
    if (i < C2*C2) w1h[i] = __float2half_rn(w1[i]);
    if (i < CH*C2) w2h[i] = __float2half_rn(w2[i]);
}

// ---------------- 1. fused maxpool + xcopy + LN partials ----------------
#define PUX_PITCH 516
#define PUX_SMEM ((32*PUX_PITCH + 32*33)*4)
__global__ __launch_bounds__(256) void pux_kernel(const float* __restrict__ x1,
                                                  const float* __restrict__ x2) {
    extern __shared__ float sh[];           // [32][PUX_PITCH] + po[32][33]
    float* po = sh + 32*PUX_PITCH;
    int ct = blockIdx.x;
    int y4 = blockIdx.y;
    int n  = blockIdx.z & 3;
    int o  = blockIdx.z >> 2;
    const float* xs = o ? x2 : x1;
    int tid = threadIdx.x;
    int c0 = ct*32;
    #pragma unroll
    for (int i = 0; i < 16; i++) {
        int f = tid + i*256;
        int cc = f >> 7, rem = f & 127;
        int yy = rem >> 5, c4 = rem & 31;
        float4 v = *(const float4*)(xs +
            (((size_t)(n*CH + c0+cc))*HH + y4*4+yy)*WW + c4*4);
        *(float4*)&sh[cc*PUX_PITCH + yy*128 + c4*4] = v;
    }
    __syncthreads();
    {
        int c = tid >> 3, xo = (tid & 7)*4;
        float4 out;
        float* pov = &out.x;
        #pragma unroll
        for (int k = 0; k < 4; k++) {
            int px = xo + k;
            float m = NEGINF;
            #pragma unroll
            for (int yy = 0; yy < 4; yy++) {
                float4 v = *(const float4*)&sh[c*PUX_PITCH + yy*128 + px*4];
                m = fmaxf(m, fmaxf(fmaxf(v.x, v.y), fmaxf(v.z, v.w)));
            }
            pov[k] = m;
            po[c*33 + px] = m;
        }
        *(float4*)(g_p[o] + ((size_t)(n*CH + c0 + c))*LL + y4*32 + xo) = out;
    }
    __syncthreads();
    if (tid < 32) {
        float s = 0.f, sq = 0.f;
        #pragma unroll
        for (int c = 0; c < 32; c++) { float v = po[c*33 + tid]; s += v; sq += v*v; }
        int sp = y4*32 + tid;
        size_t pidx = (((size_t)(o*BATCH + n))*8 + ct)*LL + sp;
        g_lnps[pidx] = s;
        g_lnpq[pidx] = sq;
    }
    size_t rbase = (size_t)o*NPIX + (size_t)n*HH*WW + (size_t)(y4*4)*WW;
    #pragma unroll
    for (int j = 0; j < 2; j++) {
        int p = tid + j*256;
        __half2 hb[16];
        #pragma unroll
        for (int cc = 0; cc < 32; cc += 2)
            hb[cc>>1] = __floats2half2_rn(sh[cc*PUX_PITCH + p], sh[(cc+1)*PUX_PITCH + p]);
        uint4* dst = (uint4*)(g_u + (rbase + p)*C2 + c0);
        const uint4* src = (const uint4*)hb;
        dst[0] = src[0]; dst[1] = src[1]; dst[2] = src[2]; dst[3] = src[3];
    }
}

// ---------------- 2. finalize LN stats ----------------
__global__ void lnfin_kernel() {
    int gi = blockIdx.x*256 + threadIdx.x;
    int on = gi / LL, sp = gi % LL;
    float s = 0.f, sq = 0.f;
    #pragma unroll
    for (int ctt = 0; ctt < 8; ctt++) {
        size_t pidx = (((size_t)on)*8 + ctt)*LL + sp;
        s += g_lnps[pidx]; sq += g_lnpq[pidx];
    }
    float mu = s * (1.0f/CH);
    g_mu1[gi] = mu;
    g_rs1[gi] = rsqrtf(sq * (1.0f/CH) - mu*mu + EPSF);
}

// ---------------- 3. dwconv3x3 + BN (LN applied inline), q/k fp16 out ----------------
__global__ __launch_bounds__(256) void dwbn2_kernel(
        const float* __restrict__ qw, const float* __restrict__ qg, const float* __restrict__ qb,
        const float* __restrict__ qm, const float* __restrict__ qvv,
        const float* __restrict__ vw, const float* __restrict__ vg, const float* __restrict__ vb,
        const float* __restrict__ vm, const float* __restrict__ vvv,
        const float* __restrict__ l1g, const float* __restrict__ l1b) {
    int c0 = blockIdx.x * 8;
    int n  = blockIdx.y;
    int o  = blockIdx.z;
    __shared__ float sp[8*1028];
    int t = threadIdx.x;
    const float* mub = g_mu1 + (size_t)(o*BATCH + n)*LL;
    const float* rsb = g_rs1 + (size_t)(o*BATCH + n)*LL;
    #pragma unroll
    for (int cc = 0; cc < 8; cc++) {
        float gc = l1g[c0+cc], bc = l1b[c0+cc];
        #pragma unroll
        for (int it = 0; it < 4; it++) {
            int spi = t + it*256;
            float raw = g_p[o][((size_t)(n*CH + c0+cc))*LL + spi];
            sp[cc*1028 + spi] = gc*(raw - mub[spi])*rsb[spi] + bc;
        }
    }
    __syncthreads();

    int cc = t & 7, jq = t >> 3;
    int c = c0 + cc;
    float wq[9], wv[9];
    #pragma unroll
    for (int k = 0; k < 9; k++) { wq[k] = qw[c*9+k]; wv[k] = vw[c*9+k]; }
    float scq = qg[c]*rsqrtf(qvv[c]+EPSF), bq = qb[c] - scq*qm[c];
    float scv = vg[c]*rsqrtf(vvv[c]+EPSF), bv = vb[c] - scv*vm[c];
    const float* s = sp + cc*1028;
    __half* oq = g_qh[o] + (size_t)(n*LL)*CH + c;
    float*  ov = g_v[o]  + (size_t)(n*LL)*CH + c;

    for (int i = 0; i < 32; i++) {
        float aq = 0.f, av = 0.f;
        #pragma unroll
        for (int di = 0; di < 3; di++) {
            int ii = i + di - 1;
            if (ii < 0 || ii >= HP) continue;
            #pragma unroll
            for (int dj = 0; dj < 3; dj++) {
                int jj = jq + dj - 1;
                if (jj < 0 || jj >= WP) continue;
                float x = s[ii*32 + jj];
                aq += wq[di*3+dj]*x;
                av += wv[di*3+dj]*x;
            }
        }
        int l = i*32 + jq;
        oq[(size_t)l*CH] = __float2half_rn(scq*aq + bq);
        ov[(size_t)l*CH] = scv*av + bv;
    }
}

// ---------------- 5. combine tile partials ----------------
__global__ void rowstat2_kernel() {
    int r = blockIdx.x*256 + threadIdx.x;
    float pm[NTILES];
    float m = NEGINF;
    #pragma unroll
    for (int i = 0; i < NTILES; i++) {
        pm[i] = g_pmax[(size_t)r*NTILES + i];
        m = fmaxf(m, pm[i]);
    }
    float sum = 0.f;
    #pragma unroll
    for (int i = 0; i < NTILES; i++)
        sum += g_psum[(size_t)r*NTILES + i] * __expf(pm[i] - m);
    g_rmax[r] = m;
    g_rinv[r] = 1.f/sum;
}

// ---------------- 6. m1 = S1 @ v2h ----------------
__global__ __launch_bounds__(256) void m1_kernel() {
    int n = blockIdx.y >> 3, h = blockIdx.y & 7;
    int l0 = blockIdx.x * 128;
    __shared__ float Ps[32][132], Vs[32][36], mxs[128], ris[128];
    int t = threadIdx.x;
    int rbase = (n*NHEAD + h)*LL + l0;
    if (t < 128) { mxs[t] = g_rmax[rbase + t]; ris[t] = g_rinv[rbase + t]; }
    __syncthreads();
    int tx = t & 7, ty = t >> 3;
    float acc[4][4] = {};
    for (int st = 0; st < LL; st += 32) {
        #pragma unroll
        for (int i = 0; i < 4; i++) {
            int id = t + i*256;
            int lrow = id >> 3, sseg = id & 7;
            uint2 raw = *(const uint2*)(g_qkh + ((size_t)(rbase + lrow))*LL + st + sseg*4);
            float2 f01 = __half22float2(*(__half2*)&raw.x);
            float2 f23 = __half22float2(*(__half2*)&raw.y);
            float mx = mxs[lrow], ri = ris[lrow];
            Ps[sseg*4+0][lrow] = __expf(f01.x - mx)*ri;
            Ps[sseg*4+1][lrow] = __expf(f01.y - mx)*ri;
            Ps[sseg*4+2][lrow] = __expf(f23.x - mx)*ri;
            Ps[sseg*4+3][lrow] = __expf(f23.y - mx)*ri;
        }
        {
            int srow = t >> 3, dseg = t & 7;
            *(float4*)&Vs[srow][dseg*4] =
                *(const float4*)(g_v[1] + ((size_t)(n*LL + st + srow))*CH + h*DH + dseg*4);
        }
        __syncthreads();
        #pragma unroll
        for (int k = 0; k < 32; k++) {
            float4 av = *(const float4*)&Ps[k][ty*4];
            float4 bv = *(const float4*)&Vs[k][tx*4];
            acc[0][0]+=av.x*bv.x; acc[0][1]+=av.x*bv.y; acc[0][2]+=av.x*bv.z; acc[0][3]+=av.x*bv.w;
            acc[1][0]+=av.y*bv.x; acc[1][1]+=av.y*bv.y; acc[1][2]+=av.y*bv.z; acc[1][3]+=av.y*bv.w;
            acc[2][0]+=av.z*bv.x; acc[2][1]+=av.z*bv.y; acc[2][2]+=av.z*bv.z; acc[2][3]+=av.z*bv.w;
            acc[3][0]+=av.w*bv.x; acc[3][1]+=av.w*bv.y; acc[3][2]+=av.w*bv.z; acc[3][3]+=av.w*bv.w;
        }
        __syncthreads();
    }
    #pragma unroll
    for (int i = 0; i < 4; i++) {
        int l = l0 + ty*4 + i;
        __half2* dst = (__half2*)(g_m[0] + ((size_t)(n*LL + l))*CH + h*DH + tx*4);
        dst[0] = __floats2half2_rn(acc[i][0], acc[i][1]);
        dst[1] = __floats2half2_rn(acc[i][2], acc[i][3]);
    }
}

// ---------------- 7. S2 softmax over heads (half2) ----------------
__global__ void s2_kernel() {
    size_t idx = (size_t)blockIdx.x*blockDim.x + threadIdx.x;
    int s2i = (int)(idx % (LL/2));
    int l = (int)((idx / (LL/2)) % LL);
    int n = (int)(idx / ((size_t)LL*LL/2));
    float2 v[NHEAD];
    float mx0 = NEGINF, mx1 = NEGINF;
    #pragma unroll
    for (int h = 0; h < NHEAD; h++) {
        __half2 hv = *(__half2*)(g_qkh + (((size_t)(n*NHEAD + h))*LL + l)*LL + s2i*2);
        v[h] = __half22float2(hv);
        mx0 = fmaxf(mx0, v[h].x);
        mx1 = fmaxf(mx1, v[h].y);
    }
    float sm0 = 0.f, sm1 = 0.f;
    #pragma unroll
    for (int h = 0; h < NHEAD; h++) {
        v[h].x = __expf(v[h].x-mx0); sm0 += v[h].x;
        v[h].y = __expf(v[h].y-mx1); sm1 += v[h].y;
    }
    float r0 = 1.f/sm0, r1 = 1.f/sm1;
    #pragma unroll
    for (int h = 0; h < NHEAD; h++)
        *(__half2*)(g_qkh + (((size_t)(n*NHEAD + h))*LL + l)*LL + s2i*2) =
            __floats2half2_rn(v[h].x*r0, v[h].y*r1);
}

// ---------------- 8. m2 = S2^T @ v1h ----------------
__global__ __launch_bounds__(256) void m2_kernel() {
    int n = blockIdx.y >> 3, h = blockIdx.y & 7;
    int s0 = blockIdx.x * 128;
    __shared__ float As[32][132], Vs[32][36];
    int t = threadIdx.x;
    size_t qbase = ((size_t)(n*NHEAD + h))*LL;
    int tx = t & 7, ty = t >> 3;
    float acc[4][4] = {};
    for (int lt = 0; lt < LL; lt += 32) {
        #pragma unroll
        for (int i = 0; i < 4; i++) {
            int id = t + i*256;
            int lrow = id >> 5, sseg = id & 31;
            uint2 raw = *(const uint2*)(g_qkh + (qbase + lt + lrow)*LL + s0 + sseg*4);
            float2 f01 = __half22float2(*(__half2*)&raw.x);
            float2 f23 = __half22float2(*(__half2*)&raw.y);
            As[lrow][sseg*4+0] = f01.x; As[lrow][sseg*4+1] = f01.y;
            As[lrow][sseg*4+2] = f23.x; As[lrow][sseg*4+3] = f23.y;
        }
        {
            int srow = t >> 3, dseg = t & 7;
            *(float4*)&Vs[srow][dseg*4] =
                *(const float4*)(g_v[0] + ((size_t)(n*LL + lt + srow))*CH + h*DH + dseg*4);
        }
        __syncthreads();
        #pragma unroll
        for (int k = 0; k < 32; k++) {
            float4 av = *(const float4*)&As[k][ty*4];
            float4 bv = *(const float4*)&Vs[k][tx*4];
            acc[0][0]+=av.x*bv.x; acc[0][1]+=av.x*bv.y; acc[0][2]+=av.x*bv.z; acc[0][3]+=av.x*bv.w;
            acc[1][0]+=av.y*bv.x; acc[1][1]+=av.y*bv.y; acc[1][2]+=av.y*bv.z; acc[1][3]+=av.y*bv.w;
            acc[2][0]+=av.z*bv.x; acc[2][1]+=av.z*bv.y; acc[2][2]+=av.z*bv.z; acc[2][3]+=av.z*bv.w;
            acc[3][0]+=av.w*bv.x; acc[3][1]+=av.w*bv.y; acc[3][2]+=av.w*bv.z; acc[3][3]+=av.w*bv.w;
        }
        __syncthreads();
    }
    #pragma unroll
    for (int i = 0; i < 4; i++) {
        int s = s0 + ty*4 + i;
        __half2* dst = (__half2*)(g_m[1] + ((size_t)(n*LL + s))*CH + h*DH + tx*4);
        dst[0] = __floats2half2_rn(acc[i][0], acc[i][1]);
        dst[1] = __floats2half2_rn(acc[i][2], acc[i][3]);
    }
}

// ---------------- 9. bilinear x4 upsample into U[:, 256:512] ----------------
__global__ void upsample_kernel() {
    int tid = threadIdx.x;
    int pix = blockIdx.x*4 + (tid >> 6);
    int cg = (tid & 63) * 4;
    int x = pix % WW;
    int y = (pix / WW) % HH;
    int n = (pix / (WW*HH)) % BATCH;
    int o =  pix / (WW*HH*BATCH);
    float sy = (y + 0.5f)*0.25f - 0.5f;
    float sx = (x + 0.5f)*0.25f - 0.5f;
    int y0 = (int)floorf(sy), x0 = (int)floorf(sx);
    float fy = sy - (float)y0, fx = sx - (float)x0;
    int y0c = min(max(y0, 0), HP-1), y1c = min(max(y0+1, 0), HP-1);
    int x0c = min(max(x0, 0), WP-1), x1c = min(max(x0+1, 0), WP-1);
    const float* mm = g_mm[o] + (size_t)n*LL*CH;
    float4 v00 = *(const float4*)(mm + (size_t)(y0c*WP + x0c)*CH + cg);
    float4 v01 = *(const float4*)(mm + (size_t)(y0c*WP + x1c)*CH + cg);
    float4 v10 = *(const float4*)(mm + (size_t)(y1c*WP + x0c)*CH + cg);
    float4 v11 = *(const float4*)(mm + (size_t)(y1c*WP + x1c)*CH + cg);
    float w00 = (1.f-fy)*(1.f-fx), w01 = (1.f-fy)*fx, w10 = fy*(1.f-fx), w11 = fy*fx;
    __half2 h0 = __floats2half2_rn(w00*v00.x + w01*v01.x + w10*v10.x + w11*v11.x,
                                   w00*v00.y + w01*v01.y + w10*v10.y + w11*v11.y);
    __half2 h1 = __floats2half2_rn(w00*v00.z + w01*v01.z + w10*v10.z + w11*v11.z,
                                   w00*v00.w + w01*v01.w + w10*v10.w + w11*v11.w);
    __half2* dst = (__half2*)(g_u + (size_t)pix*C2 + CH + cg);
    dst[0] = h0; dst[1] = h1;
}

// ---------------- 10. fused LN stats + apply + residual + write-out ----------------
__global__ __launch_bounds__(256) void out_fused_kernel(
        const float* __restrict__ x1, const float* __restrict__ x2,
        const float* __restrict__ lg, const float* __restrict__ lb,
        float* __restrict__ out) {
    int xt = blockIdx.x;
    int y  = blockIdx.y;
    int n  = blockIdx.z % BATCH;
    int o  = blockIdx.z / BATCH;
    __shared__ float zsh[32][257];
    __shared__ float smu[32], srs[32];
    int tid = threadIdx.x;
    size_t rbase = (size_t)o*NPIX + (size_t)n*HH*WW + (size_t)y*WW + xt*32;
    #pragma unroll
    for (int j = 0; j < 4; j++) {
        int px = j*8 + (tid >> 5);
        int c = (tid & 31) * 8;
        const float* zr = g_z2 + (rbase + px)*CH + c;
        float4 a = *(const float4*)zr;
        float4 b = *(const float4*)(zr + 4);
        zsh[px][c+0] = a.x; zsh[px][c+1] = a.y; zsh[px][c+2] = a.z; zsh[px][c+3] = a.w;
        zsh[px][c+4] = b.x; zsh[px][c+5] = b.y; zsh[px][c+6] = b.z; zsh[px][c+7] = b.w;
    }
    __syncthreads();
    int w = tid >> 5, lane = tid & 31;
    #pragma unroll
    for (int i = 0; i < 4; i++) {
        int px = w*4 + i;
        float s = 0.f, sq = 0.f;
        #pragma unroll
        for (int k = 0; k < 8; k++) { float v = zsh[px][lane + k*32]; s += v; sq += v*v; }
        #pragma unroll
        for (int off = 16; off; off >>= 1) {
            s  += __shfl_xor_sync(0xffffffffu, s,  off);
            sq += __shfl_xor_sync(0xffffffffu, sq, off);
        }
        if (!lane) {
            float mu = s * (1.0f/CH);
            smu[px] = mu;
            srs[px] = rsqrtf(sq * (1.0f/CH) - mu*mu + EPSF);
        }
    }
    __syncthreads();
    const float* xs = o ? x2 : x1;
    int cth = tid >> 5, tx = tid & 31;
    float mu = smu[tx], rs = srs[tx];
    size_t xbase = ((size_t)(n*CH))*HH*WW + (size_t)y*WW + xt*32 + tx;
    float* outb = out + (size_t)o*NPIX*CH;
    #pragma unroll 8
    for (int cc = 0; cc < 32; cc++) {
        int c = cc*8 + cth;
        float val = lg[c]*(zsh[tx][c] - mu)*rs + lb[c];
        size_t gi = xbase + (size_t)c*HH*WW;
        outb[gi] = xs[gi] + val;
    }
}

// ---------------- launch ----------------
extern "C" void kernel_launch(void* const* d_in, const int* in_sizes, int n_in,
                              void* d_out, int out_size) {
    const float* x1     = (const float*)d_in[0];
    const float* x2     = (const float*)d_in[1];
    const float* qk_w   = (const float*)d_in[2];
    const float* qk_g   = (const float*)d_in[3];
    const float* qk_b   = (const float*)d_in[4];
    const float* qk_m   = (const float*)d_in[5];
    const float* qk_v   = (const float*)d_in[6];
    const float* v_w    = (const float*)d_in[7];
    const float* v_g    = (const float*)d_in[8];
    const float* v_b    = (const float*)d_in[9];
    const float* v_m    = (const float*)d_in[10];
    const float* v_v    = (const float*)d_in[11];
    const float* ln1_g  = (const float*)d_in[12];
    const float* ln1_b  = (const float*)d_in[13];
    const float* ln2_g  = (const float*)d_in[14];
    const float* ln2_b  = (const float*)d_in[15];
    const float* merge_w= (const float*)d_in[16];
    const float* mlp_w1 = (const float*)d_in[17];
    const float* mlp_w2 = (const float*)d_in[18];
    float* out = (float*)d_out;

    __half *pm, *pu, *pz1, *pmw, *pw1, *pw2;
    float *pmm, *pz2;
    cudaGetSymbolAddress((void**)&pm,  g_m);
    cudaGetSymbolAddress((void**)&pmm, g_mm);
    cudaGetSymbolAddress((void**)&pu,  g_u);
    cudaGetSymbolAddress((void**)&pz1, g_z1);
    cudaGetSymbolAddress((void**)&pz2, g_z2);
    cudaGetSymbolAddress((void**)&pmw, g_mwh);
    cudaGetSymbolAddress((void**)&pw1, g_w1h);
    cudaGetSymbolAddress((void**)&pw2, g_w2h);

    cudaFuncSetAttribute(hgemm_kernel, cudaFuncAttributeMaxDynamicSharedMemorySize, GEMM_SMEM);
    cudaFuncSetAttribute(pux_kernel,   cudaFuncAttributeMaxDynamicSharedMemorySize, PUX_SMEM);

    roundh3_kernel<<<(C2*C2+255)/256, 256>>>(merge_w, mlp_w1, mlp_w2, pmw, pw1, pw2);

    // pool + U-left + LN partials, then finalize stats
    pux_kernel<<<dim3(CH/32, HP, 2*BATCH), 256, PUX_SMEM>>>(x1, x2);
    lnfin_kernel<<<(2*BATCH*LL)/256, 256>>>();

    // dwconv + BN with inline LN -> q/k fp16, v fp32
    dwbn2_kernel<<<dim3(CH/8, BATCH, 2), 256>>>(qk_w, qk_g, qk_b, qk_m, qk_v,
                                                v_w, v_g, v_b, v_m, v_v, ln1_g, ln1_b);

    // attention
    qkmma_kernel<<<dim3(LL/128, LL/128, BATCH*NHEAD), 256>>>();
    rowstat2_kernel<<<BATCH*NHEAD*LL/256, 256>>>();
    m1_kernel<<<dim3(LL/128, BATCH*NHEAD), 256>>>();
    s2_kernel<<<(BATCH*LL*(LL/2))/256, 256>>>();
    m2_kernel<<<dim3(LL/128, BATCH*NHEAD), 256>>>();

    // merge linear
    hgemm_kernel<<<dim3(CH/128, (2*BATCH*LL)/128), 256, GEMM_SMEM>>>(
        pm, pmw, pmm, 2*BATCH*LL, CH, CH, 0, 0);

    upsample_kernel<<<NROWS/4, 256>>>();

    // MLP
    hgemm_kernel<<<dim3(C2/128, NROWS/128), 256, GEMM_SMEM>>>(
        pu, pw1, pz1, NROWS, C2, C2, 1, 1);
    hgemm_kernel<<<dim3(CH/128, NROWS/128), 256, GEMM_SMEM>>>(
        pz1, pw2, pz2, NROWS, CH, C2, 0, 0);

    out_fused_kernel<<<dim3(WW/32, HH, 2*BATCH), 256>>>(x1, x2, ln2_g, ln2_b, out);
}

// round 11
// speedup vs baseline: 6.9604x; 1.1052x over previous
#include <cuda_runtime.h>
#include <cuda_fp16.h>
#include <cstdint>

#define BATCH 4
#define CH 256
#define HH 128
#define WW 128
#define HP 32
#define WP 32
#define LL 1024
#define NHEAD 8
#define DH 32
#define C2 512
#define NPIX (BATCH*HH*WW)
#define NROWS (2*NPIX)
#define EPSF 1e-5f
#define TSCALE 0.17677669529663687f
#define NEGINF (-3.402823466e38f)
#define NTILES 16

// ---------------- scratch ----------------
__device__ float  g_p[2][BATCH*CH*LL];
__device__ float  g_lnps[2*BATCH*8*LL];
__device__ float  g_lnpq[2*BATCH*8*LL];
__device__ float  g_mu1[2*BATCH*LL];
__device__ float  g_rs1[2*BATCH*LL];
__device__ __half g_qh[2][(size_t)BATCH*LL*CH];        // q/k heads fp16
__device__ __half g_vh[2][(size_t)BATCH*LL*CH];        // v heads fp16
__device__ __half g_qkh[(size_t)BATCH*NHEAD*LL*LL];    // fp16 logits
__device__ __half g_s2t[(size_t)BATCH*NHEAD*LL*LL];    // S2 transposed [h][s][l]
__device__ float  g_pmax[(size_t)BATCH*NHEAD*LL*NTILES];
__device__ float  g_psum[(size_t)BATCH*NHEAD*LL*NTILES];
__device__ float  g_rmax[BATCH*NHEAD*LL];
__device__ float  g_rinv[BATCH*NHEAD*LL];
__device__ __half g_m[2][(size_t)BATCH*LL*CH];
__device__ float  g_mm[2][(size_t)BATCH*LL*CH];
__device__ __half g_u[(size_t)NROWS*C2];
__device__ __half g_z1[(size_t)NROWS*C2];
__device__ float  g_z2[(size_t)NROWS*CH];
__device__ __half g_mwh[CH*CH];
__device__ __half g_w1h[C2*C2];
__device__ __half g_w2h[CH*C2];

// ================= helpers =================
__device__ __forceinline__ uint32_t smem_u32(const void* p) {
    uint32_t a;
    asm("{ .reg .u64 t; cvta.to.shared.u64 t, %1; cvt.u32.u64 %0, t; }" : "=r"(a) : "l"(p));
    return a;
}
#define CP_ASYNC16(dst, src) \
    asm volatile("cp.async.cg.shared.global [%0], [%1], 16;" :: "r"(dst), "l"(src) : "memory")
#define CP_COMMIT() asm volatile("cp.async.commit_group;" ::: "memory")
#define CP_WAIT(n)  asm volatile("cp.async.wait_group %0;" :: "n"(n) : "memory")
#define LDSM_X4(r0, r1, r2, r3, addr) \
    asm volatile("ldmatrix.sync.aligned.m8n8.x4.shared.b16 {%0,%1,%2,%3}, [%4];" \
        : "=r"(r0), "=r"(r1), "=r"(r2), "=r"(r3) : "r"(addr))
#define LDSM_X4_T(r0, r1, r2, r3, addr) \
    asm volatile("ldmatrix.sync.aligned.m8n8.x4.trans.shared.b16 {%0,%1,%2,%3}, [%4];" \
        : "=r"(r0), "=r"(r1), "=r"(r2), "=r"(r3) : "r"(addr))

__device__ __forceinline__ void mma_f16(float* d, const uint32_t* a, uint32_t b0, uint32_t b1) {
    asm volatile(
        "mma.sync.aligned.m16n8k16.row.col.f32.f16.f16.f32 "
        "{%0,%1,%2,%3}, {%4,%5,%6,%7}, {%8,%9}, {%0,%1,%2,%3};"
        : "+f"(d[0]), "+f"(d[1]), "+f"(d[2]), "+f"(d[3])
        : "r"(a[0]), "r"(a[1]), "r"(a[2]), "r"(a[3]), "r"(b0), "r"(b1));
}

// ================= fp16 mma GEMM (validated R7 version) =================
#define BKH 64
#define PADH 72
#define TILEH (128*PADH)
#define TILE_BYTES (TILEH*2)
#define STAGE_BYTES (2*TILE_BYTES)
#define GEMM_SMEM (3*STAGE_BYTES)

__global__ __launch_bounds__(256) void hgemm_kernel(
        const __half* __restrict__ A, const __half* __restrict__ Bw, void* __restrict__ C,
        int M, int N, int K, int relu, int outHalf) {
    extern __shared__ __half smh[];
    int tid = threadIdx.x, wid = tid >> 5, lane = tid & 31;
    int g = lane >> 2, t = lane & 3;
    int r = lane & 7, quad = lane >> 3;
    int wm = wid >> 1, wn = wid & 1;
    size_t am0 = (size_t)blockIdx.y * 128;
    size_t bn0 = (size_t)blockIdx.x * 128;
    uint32_t smembase = smem_u32(smh);

    uint32_t a_off[2], b_off[4];
    #pragma unroll
    for (int mt = 0; mt < 2; mt++)
        a_off[mt] = (uint32_t)(((wm*32 + mt*16 + (quad&1)*8 + r)*PADH + (quad>>1)*8) * 2);
    #pragma unroll
    for (int p = 0; p < 4; p++)
        b_off[p] = (uint32_t)(((wn*64 + p*16 + (quad>>1)*8 + r)*PADH + (quad&1)*8) * 2);

    int nchunk = K >> 6;
    float acc[2][8][4];
    #pragma unroll
    for (int mt = 0; mt < 2; mt++)
        #pragma unroll
        for (int nt = 0; nt < 8; nt++)
            #pragma unroll
            for (int i = 0; i < 4; i++) acc[mt][nt][i] = 0.f;

    auto issue = [&](int ch, int st) {
        const __half* Ag = A + am0 * K + ch*BKH;
        const __half* Bg = Bw + bn0 * K + ch*BKH;
        uint32_t base = smembase + st*STAGE_BYTES;
        #pragma unroll
        for (int j = 0; j < 4; j++) {
            int idx = tid + j * 256;
            int row = idx >> 3, seg = idx & 7;
            uint32_t d = (uint32_t)((row*PADH + seg*8) * 2);
            CP_ASYNC16(base + d,              Ag + (size_t)row*K + seg*8);
            CP_ASYNC16(base + TILE_BYTES + d, Bg + (size_t)row*K + seg*8);
        }
        CP_COMMIT();
    };

    issue(0, 0);
    if (nchunk > 1) issue(1, 1);

    for (int i = 0; i < nchunk; i++) {
        int s = i % 3;
        if (i + 2 < nchunk) { issue(i + 2, (i + 2) % 3); CP_WAIT(2); }
        else if (i + 1 < nchunk) { CP_WAIT(1); }
        else { CP_WAIT(0); }
        __syncthreads();

        uint32_t abase = smembase + s*STAGE_BYTES;
        uint32_t bbase = abase + TILE_BYTES;
        #pragma unroll
        for (int ks = 0; ks < 4; ks++) {
            uint32_t koff = (uint32_t)(ks * 32);
            uint32_t af[2][4];
            LDSM_X4(af[0][0], af[0][1], af[0][2], af[0][3], abase + a_off[0] + koff);
            LDSM_X4(af[1][0], af[1][1], af[1][2], af[1][3], abase + a_off[1] + koff);
            #pragma unroll
            for (int p = 0; p < 4; p++) {
                uint32_t b0, b1, b2, b3;
                LDSM_X4(b0, b1, b2, b3, bbase + b_off[p] + koff);
                mma_f16(acc[0][2*p],   af[0], b0, b1);
                mma_f16(acc[1][2*p],   af[1], b0, b1);
                mma_f16(acc[0][2*p+1], af[0], b2, b3);
                mma_f16(acc[1][2*p+1], af[1], b2, b3);
            }
        }
        __syncthreads();
    }

    #pragma unroll
    for (int mt = 0; mt < 2; mt++) {
        size_t row = am0 + wm*32 + mt*16 + g;
        #pragma unroll
        for (int nt = 0; nt < 8; nt++) {
            size_t col = bn0 + wn*64 + nt*8 + 2*t;
            float v0 = acc[mt][nt][0], v1 = acc[mt][nt][1];
            float v2 = acc[mt][nt][2], v3 = acc[mt][nt][3];
            if (relu) {
                v0 = fmaxf(v0,0.f); v1 = fmaxf(v1,0.f);
                v2 = fmaxf(v2,0.f); v3 = fmaxf(v3,0.f);
            }
            if (outHalf) {
                __half* Ch = (__half*)C;
                *(__half2*)(Ch + row*N + col)     = __floats2half2_rn(v0, v1);
                *(__half2*)(Ch + (row+8)*N + col) = __floats2half2_rn(v2, v3);
            } else {
                float* Cf = (float*)C;
                *(float2*)(Cf + row*N + col)     = make_float2(v0, v1);
                *(float2*)(Cf + (row+8)*N + col) = make_float2(v2, v3);
            }
        }
    }
}

// ================= QK tensor-core GEMM: logits + softmax partials =================
#define PADQ 40
__global__ __launch_bounds__(256) void qkmma_kernel() {
    __shared__ __half qs[2][128*PADQ];
    int tid = threadIdx.x, wid = tid >> 5, lane = tid & 31;
    int g = lane >> 2, t = lane & 3;
    int r = lane & 7, quad = lane >> 3;
    int wm = wid >> 1, wn = wid & 1;
    int n = blockIdx.z >> 3, h = blockIdx.z & 7;
    int l0 = blockIdx.y * 128, s0 = blockIdx.x * 128;
    uint32_t abase = smem_u32(qs[0]);
    uint32_t bbase = smem_u32(qs[1]);

    #pragma unroll
    for (int j = 0; j < 2; j++) {
        int idx = tid + j*256;
        int row = idx >> 2, seg = idx & 3;
        uint32_t d = (uint32_t)((row*PADQ + seg*8) * 2);
        const __half* Aq = g_qh[0] + ((size_t)(n*LL + l0 + row))*CH + h*DH + seg*8;
        const __half* Bq = g_qh[1] + ((size_t)(n*LL + s0 + row))*CH + h*DH + seg*8;
        CP_ASYNC16(abase + d, Aq);
        CP_ASYNC16(bbase + d, Bq);
    }
    CP_COMMIT();
    CP_WAIT(0);
    __syncthreads();

    uint32_t a_off[2], b_off[4];
    #pragma unroll
    for (int mt = 0; mt < 2; mt++)
        a_off[mt] = (uint32_t)(((wm*32 + mt*16 + (quad&1)*8 + r)*PADQ + (quad>>1)*8) * 2);
    #pragma unroll
    for (int p = 0; p < 4; p++)
        b_off[p] = (uint32_t)(((wn*64 + p*16 + (quad>>1)*8 + r)*PADQ + (quad&1)*8) * 2);

    float acc[2][8][4];
    #pragma unroll
    for (int mt = 0; mt < 2; mt++)
        #pragma unroll
        for (int nt = 0; nt < 8; nt++)
            #pragma unroll
            for (int i = 0; i < 4; i++) acc[mt][nt][i] = 0.f;

    #pragma unroll
    for (int ks = 0; ks < 2; ks++) {
        uint32_t koff = (uint32_t)(ks * 32);
        uint32_t af[2][4];
        LDSM_X4(af[0][0], af[0][1], af[0][2], af[0][3], abase + a_off[0] + koff);
        LDSM_X4(af[1][0], af[1][1], af[1][2], af[1][3], abase + a_off[1] + koff);
        #pragma unroll
        for (int p = 0; p < 4; p++) {
            uint32_t b0, b1, b2, b3;
            LDSM_X4(b0, b1, b2, b3, bbase + b_off[p] + koff);
            mma_f16(acc[0][2*p],   af[0], b0, b1);
            mma_f16(acc[1][2*p],   af[1], b0, b1);
            mma_f16(acc[0][2*p+1], af[0], b2, b3);
            mma_f16(acc[1][2*p+1], af[1], b2, b3);
        }
    }

    size_t qkbase = ((size_t)(n*NHEAD + h))*LL;
    int tile = blockIdx.x*2 + wn;
    #pragma unroll
    for (int mt = 0; mt < 2; mt++) {
        int row0 = l0 + wm*32 + mt*16 + g;
        float mx0 = NEGINF, mx1 = NEGINF;
        float vals[8][4];
        #pragma unroll
        for (int nt = 0; nt < 8; nt++) {
            #pragma unroll
            for (int i = 0; i < 4; i++) vals[nt][i] = TSCALE*acc[mt][nt][i];
            int col = s0 + wn*64 + nt*8 + 2*t;
            *(__half2*)(g_qkh + (qkbase + row0)*LL + col)   = __floats2half2_rn(vals[nt][0], vals[nt][1]);
            *(__half2*)(g_qkh + (qkbase + row0+8)*LL + col) = __floats2half2_rn(vals[nt][2], vals[nt][3]);
            mx0 = fmaxf(mx0, fmaxf(vals[nt][0], vals[nt][1]));
            mx1 = fmaxf(mx1, fmaxf(vals[nt][2], vals[nt][3]));
        }
        #pragma unroll
        for (int off = 1; off <= 2; off <<= 1) {
            mx0 = fmaxf(mx0, __shfl_xor_sync(0xffffffffu, mx0, off));
            mx1 = fmaxf(mx1, __shfl_xor_sync(0xffffffffu, mx1, off));
        }
        float sm0 = 0.f, sm1 = 0.f;
        #pragma unroll
        for (int nt = 0; nt < 8; nt++) {
            sm0 += __expf(vals[nt][0]-mx0) + __expf(vals[nt][1]-mx0);
            sm1 += __expf(vals[nt][2]-mx1) + __expf(vals[nt][3]-mx1);
        }
        #pragma unroll
        for (int off = 1; off <= 2; off <<= 1) {
            sm0 += __shfl_xor_sync(0xffffffffu, sm0, off);
            sm1 += __shfl_xor_sync(0xffffffffu, sm1, off);
        }
        if (t == 0) {
            g_pmax[(qkbase + row0)*NTILES + tile]   = mx0;
            g_psum[(qkbase + row0)*NTILES + tile]   = sm0;
            g_pmax[(qkbase + row0+8)*NTILES + tile] = mx1;
            g_psum[(qkbase + row0+8)*NTILES + tile] = sm1;
        }
    }
}

// ================= unified AV tensor-core GEMM (m1 / m2) =================
// out[128 rows][32 d] = A[128][K=1024] @ V[K][32], K-chunks of 64.
// which=0: A = softmax1 rows from g_qkh (exp on the fly), B = v2h -> g_m[0]
// which=1: A = g_s2t rows (plain),                        B = v1h -> g_m[1]
#define PADA 72
#define PADB 40
__global__ __launch_bounds__(256) void av_kernel(int which) {
    __shared__ __half As[128*PADA];
    __shared__ __half Bs[64*PADB];
    __shared__ float mxs[128], ris[128];
    int t = threadIdx.x, wid = t >> 5, lane = t & 31;
    int r = lane & 7, quad = lane >> 3;
    int n = blockIdx.y >> 3, h = blockIdx.y & 7;
    int m0 = blockIdx.x * 128;
    size_t lbase = ((size_t)(n*NHEAD + h))*LL + m0;        // row index base
    const __half* Asrc = (which == 0 ? g_qkh : g_s2t);
    const __half* Bsrc = g_vh[which ^ 1] + ((size_t)(n*LL))*CH + h*DH;
    uint32_t asm_b = smem_u32(As), bsm_b = smem_u32(Bs);

    if (which == 0 && t < 128) {
        mxs[t] = g_rmax[lbase + t];
        ris[t] = g_rinv[lbase + t];
    }
    __syncthreads();

    uint32_t a_off = (uint32_t)(((wid*16 + (quad&1)*8 + r)*PADA + (quad>>1)*8) * 2);
    float acc[4][4];
    #pragma unroll
    for (int nt = 0; nt < 4; nt++)
        #pragma unroll
        for (int i = 0; i < 4; i++) acc[nt][i] = 0.f;

    for (int k0 = 0; k0 < LL; k0 += 64) {
        // A: 128 rows x 64 halfs; 2 threads/row
        {
            int row = t >> 1, half0 = (t & 1)*32;
            const __half* src = Asrc + (lbase + row)*LL + k0 + half0;
            __half* dst = As + row*PADA + half0;
            if (which == 0) {
                float mx = mxs[row], ri = ris[row];
                #pragma unroll
                for (int j = 0; j < 4; j++) {
                    uint4 raw = *(const uint4*)(src + j*8);
                    __half2* hp = (__half2*)&raw;
                    __half2 o[4];
                    #pragma unroll
                    for (int q = 0; q < 4; q++) {
                        float2 f = __half22float2(hp[q]);
                        o[q] = __floats2half2_rn(__expf(f.x - mx)*ri, __expf(f.y - mx)*ri);
                    }
                    *(uint4*)(dst + j*8) = *(uint4*)o;
                }
            } else {
                #pragma unroll
                for (int j = 0; j < 4; j++)
                    *(uint4*)(dst + j*8) = *(const uint4*)(src + j*8);
            }
        }
        // B: 64 rows x 32 halfs; 4 threads/row
        {
            int row = t >> 2, seg = (t & 3)*8;
            *(uint4*)(Bs + row*PADB + seg) = *(const uint4*)(Bsrc + (size_t)(k0 + row)*CH + seg);
        }
        __syncthreads();

        #pragma unroll
        for (int ks = 0; ks < 4; ks++) {
            uint32_t af[4];
            LDSM_X4(af[0], af[1], af[2], af[3], asm_b + a_off + (uint32_t)(ks*32));
            #pragma unroll
            for (int p = 0; p < 2; p++) {
                uint32_t b0, b1, b2, b3;
                uint32_t boff = (uint32_t)(((ks*16 + (quad&1)*8 + r)*PADB + p*16 + (quad>>1)*8) * 2);
                LDSM_X4_T(b0, b1, b2, b3, bsm_b + boff);
                mma_f16(acc[2*p],   af, b0, b1);
                mma_f16(acc[2*p+1], af, b2, b3);
            }
        }
        __syncthreads();
    }

    // epilogue
    int rrow = lane >> 2, ccol = (lane & 3)*2;
    #pragma unroll
    for (int nt = 0; nt < 4; nt++) {
        size_t orow = (size_t)(n*LL + m0 + wid*16 + rrow);
        __half* dst = g_m[which] + orow*CH + h*DH + nt*8 + ccol;
        *(__half2*)dst            = __floats2half2_rn(acc[nt][0], acc[nt][1]);
        *(__half2*)(dst + 8*CH)   = __floats2half2_rn(acc[nt][2], acc[nt][3]);
    }
}

// ---------------- merged weight fp16 prepass ----------------
__global__ void roundh3_kernel(const float* __restrict__ mw, const float* __restrict__ w1,
                               const float* __restrict__ w2,
                               __half* __restrict__ mwh, __half* __restrict__ w1h,
                               __half* __restrict__ w2h) {
    int i = blockIdx.x*256 + threadIdx.x;
    if (i < CH*CH) mwh[i] = __float2half_rn(mw[i]);
    if (i < C2*C2) w1h[i] = __float2half_rn(w1[i]);
    if (i < CH*C2) w2h[i] = __float2half_rn(w2[i]);
}

// ---------------- 1. fused maxpool + xcopy + LN partials ----------------
#define PUX_PITCH 516
#define PUX_SMEM ((32*PUX_PITCH + 32*33)*4)
__global__ __launch_bounds__(256) void pux_kernel(const float* __restrict__ x1,
                                                  const float* __restrict__ x2) {
    extern __shared__ float sh[];
    float* po = sh + 32*PUX_PITCH;
    int ct = blockIdx.x;
    int y4 = blockIdx.y;
    int n  = blockIdx.z & 3;
    int o  = blockIdx.z >> 2;
    const float* xs = o ? x2 : x1;
    int tid = threadIdx.x;
    int c0 = ct*32;
    #pragma unroll
    for (int i = 0; i < 16; i++) {
        int f = tid + i*256;
        int cc = f >> 7, rem = f & 127;
        int yy = rem >> 5, c4 = rem & 31;
        float4 v = *(const float4*)(xs +
            (((size_t)(n*CH + c0+cc))*HH + y4*4+yy)*WW + c4*4);
        *(float4*)&sh[cc*PUX_PITCH + yy*128 + c4*4] = v;
    }
    __syncthreads();
    {
        int c = tid >> 3, xo = (tid & 7)*4;
        float4 out;
        float* pov = &out.x;
        #pragma unroll
        for (int k = 0; k < 4; k++) {
            int px = xo + k;
            float m = NEGINF;
            #pragma unroll
            for (int yy = 0; yy < 4; yy++) {
                float4 v = *(const float4*)&sh[c*PUX_PITCH + yy*128 + px*4];
                m = fmaxf(m, fmaxf(fmaxf(v.x, v.y), fmaxf(v.z, v.w)));
            }
            pov[k] = m;
            po[c*33 + px] = m;
        }
        *(float4*)(g_p[o] + ((size_t)(n*CH + c0 + c))*LL + y4*32 + xo) = out;
    }
    __syncthreads();
    if (tid < 32) {
        float s = 0.f, sq = 0.f;
        #pragma unroll
        for (int c = 0; c < 32; c++) { float v = po[c*33 + tid]; s += v; sq += v*v; }
        int sp = y4*32 + tid;
        size_t pidx = (((size_t)(o*BATCH + n))*8 + ct)*LL + sp;
        g_lnps[pidx] = s;
        g_lnpq[pidx] = sq;
    }
    size_t rbase = (size_t)o*NPIX + (size_t)n*HH*WW + (size_t)(y4*4)*WW;
    #pragma unroll
    for (int j = 0; j < 2; j++) {
        int p = tid + j*256;
        __half2 hb[16];
        #pragma unroll
        for (int cc = 0; cc < 32; cc += 2)
            hb[cc>>1] = __floats2half2_rn(sh[cc*PUX_PITCH + p], sh[(cc+1)*PUX_PITCH + p]);
        uint4* dst = (uint4*)(g_u + (rbase + p)*C2 + c0);
        const uint4* src = (const uint4*)hb;
        dst[0] = src[0]; dst[1] = src[1]; dst[2] = src[2]; dst[3] = src[3];
    }
}

// ---------------- 2. finalize LN stats ----------------
__global__ void lnfin_kernel() {
    int gi = blockIdx.x*256 + threadIdx.x;
    int on = gi / LL, sp = gi % LL;
    float s = 0.f, sq = 0.f;
    #pragma unroll
    for (int ctt = 0; ctt < 8; ctt++) {
        size_t pidx = (((size_t)on)*8 + ctt)*LL + sp;
        s += g_lnps[pidx]; sq += g_lnpq[pidx];
    }
    float mu = s * (1.0f/CH);
    g_mu1[gi] = mu;
    g_rs1[gi] = rsqrtf(sq * (1.0f/CH) - mu*mu + EPSF);
}

// ---------------- 3. dwconv3x3 + BN (LN inline), q/k/v fp16 out ----------------
__global__ __launch_bounds__(256) void dwbn2_kernel(
        const float* __restrict__ qw, const float* __restrict__ qg, const float* __restrict__ qb,
        const float* __restrict__ qm, const float* __restrict__ qvv,
        const float* __restrict__ vw, const float* __restrict__ vg, const float* __restrict__ vb,
        const float* __restrict__ vm, const float* __restrict__ vvv,
        const float* __restrict__ l1g, const float* __restrict__ l1b) {
    int c0 = blockIdx.x * 8;
    int n  = blockIdx.y;
    int o  = blockIdx.z;
    __shared__ float sp[8*1028];
    int t = threadIdx.x;
    const float* mub = g_mu1 + (size_t)(o*BATCH + n)*LL;
    const float* rsb = g_rs1 + (size_t)(o*BATCH + n)*LL;
    #pragma unroll
    for (int cc = 0; cc < 8; cc++) {
        float gc = l1g[c0+cc], bc = l1b[c0+cc];
        #pragma unroll
        for (int it = 0; it < 4; it++) {
            int spi = t + it*256;
            float raw = g_p[o][((size_t)(n*CH + c0+cc))*LL + spi];
            sp[cc*1028 + spi] = gc*(raw - mub[spi])*rsb[spi] + bc;
        }
    }
    __syncthreads();

    int cc = t & 7, jq = t >> 3;
    int c = c0 + cc;
    float wq[9], wv[9];
    #pragma unroll
    for (int k = 0; k < 9; k++) { wq[k] = qw[c*9+k]; wv[k] = vw[c*9+k]; }
    float scq = qg[c]*rsqrtf(qvv[c]+EPSF), bq = qb[c] - scq*qm[c];
    float scv = vg[c]*rsqrtf(vvv[c]+EPSF), bv = vb[c] - scv*vm[c];
    const float* s = sp + cc*1028;
    __half* oq = g_qh[o] + (size_t)(n*LL)*CH + c;
    __half* ov = g_vh[o] + (size_t)(n*LL)*CH + c;

    for (int i = 0; i < 32; i++) {
        float aq = 0.f, av = 0.f;
        #pragma unroll
        for (int di = 0; di < 3; di++) {
            int ii = i + di - 1;
            if (ii < 0 || ii >= HP) continue;
            #pragma unroll
            for (int dj = 0; dj < 3; dj++) {
                int jj = jq + dj - 1;
                if (jj < 0 || jj >= WP) continue;
                float x = s[ii*32 + jj];
                aq += wq[di*3+dj]*x;
                av += wv[di*3+dj]*x;
            }
        }
        int l = i*32 + jq;
        oq[(size_t)l*CH] = __float2half_rn(scq*aq + bq);
        ov[(size_t)l*CH] = __float2half_rn(scv*av + bv);
    }
}

// ---------------- 5. combine tile partials ----------------
__global__ void rowstat2_kernel() {
    int r = blockIdx.x*256 + threadIdx.x;
    float pm[NTILES];
    float m = NEGINF;
    #pragma unroll
    for (int i = 0; i < NTILES; i++) {
        pm[i] = g_pmax[(size_t)r*NTILES + i];
        m = fmaxf(m, pm[i]);
    }
    float sum = 0.f;
    #pragma unroll
    for (int i = 0; i < NTILES; i++)
        sum += g_psum[(size_t)r*NTILES + i] * __expf(pm[i] - m);
    g_rmax[r] = m;
    g_rinv[r] = 1.f/sum;
}

// ---------------- 7. S2 softmax over heads + transpose ----------------
__global__ __launch_bounds__(256) void s2t_kernel() {
    __shared__ __half sm[8][32][36];
    int t = threadIdx.x;
    int s0 = blockIdx.x*32, l0 = blockIdx.y*32, n = blockIdx.z;
    int row = t >> 3, seg = t & 7;
    #pragma unroll
    for (int h = 0; h < NHEAD; h++) {
        uint2 v = *(const uint2*)(g_qkh +
            (((size_t)(n*NHEAD + h))*LL + l0 + row)*LL + s0 + seg*4);
        *(uint2*)&sm[h][row][seg*4] = v;
    }
    __syncthreads();
    #pragma unroll
    for (int j = 0; j < 4; j++) {
        int e = t*4 + j;
        int l = e >> 5, s = e & 31;
        float v[NHEAD];
        float mx = NEGINF;
        #pragma unroll
        for (int h = 0; h < NHEAD; h++) {
            v[h] = __half2float(sm[h][l][s]);
            mx = fmaxf(mx, v[h]);
        }
        float smm = 0.f;
        #pragma unroll
        for (int h = 0; h < NHEAD; h++) { v[h] = __expf(v[h]-mx); smm += v[h]; }
        float ri = 1.f/smm;
        #pragma unroll
        for (int h = 0; h < NHEAD; h++)
            sm[h][l][s] = __float2half_rn(v[h]*ri);
    }
    __syncthreads();
    #pragma unroll
    for (int h = 0; h < NHEAD; h++) {
        __half tmp[4];
        #pragma unroll
        for (int jj = 0; jj < 4; jj++) tmp[jj] = sm[h][seg*4+jj][row];
        *(uint2*)(g_s2t + (((size_t)(n*NHEAD + h))*LL + s0 + row)*LL + l0 + seg*4) =
            *(uint2*)tmp;
    }
}

// ---------------- 9. bilinear x4 upsample into U[:, 256:512] ----------------
__global__ void upsample_kernel() {
    int tid = threadIdx.x;
    int pix = blockIdx.x*4 + (tid >> 6);
    int cg = (tid & 63) * 4;
    int x = pix % WW;
    int y = (pix / WW) % HH;
    int n = (pix / (WW*HH)) % BATCH;
    int o =  pix / (WW*HH*BATCH);
    float sy = (y + 0.5f)*0.25f - 0.5f;
    float sx = (x + 0.5f)*0.25f - 0.5f;
    int y0 = (int)floorf(sy), x0 = (int)floorf(sx);
    float fy = sy - (float)y0, fx = sx - (float)x0;
    int y0c = min(max(y0, 0), HP-1), y1c = min(max(y0+1, 0), HP-1);
    int x0c = min(max(x0, 0), WP-1), x1c = min(max(x0+1, 0), WP-1);
    const float* mm = g_mm[o] + (size_t)n*LL*CH;
    float4 v00 = *(const float4*)(mm + (size_t)(y0c*WP + x0c)*CH + cg);
    float4 v01 = *(const float4*)(mm + (size_t)(y0c*WP + x1c)*CH + cg);
    float4 v10 = *(const float4*)(mm + (size_t)(y1c*WP + x0c)*CH + cg);
    float4 v11 = *(const float4*)(mm + (size_t)(y1c*WP + x1c)*CH + cg);
    float w00 = (1.f-fy)*(1.f-fx), w01 = (1.f-fy)*fx, w10 = fy*(1.f-fx), w11 = fy*fx;
    __half2 h0 = __floats2half2_rn(w00*v00.x + w01*v01.x + w10*v10.x + w11*v11.x,
                                   w00*v00.y + w01*v01.y + w10*v10.y + w11*v11.y);
    __half2 h1 = __floats2half2_rn(w00*v00.z + w01*v01.z + w10*v10.z + w11*v11.z,
                                   w00*v00.w + w01*v01.w + w10*v10.w + w11*v11.w);
    __half2* dst = (__half2*)(g_u + (size_t)pix*C2 + CH + cg);
    dst[0] = h0; dst[1] = h1;
}

// ---------------- 10. fused LN stats + apply + residual + write-out ----------------
__global__ __launch_bounds__(256) void out_fused_kernel(
        const float* __restrict__ x1, const float* __restrict__ x2,
        const float* __restrict__ lg, const float* __restrict__ lb,
        float* __restrict__ out) {
    int xt = blockIdx.x;
    int y  = blockIdx.y;
    int n  = blockIdx.z % BATCH;
    int o  = blockIdx.z / BATCH;
    __shared__ float zsh[32][257];
    __shared__ float smu[32], srs[32];
    int tid = threadIdx.x;
    size_t rbase = (size_t)o*NPIX + (size_t)n*HH*WW + (size_t)y*WW + xt*32;
    #pragma unroll
    for (int j = 0; j < 4; j++) {
        int px = j*8 + (tid >> 5);
        int c = (tid & 31) * 8;
        const float* zr = g_z2 + (rbase + px)*CH + c;
        float4 a = *(const float4*)zr;
        float4 b = *(const float4*)(zr + 4);
        zsh[px][c+0] = a.x; zsh[px][c+1] = a.y; zsh[px][c+2] = a.z; zsh[px][c+3] = a.w;
        zsh[px][c+4] = b.x; zsh[px][c+5] = b.y; zsh[px][c+6] = b.z; zsh[px][c+7] = b.w;
    }
    __syncthreads();
    int w = tid >> 5, lane = tid & 31;
    #pragma unroll
    for (int i = 0; i < 4; i++) {
        int px = w*4 + i;
        float s = 0.f, sq = 0.f;
        #pragma unroll
        for (int k = 0; k < 8; k++) { float v = zsh[px][lane + k*32]; s += v; sq += v*v; }
        #pragma unroll
        for (int off = 16; off; off >>= 1) {
            s  += __shfl_xor_sync(0xffffffffu, s,  off);
            sq += __shfl_xor_sync(0xffffffffu, sq, off);
        }
        if (!lane) {
            float mu = s * (1.0f/CH);
            smu[px] = mu;
            srs[px] = rsqrtf(sq * (1.0f/CH) - mu*mu + EPSF);
        }
    }
    __syncthreads();
    const float* xs = o ? x2 : x1;
    int cth = tid >> 5, tx = tid & 31;
    float mu = smu[tx], rs = srs[tx];
    size_t xbase = ((size_t)(n*CH))*HH*WW + (size_t)y*WW + xt*32 + tx;
    float* outb = out + (size_t)o*NPIX*CH;
    #pragma unroll 8
    for (int cc = 0; cc < 32; cc++) {
        int c = cc*8 + cth;
        float val = lg[c]*(zsh[tx][c] - mu)*rs + lb[c];
        size_t gi = xbase + (size_t)c*HH*WW;
        outb[gi] = xs[gi] + val;
    }
}

// ---------------- launch ----------------
extern "C" void kernel_launch(void* const* d_in, const int* in_sizes, int n_in,
                              void* d_out, int out_size) {
    const float* x1     = (const float*)d_in[0];
    const float* x2     = (const float*)d_in[1];
    const float* qk_w   = (const float*)d_in[2];
    const float* qk_g   = (const float*)d_in[3];
    const float* qk_b   = (const float*)d_in[4];
    const float* qk_m   = (const float*)d_in[5];
    const float* qk_v   = (const float*)d_in[6];
    const float* v_w    = (const float*)d_in[7];
    const float* v_g    = (const float*)d_in[8];
    const float* v_b    = (const float*)d_in[9];
    const float* v_m    = (const float*)d_in[10];
    const float* v_v    = (const float*)d_in[11];
    const float* ln1_g  = (const float*)d_in[12];
    const float* ln1_b  = (const float*)d_in[13];
    const float* ln2_g  = (const float*)d_in[14];
    const float* ln2_b  = (const float*)d_in[15];
    const float* merge_w= (const float*)d_in[16];
    const float* mlp_w1 = (const float*)d_in[17];
    const float* mlp_w2 = (const float*)d_in[18];
    float* out = (float*)d_out;

    __half *pm, *pu, *pz1, *pmw, *pw1, *pw2;
    float *pmm, *pz2;
    cudaGetSymbolAddress((void**)&pm,  g_m);
    cudaGetSymbolAddress((void**)&pmm, g_mm);
    cudaGetSymbolAddress((void**)&pu,  g_u);
    cudaGetSymbolAddress((void**)&pz1, g_z1);
    cudaGetSymbolAddress((void**)&pz2, g_z2);
    cudaGetSymbolAddress((void**)&pmw, g_mwh);
    cudaGetSymbolAddress((void**)&pw1, g_w1h);
    cudaGetSymbolAddress((void**)&pw2, g_w2h);

    cudaFuncSetAttribute(hgemm_kernel, cudaFuncAttributeMaxDynamicSharedMemorySize, GEMM_SMEM);
    cudaFuncSetAttribute(pux_kernel,   cudaFuncAttributeMaxDynamicSharedMemorySize, PUX_SMEM);

    roundh3_kernel<<<(C2*C2+255)/256, 256>>>(merge_w, mlp_w1, mlp_w2, pmw, pw1, pw2);

    pux_kernel<<<dim3(CH/32, HP, 2*BATCH), 256, PUX_SMEM>>>(x1, x2);
    lnfin_kernel<<<(2*BATCH*LL)/256, 256>>>();

    dwbn2_kernel<<<dim3(CH/8, BATCH, 2), 256>>>(qk_w, qk_g, qk_b, qk_m, qk_v,
                                                v_w, v_g, v_b, v_m, v_v, ln1_g, ln1_b);

    // attention (all tensor-core)
    qkmma_kernel<<<dim3(LL/128, LL/128, BATCH*NHEAD), 256>>>();
    rowstat2_kernel<<<BATCH*NHEAD*LL/256, 256>>>();
    av_kernel<<<dim3(LL/128, BATCH*NHEAD), 256>>>(0);   // m1
    s2t_kernel<<<dim3(LL/32, LL/32, BATCH), 256>>>();
    av_kernel<<<dim3(LL/128, BATCH*NHEAD), 256>>>(1);   // m2

    // merge linear
    hgemm_kernel<<<dim3(CH/128, (2*BATCH*LL)/128), 256, GEMM_SMEM>>>(
        pm, pmw, pmm, 2*BATCH*LL, CH, CH, 0, 0);

    upsample_kernel<<<NROWS/4, 256>>>();

    // MLP
    hgemm_kernel<<<dim3(C2/128, NROWS/128), 256, GEMM_SMEM>>>(
        pu, pw1, pz1, NROWS, C2, C2, 1, 1);
    hgemm_kernel<<<dim3(CH/128, NROWS/128), 256, GEMM_SMEM>>>(
        pz1, pw2, pz2, NROWS, CH, C2, 0, 0);

    out_fused_kernel<<<dim3(WW/32, HH, 2*BATCH), 256>>>(x1, x2, ln2_g, ln2_b, out);
}